// round 10
// baseline (speedup 1.0000x reference)
#include <cuda_runtime.h>
#include <cuda_fp16.h>
#include <cstdint>

// ---------------------------------------------------------------------------
// FeedForwardNetwork (SO(3) equivariant FFN), sm_103a — all-MMA plain-fp16
// Round 10: grid1 and grid2 fused into one kernel; grid1 intermediate lives
// in shared memory (64 KB, grid2 A-chunk layout). grid1b global eliminated.
//
//   nfh    = fp16(node_feats)
//   y      = nfh @ fp16(W1G1[l])     (MMA K=128, per-coeff i) -> fp16 planes
//   fused: g1t = silu(fp16(T) @ y) (K=64) -> smem
//          grid2 = silu(g1t @ fp16(g2)) (K=256) -> g_grid2b fp16
//   z      = fp16(F^T) @ grid2       (MMA K=352, per node)    -> fp16
//   out[:,i>=1,:] = z[:,i,:] @ fp16(g3 @ w2[l(i)])  (MMA K=256) -> fp32
//   out[:,0,:]    = silu(nf[:,0,:] @ ws + bs) @ w2[0] + b2      (SIMT, tiny)
// ---------------------------------------------------------------------------

#define N_NODES 1024
#define NC      49
#define CIN     128
#define HID     256
#define RES     18
#define NP      (RES*RES)   // 324
#define NL      7
#define MROWS   ((size_t)N_NODES * NP)
#define PBLK    352
#define BM      128
#define BN      256
#define BK      32
#define NITERZ  11           // z K chunks (352/32)
#define NITERY  4            // y K chunks (128/32)
#define NITERO  8            // out K chunks (256/32)
#define NITERF2 8            // fused phase-2 K chunks (256/32)

// -------- scratch (static device globals; no runtime allocation) -----------
__device__ float g_W1G1[NL * CIN * HID];
__device__ float g_G3W2[NL * HID * CIN];
__device__ float g_b1g1[HID];
__device__ __half g_Tb[384 * 64];                    // to_grid hi [384x64]
__device__ __half g_FTb[64 * PBLK];                  // from_grid^T hi [64x352]
__device__ __half g_g2b[HID * 256];                  // g2^T hi [256x256]
__device__ __half g_w1g1h[NL * HID * 128];           // W1G1^T hi rows
__device__ __half g_g3w2h[NL * CIN * 256];           // (g3 w2)^T hi rows
__device__ __half g_nfh[(size_t)N_NODES * NC * CIN];       // 12.8 MB
__device__ __half g_yb[(size_t)N_NODES * 64 * HID];        // 34 MB
__device__ __half g_grid2b[(size_t)N_NODES * PBLK * HID];  // 185 MB
__device__ __half g_zh[(size_t)N_NODES * NC * HID];        // 25.7 MB
__device__ float g_gate[(size_t)N_NODES * HID];

__device__ __forceinline__ float silu_f(float x) {
    return x / (1.0f + __expf(-x));
}
__device__ __forceinline__ int deg_of(int i) {
    int l = 0;
    while ((l + 1) * (l + 1) <= i) ++l;
    return l;
}
__device__ __forceinline__ uint32_t smem_u32(const void* p) {
    uint32_t a;
    asm("{ .reg .u64 t; cvta.to.shared.u64 t, %1; cvt.u32.u64 %0, t; }"
        : "=r"(a) : "l"(p));
    return a;
}
__device__ __forceinline__ void cp_async16(uint32_t dst, const void* src) {
    asm volatile("cp.async.cg.shared.global [%0], [%1], 16;" :: "r"(dst), "l"(src));
}
__device__ __forceinline__ void ldsm_x4(uint32_t& r0, uint32_t& r1,
                                        uint32_t& r2, uint32_t& r3, uint32_t addr) {
    asm volatile("ldmatrix.sync.aligned.m8n8.x4.shared.b16 {%0,%1,%2,%3}, [%4];"
                 : "=r"(r0), "=r"(r1), "=r"(r2), "=r"(r3) : "r"(addr));
}
__device__ __forceinline__ void ldsm_x4_t(uint32_t& r0, uint32_t& r1,
                                          uint32_t& r2, uint32_t& r3, uint32_t addr) {
    asm volatile("ldmatrix.sync.aligned.m8n8.x4.trans.shared.b16 {%0,%1,%2,%3}, [%4];"
                 : "=r"(r0), "=r"(r1), "=r"(r2), "=r"(r3) : "r"(addr));
}
__device__ __forceinline__ void mma_f16(float* d, const uint32_t* a, const uint32_t* b) {
    asm volatile(
        "mma.sync.aligned.m16n8k16.row.col.f32.f16.f16.f32 "
        "{%0,%1,%2,%3}, {%4,%5,%6,%7}, {%8,%9}, {%0,%1,%2,%3};"
        : "+f"(d[0]), "+f"(d[1]), "+f"(d[2]), "+f"(d[3])
        : "r"(a[0]), "r"(a[1]), "r"(a[2]), "r"(a[3]), "r"(b[0]), "r"(b[1]));
}
__device__ __forceinline__ uint32_t pkh2(float x, float y) {
    __half hx = __float2half_rn(x), hy = __float2half_rn(y);
    uint16_t bx = *(uint16_t*)&hx, by = *(uint16_t*)&hy;
    return (uint32_t)bx | ((uint32_t)by << 16);
}

// ---------------------------------------------------------------------------
// Generic 64x64x16 SIMT tiled GEMM (small stages only).
// ---------------------------------------------------------------------------
template<bool DO_SILU, bool HAS_BIAS>
__device__ __forceinline__ void gemm_tile(
    const float* __restrict__ A, int lda,
    const float* __restrict__ B, int ldb,
    const float* __restrict__ bias,
    float* __restrict__ C, int ldc,
    int M, int N, int K)
{
    __shared__ float As[16][64];
    __shared__ float Bs[16][64];

    const int tid = threadIdx.x;
    const int tx  = tid & 15;
    const int ty  = tid >> 4;
    const int m0  = blockIdx.y * 64;
    const int n0  = blockIdx.x * 64;

    float acc[4][4];
#pragma unroll
    for (int i = 0; i < 4; i++)
#pragma unroll
        for (int j = 0; j < 4; j++) acc[i][j] = 0.0f;

    for (int k0 = 0; k0 < K; k0 += 16) {
#pragma unroll
        for (int e = tid; e < 64 * 16; e += 256) {
            int m = e >> 4, k = e & 15;
            int gm = m0 + m, gk = k0 + k;
            As[k][m] = (gm < M && gk < K) ? A[(size_t)gm * lda + gk] : 0.0f;
        }
#pragma unroll
        for (int e = tid; e < 16 * 64; e += 256) {
            int k = e >> 6, n = e & 63;
            int gk = k0 + k, gn = n0 + n;
            Bs[k][n] = (gk < K && gn < N) ? B[(size_t)gk * ldb + gn] : 0.0f;
        }
        __syncthreads();

#pragma unroll
        for (int k = 0; k < 16; k++) {
            float4 av = *(const float4*)&As[k][ty * 4];
            float4 bv = *(const float4*)&Bs[k][tx * 4];
            float a4[4] = {av.x, av.y, av.z, av.w};
            float b4[4] = {bv.x, bv.y, bv.z, bv.w};
#pragma unroll
            for (int i = 0; i < 4; i++)
#pragma unroll
                for (int j = 0; j < 4; j++)
                    acc[i][j] += a4[i] * b4[j];
        }
        __syncthreads();
    }

#pragma unroll
    for (int i = 0; i < 4; i++) {
        int gm = m0 + ty * 4 + i;
        if (gm >= M) continue;
#pragma unroll
        for (int j = 0; j < 4; j++) {
            int gn = n0 + tx * 4 + j;
            if (gn >= N) continue;
            float v = acc[i][j];
            if (HAS_BIAS) v += bias[gn];
            if (DO_SILU)  v = silu_f(v);
            C[(size_t)gm * ldc + gn] = v;
        }
    }
}

// ---------------------------- prolog kernels --------------------------------

__global__ void __launch_bounds__(256) k_w1g1(const float* __restrict__ w1,
                                              const float* __restrict__ g1) {
    int l = blockIdx.z;
    gemm_tile<false, false>(w1 + (size_t)l * CIN * HID, HID, g1, HID, nullptr,
                            g_W1G1 + (size_t)l * CIN * HID, HID, CIN, HID, HID);
}

__global__ void __launch_bounds__(256) k_g3w2(const float* __restrict__ g3,
                                              const float* __restrict__ w2) {
    int l = blockIdx.z;
    gemm_tile<false, false>(g3, HID, w2 + (size_t)l * HID * CIN, CIN, nullptr,
                            g_G3W2 + (size_t)l * HID * CIN, CIN, HID, CIN, HID);
}

__global__ void k_b1g1(const float* __restrict__ b1, const float* __restrict__ g1) {
    int k = threadIdx.x;
    float s = 0.0f;
    for (int h = 0; h < HID; h++) s += b1[h] * g1[(size_t)h * HID + k];
    g_b1g1[k] = s;
}

// g_Tb [384 x 64]: hi(T[p][i]); pads 0.
__global__ void k_prepT(const float* __restrict__ T) {
    int p = blockIdx.x;
    int i = threadIdx.x;
    float v = (p < NP && i < NC) ? T[p * NC + i] : 0.0f;
    g_Tb[p * 64 + i] = __float2half_rn(v);
}

// g_FTb [64 x 352]: hi(F[p][i]); pads 0.
__global__ void k_prepFT(const float* __restrict__ F) {
    int i = blockIdx.x;
    int p = threadIdx.x;
    float v = (i < NC && p < NP) ? F[p * NC + i] : 0.0f;
    g_FTb[i * PBLK + p] = __float2half_rn(v);
}

// g_g2b [256 x 256] rows n: hi(g2[k][n])
__global__ void k_prepg2(const float* __restrict__ g2) {
    int k = blockIdx.x;
    int n = threadIdx.x;
    g_g2b[(size_t)n * 256 + k] = __float2half_rn(g2[(size_t)k * HID + n]);
}

// g_w1g1h [l][n(256)][128]: hi(W1G1[l][k][n])
__global__ void k_prep_w1g1h() {
    int l = blockIdx.x, n = blockIdx.y, k = threadIdx.x;
    g_w1g1h[((size_t)l * HID + n) * 128 + k] =
        __float2half_rn(g_W1G1[((size_t)l * CIN + k) * HID + n]);
}

// g_g3w2h [l][n(128)][256]: hi(G3W2[l][k][n])
__global__ void k_prep_g3w2h() {
    int l = blockIdx.x, n = blockIdx.y, k = threadIdx.x;
    g_g3w2h[((size_t)l * CIN + n) * 256 + k] =
        __float2half_rn(g_G3W2[((size_t)l * HID + k) * CIN + n]);
}

// nf -> fp16
__global__ void k_prep_nfh(const float* __restrict__ nf) {
    size_t idx = ((size_t)blockIdx.x * blockDim.x + threadIdx.x) * 2;
    float2 v = *(const float2*)(nf + idx);
    *(uint32_t*)&g_nfh[idx] = pkh2(v.x, v.y);
}

// zero y pad rows (rows [49,64))
__global__ void k_pad_yb() {
    int q = blockIdx.x;
    int node = blockIdx.y;
    int row = NC + q;
    *(uint32_t*)&g_yb[(size_t)node * (64 * HID) + (size_t)row * HID + threadIdx.x * 2] = 0;
}

// zero grid2b pad rows (rows [324,352))
__global__ void k_pad_g2b() {
    int q = blockIdx.x;
    int node = blockIdx.y;
    int row = NP + q;
    *(uint32_t*)&g_grid2b[(size_t)node * (PBLK * HID) + (size_t)row * HID + threadIdx.x * 2] = 0;
}

// ---------------------------- main stage kernels ----------------------------

__global__ void __launch_bounds__(256) k_gate(const float* __restrict__ nf,
                                              const float* __restrict__ ws,
                                              const float* __restrict__ bs) {
    gemm_tile<true, true>(nf, NC * CIN, ws, HID, bs, g_gate, HID,
                          N_NODES, HID, CIN);
}

// ---------------- y = nfh @ W1G1[l] : fp16 MMA, K=128, 256 thr --------------
__global__ void __launch_bounds__(256, 1) k_y_mma() {
    extern __shared__ __align__(128) char smem[];
    const uint32_t sbase = smem_u32(smem);
    const int tid = threadIdx.x;
    const int wid = tid >> 5;
    const int lid = tid & 31;
    const int wm  = wid & 1;
    const int wn  = wid >> 1;
    const int i   = blockIdx.y;
    const int l   = deg_of(i);
    const int m0  = blockIdx.x * BM;

    const uint32_t STAGE = BM * 64 + BN * 64;    // 24576
    const uint32_t BOFF  = BM * 64;

    uint32_t a_addr[4][2], b_addr[4][2];
#pragma unroll
    for (int mt = 0; mt < 4; mt++)
#pragma unroll
        for (int ks = 0; ks < 2; ks++) {
            int row = wm * 64 + mt * 16 + (lid & 7) + ((lid >> 3) & 1) * 8;
            int ch  = ks * 2 + (lid >> 4);
            a_addr[mt][ks] = sbase + row * 64 + 16 * (ch ^ ((row >> 1) & 3));
        }
#pragma unroll
    for (int np = 0; np < 4; np++)
#pragma unroll
        for (int ks = 0; ks < 2; ks++) {
            int row = wn * 64 + np * 16 + (lid & 7) + (lid >> 4) * 8;
            int ch  = ks * 2 + ((lid >> 3) & 1);
            b_addr[np][ks] = sbase + BOFF + row * 64 + 16 * (ch ^ ((row >> 1) & 3));
        }

    uint32_t a_rel[2], b_rel[4];
    const __half* a_base[2];
    const __half* b_base[4];
#pragma unroll
    for (int j = 0; j < 2; j++) {
        int id = tid + j * 256, r = id >> 2, c = id & 3;
        a_rel[j] = sbase + r * 64 + 16 * (c ^ ((r >> 1) & 3));
        a_base[j] = g_nfh + ((size_t)(m0 + r) * NC + i) * CIN + c * 8;
    }
#pragma unroll
    for (int j = 0; j < 4; j++) {
        int id = tid + j * 256, r = id >> 2, c = id & 3;
        b_rel[j] = sbase + BOFF + r * 64 + 16 * (c ^ ((r >> 1) & 3));
        b_base[j] = g_w1g1h + ((size_t)l * HID + r) * 128 + c * 8;
    }

    float acc[4][8][4];
#pragma unroll
    for (int mt = 0; mt < 4; mt++)
#pragma unroll
        for (int nt = 0; nt < 8; nt++)
#pragma unroll
            for (int v = 0; v < 4; v++) acc[mt][nt][v] = 0.0f;

#pragma unroll
    for (int s = 0; s < 3; s++) {
        uint32_t so = s * STAGE;
        if (s < NITERY) {
#pragma unroll
            for (int j = 0; j < 2; j++) cp_async16(a_rel[j] + so, a_base[j] + s * 32);
#pragma unroll
            for (int j = 0; j < 4; j++) cp_async16(b_rel[j] + so, b_base[j] + s * 32);
        }
        asm volatile("cp.async.commit_group;");
    }

#pragma unroll 1
    for (int kc = 0; kc < NITERY; kc++) {
        asm volatile("cp.async.wait_group 2;");
        __syncthreads();
        int pf = kc + 3;
        if (pf < NITERY) {
            uint32_t so = (pf & 3) * STAGE;
#pragma unroll
            for (int j = 0; j < 2; j++) cp_async16(a_rel[j] + so, a_base[j] + pf * 32);
#pragma unroll
            for (int j = 0; j < 4; j++) cp_async16(b_rel[j] + so, b_base[j] + pf * 32);
        }
        asm volatile("cp.async.commit_group;");

        const uint32_t so = (kc & 3) * STAGE;
#pragma unroll
        for (int ks = 0; ks < 2; ks++) {
            uint32_t af[4][4], bf[8][2];
#pragma unroll
            for (int mt = 0; mt < 4; mt++)
                ldsm_x4(af[mt][0], af[mt][1], af[mt][2], af[mt][3],
                        a_addr[mt][ks] + so);
#pragma unroll
            for (int np = 0; np < 4; np++)
                ldsm_x4(bf[2 * np][0], bf[2 * np][1], bf[2 * np + 1][0],
                        bf[2 * np + 1][1], b_addr[np][ks] + so);
#pragma unroll
            for (int mt = 0; mt < 4; mt++)
#pragma unroll
                for (int nt = 0; nt < 8; nt++)
                    mma_f16(acc[mt][nt], af[mt], bf[nt]);
        }
    }

    const int tq = lid >> 2;
    const int tr = lid & 3;
#pragma unroll
    for (int mt = 0; mt < 4; mt++) {
#pragma unroll
        for (int half = 0; half < 2; half++) {
            int node = m0 + wm * 64 + mt * 16 + tq + half * 8;
            __half* row = g_yb + ((size_t)node * 64 + i) * HID;
#pragma unroll
            for (int nt = 0; nt < 8; nt++) {
                int col = wn * 64 + nt * 8 + tr * 2;
                float v0 = acc[mt][nt][half * 2 + 0];
                float v1 = acc[mt][nt][half * 2 + 1];
                if (i == 0) { v0 += g_b1g1[col]; v1 += g_b1g1[col + 1]; }
                *(uint32_t*)&row[col] = pkh2(v0, v1);
            }
        }
    }
}

// ---------------- FUSED grid1+grid2, 512 thr, per (m-tile, node) ------------
// Phase 1: g1t = silu(Tb[m0:m0+128] @ y[node])   K=64, all-smem, no pipe.
//          Result written to MID in grid2 A-chunk swizzled layout.
// Phase 2: grid2 = silu(g1t @ g2b)  K=256, A from MID (no loads), B 4-stage.
__global__ void __launch_bounds__(512, 1) k_fused12() {
    extern __shared__ __align__(128) char smem[];
    const uint32_t sbase = smem_u32(smem);
    const int tid = threadIdx.x;
    const int wid = tid >> 5;           // 0..15
    const int lid = tid & 31;
    const int wm  = wid & 1;            // M half (64 rows)
    const int wn  = wid >> 1;           // 0..7, 32 cols each
    const int node = blockIdx.y;
    const int m0 = blockIdx.x * BM;     // rows in padded 384

    const uint32_t P1A = 0;             // Tb tile: 2 chunks x 8 KB
    const uint32_t P1B = 16384;         // y tile: 64 rows x 512 B = 32 KB
    const uint32_t MID = 49152;         // g1t: 8 chunks x 8 KB = 64 KB
    const uint32_t P2B = 114688;        // g2 stages: 4 x 16 KB = 64 KB

    const int tq = lid >> 2;
    const int tr = lid & 3;

    // ---- phase 1 ldsm addresses ----
    uint32_t a1[4][4];                  // [mt][kk], kk = kc*2+ks over K=64
#pragma unroll
    for (int mt = 0; mt < 4; mt++)
#pragma unroll
        for (int kk = 0; kk < 4; kk++) {
            int kc = kk >> 1, ks = kk & 1;
            int row = wm * 64 + mt * 16 + (lid & 7) + ((lid >> 3) & 1) * 8;
            int ch  = ks * 2 + (lid >> 4);
            a1[mt][kk] = sbase + P1A + kc * 8192 + row * 64 + 16 * (ch ^ ((row >> 1) & 3));
        }
    uint32_t b1[2][4];                  // [np][kk], trans-ldsm over y rows
#pragma unroll
    for (int np = 0; np < 2; np++)
#pragma unroll
        for (int kk = 0; kk < 4; kk++) {
            int kc = kk >> 1, ks = kk & 1;
            int row = kc * 32 + ks * 16 + (lid & 7) + 8 * ((lid >> 3) & 1);
            int cn  = wn * 4 + np * 2 + (lid >> 4);
            b1[np][kk] = sbase + P1B + row * 512 + 16 * (cn ^ (row & 7));
        }

    // ---- phase 1 loads (single group) ----
    const __half* ybn = g_yb + (size_t)node * (64 * HID);
#pragma unroll
    for (int j = 0; j < 2; j++) {       // Tb: 1024 x 16B
        int id = tid + j * 512;
        int r = id >> 3, rem = id & 7, kc = rem >> 2, c = rem & 3;
        cp_async16(sbase + P1A + kc * 8192 + r * 64 + 16 * (c ^ ((r >> 1) & 3)),
                   g_Tb + (m0 + r) * 64 + kc * 32 + c * 8);
    }
#pragma unroll
    for (int j = 0; j < 4; j++) {       // y: 2048 x 16B
        int id = tid + j * 512;
        int r = id >> 5, c = id & 31;
        cp_async16(sbase + P1B + r * 512 + 16 * (c ^ (r & 7)),
                   ybn + r * HID + c * 8);
    }
    asm volatile("cp.async.commit_group;");   // c0

    // ---- prefetch phase-2 B stages 0..2 (overlaps phase-1 compute) ----
#pragma unroll
    for (int s = 0; s < 3; s++) {
#pragma unroll
        for (int j = 0; j < 2; j++) {
            int id = tid + j * 512;
            int r = id >> 2, c = id & 3;
            cp_async16(sbase + P2B + s * 16384 + r * 64 + 16 * (c ^ ((r >> 1) & 3)),
                       g_g2b + (size_t)r * 256 + s * 32 + c * 8);
        }
        asm volatile("cp.async.commit_group;");   // c1..c3
    }

    // ---- phase 1 compute ----
    asm volatile("cp.async.wait_group 3;");       // c0 done
    __syncthreads();

    float acc1[4][4][4];
#pragma unroll
    for (int mt = 0; mt < 4; mt++)
#pragma unroll
        for (int nt = 0; nt < 4; nt++)
#pragma unroll
            for (int v = 0; v < 4; v++) acc1[mt][nt][v] = 0.0f;

#pragma unroll
    for (int kk = 0; kk < 4; kk++) {
        uint32_t af[4][4], bf[4][2];
#pragma unroll
        for (int mt = 0; mt < 4; mt++)
            ldsm_x4(af[mt][0], af[mt][1], af[mt][2], af[mt][3], a1[mt][kk]);
#pragma unroll
        for (int np = 0; np < 2; np++)
            ldsm_x4_t(bf[2 * np][0], bf[2 * np][1], bf[2 * np + 1][0],
                      bf[2 * np + 1][1], b1[np][kk]);
#pragma unroll
        for (int mt = 0; mt < 4; mt++)
#pragma unroll
            for (int nt = 0; nt < 4; nt++)
                mma_f16(acc1[mt][nt], af[mt], bf[nt]);
    }

    // ---- phase 1 epilogue: silu -> MID (grid2 A-chunk swizzle) ----
    // thread covers rows wm*64+mt*16+tq(+8), cols wn*32+nt*8+tr*2
    // chunk = wn, group = nt, byte off = tr*4
#pragma unroll
    for (int mt = 0; mt < 4; mt++) {
#pragma unroll
        for (int half = 0; half < 2; half++) {
            int row = wm * 64 + mt * 16 + tq + half * 8;
#pragma unroll
            for (int nt = 0; nt < 4; nt++) {
                uint32_t off = MID + wn * 8192 + row * 64 +
                               16 * (nt ^ ((row >> 1) & 3)) + tr * 4;
                *(uint32_t*)(smem + off) =
                    pkh2(silu_f(acc1[mt][nt][half * 2 + 0]),
                         silu_f(acc1[mt][nt][half * 2 + 1]));
            }
        }
    }
    __syncthreads();

    // ---- phase 2 addresses ----
    uint32_t a2[4][2];
#pragma unroll
    for (int mt = 0; mt < 4; mt++)
#pragma unroll
        for (int ks = 0; ks < 2; ks++) {
            int row = wm * 64 + mt * 16 + (lid & 7) + ((lid >> 3) & 1) * 8;
            int ch  = ks * 2 + (lid >> 4);
            a2[mt][ks] = sbase + MID + row * 64 + 16 * (ch ^ ((row >> 1) & 3));
        }
    uint32_t b2[2][2];
#pragma unroll
    for (int np = 0; np < 2; np++)
#pragma unroll
        for (int ks = 0; ks < 2; ks++) {
            int row = wn * 32 + np * 16 + (lid & 7) + (lid >> 4) * 8;
            int ch  = ks * 2 + ((lid >> 3) & 1);
            b2[np][ks] = sbase + P2B + row * 64 + 16 * (ch ^ ((row >> 1) & 3));
        }

    float acc2[4][4][4];
#pragma unroll
    for (int mt = 0; mt < 4; mt++)
#pragma unroll
        for (int nt = 0; nt < 4; nt++)
#pragma unroll
            for (int v = 0; v < 4; v++) acc2[mt][nt][v] = 0.0f;

    // ---- phase 2 mainloop (B pipelined, A resident in MID) ----
#pragma unroll 1
    for (int kc = 0; kc < NITERF2; kc++) {
        asm volatile("cp.async.wait_group 2;");
        __syncthreads();
        int pf = kc + 3;
        if (pf < NITERF2) {
            uint32_t so = (pf & 3) * 16384;
#pragma unroll
            for (int j = 0; j < 2; j++) {
                int id = tid + j * 512;
                int r = id >> 2, c = id & 3;
                cp_async16(sbase + P2B + so + r * 64 + 16 * (c ^ ((r >> 1) & 3)),
                           g_g2b + (size_t)r * 256 + pf * 32 + c * 8);
            }
        }
        asm volatile("cp.async.commit_group;");

        const uint32_t so_b = (kc & 3) * 16384;
        const uint32_t so_a = kc * 8192;
#pragma unroll
        for (int ks = 0; ks < 2; ks++) {
            uint32_t af[4][4], bf[4][2];
#pragma unroll
            for (int mt = 0; mt < 4; mt++)
                ldsm_x4(af[mt][0], af[mt][1], af[mt][2], af[mt][3],
                        a2[mt][ks] + so_a);
#pragma unroll
            for (int np = 0; np < 2; np++)
                ldsm_x4(bf[2 * np][0], bf[2 * np][1], bf[2 * np + 1][0],
                        bf[2 * np + 1][1], b2[np][ks] + so_b);
#pragma unroll
            for (int mt = 0; mt < 4; mt++)
#pragma unroll
                for (int nt = 0; nt < 4; nt++)
                    mma_f16(acc2[mt][nt], af[mt], bf[nt]);
        }
    }

    // ---- phase 2 epilogue: silu -> g_grid2b (guard p < NP) ----
#pragma unroll
    for (int mt = 0; mt < 4; mt++) {
#pragma unroll
        for (int half = 0; half < 2; half++) {
            int p = m0 + wm * 64 + mt * 16 + tq + half * 8;
            if (p >= NP) continue;
            __half* row = g_grid2b + ((size_t)node * PBLK + p) * HID;
#pragma unroll
            for (int nt = 0; nt < 4; nt++) {
                int col = wn * 32 + nt * 8 + tr * 2;
                *(uint32_t*)&row[col] = pkh2(silu_f(acc2[mt][nt][half * 2 + 0]),
                                             silu_f(acc2[mt][nt][half * 2 + 1]));
            }
        }
    }
}

// -------- z = F^T @ grid2[n] : fp16 MMA, K=352, trans-B, 512 thr ------------
__global__ void __launch_bounds__(512, 1) k_z_mma() {
    extern __shared__ __align__(128) char smem[];
    const uint32_t sbase = smem_u32(smem);
    const int tid = threadIdx.x;
    const int wid = tid >> 5;           // 0..15, 16 cols each
    const int lid = tid & 31;
    const int node = blockIdx.x;

    const uint32_t STAGE = 64 * 64 + BK * 512;   // 20480
    const uint32_t BOFF  = 64 * 64;

    uint32_t a_addr[4][2], b_addr[2];
#pragma unroll
    for (int mt = 0; mt < 4; mt++)
#pragma unroll
        for (int ks = 0; ks < 2; ks++) {
            int row = mt * 16 + (lid & 7) + ((lid >> 3) & 1) * 8;
            int ch  = ks * 2 + (lid >> 4);
            a_addr[mt][ks] = sbase + row * 64 + 16 * (ch ^ ((row >> 1) & 3));
        }
#pragma unroll
    for (int ks = 0; ks < 2; ks++) {
        int row = ks * 16 + (lid & 7) + 8 * ((lid >> 3) & 1);
        int cn  = wid * 2 + (lid >> 4);
        b_addr[ks] = sbase + BOFF + row * 512 + 16 * (cn ^ (row & 7));
    }

    uint32_t a_rel = 0, b_rel[2];
    const __half* a_basep = nullptr;
    const __half* b_base[2];
    const __half* g2bn = g_grid2b + (size_t)node * (PBLK * HID);
    if (tid < 256) {
        int r = tid >> 2, c = tid & 3;
        a_rel = sbase + r * 64 + 16 * (c ^ ((r >> 1) & 3));
        a_basep = g_FTb + r * PBLK + c * 8;
    }
#pragma unroll
    for (int j = 0; j < 2; j++) {
        int id = tid + j * 512, r = id >> 5, c = id & 31;
        b_rel[j] = sbase + BOFF + r * 512 + 16 * (c ^ (r & 7));
        b_base[j] = g2bn + r * HID + c * 8;
    }

    float acc[4][2][4];
#pragma unroll
    for (int mt = 0; mt < 4; mt++)
#pragma unroll
        for (int nt = 0; nt < 2; nt++)
#pragma unroll
            for (int v = 0; v < 4; v++) acc[mt][nt][v] = 0.0f;

#pragma unroll
    for (int s = 0; s < 3; s++) {
        uint32_t so = s * STAGE;
        if (tid < 256) cp_async16(a_rel + so, a_basep + s * 32);
#pragma unroll
        for (int j = 0; j < 2; j++) cp_async16(b_rel[j] + so, b_base[j] + s * 32 * HID);
        asm volatile("cp.async.commit_group;");
    }

#pragma unroll 1
    for (int kc = 0; kc < NITERZ; kc++) {
        asm volatile("cp.async.wait_group 2;");
        __syncthreads();
        int pf = kc + 3;
        if (pf < NITERZ) {
            uint32_t so = (pf & 3) * STAGE;
            if (tid < 256) cp_async16(a_rel + so, a_basep + pf * 32);
#pragma unroll
            for (int j = 0; j < 2; j++) cp_async16(b_rel[j] + so, b_base[j] + pf * 32 * HID);
        }
        asm volatile("cp.async.commit_group;");

        const uint32_t so = (kc & 3) * STAGE;
#pragma unroll
        for (int ks = 0; ks < 2; ks++) {
            uint32_t af[4][4], bf[2][2];
#pragma unroll
            for (int mt = 0; mt < 4; mt++)
                ldsm_x4(af[mt][0], af[mt][1], af[mt][2], af[mt][3],
                        a_addr[mt][ks] + so);
            ldsm_x4_t(bf[0][0], bf[0][1], bf[1][0], bf[1][1], b_addr[ks] + so);
#pragma unroll
            for (int mt = 0; mt < 4; mt++)
#pragma unroll
                for (int nt = 0; nt < 2; nt++)
                    mma_f16(acc[mt][nt], af[mt], bf[nt]);
        }
    }

    const int tq = lid >> 2;
    const int tr = lid & 3;
#pragma unroll
    for (int mt = 0; mt < 4; mt++) {
#pragma unroll
        for (int half = 0; half < 2; half++) {
            int i = mt * 16 + tq + half * 8;
            if (i >= NC) continue;
            __half* row = g_zh + ((size_t)node * NC + i) * HID;
#pragma unroll
            for (int nt = 0; nt < 2; nt++) {
                int col = wid * 16 + nt * 8 + tr * 2;
                *(uint32_t*)&row[col] = pkh2(acc[mt][nt][half * 2 + 0],
                                             acc[mt][nt][half * 2 + 1]);
            }
        }
    }
}

// ---------------- out[:,i,:] = z[:,i,:] @ G3W2[l]: fp16 MMA (i>=1) ----------
__global__ void __launch_bounds__(256, 1) k_out_mma(float* __restrict__ out) {
    extern __shared__ __align__(128) char smem[];
    const uint32_t sbase = smem_u32(smem);
    const int tid = threadIdx.x;
    const int wid = tid >> 5;
    const int lid = tid & 31;
    const int wm  = wid & 1;
    const int wn  = wid >> 1;   // 0..3, 32 cols each
    const int i   = blockIdx.y + 1;
    const int l   = deg_of(i);
    const int m0  = blockIdx.x * BM;

    const uint32_t STAGE = BM * 64 + CIN * 64;   // 16384
    const uint32_t BOFF  = BM * 64;

    uint32_t a_addr[4][2], b_addr[2][2];
#pragma unroll
    for (int mt = 0; mt < 4; mt++)
#pragma unroll
        for (int ks = 0; ks < 2; ks++) {
            int row = wm * 64 + mt * 16 + (lid & 7) + ((lid >> 3) & 1) * 8;
            int ch  = ks * 2 + (lid >> 4);
            a_addr[mt][ks] = sbase + row * 64 + 16 * (ch ^ ((row >> 1) & 3));
        }
#pragma unroll
    for (int np = 0; np < 2; np++)
#pragma unroll
        for (int ks = 0; ks < 2; ks++) {
            int row = wn * 32 + np * 16 + (lid & 7) + (lid >> 4) * 8;
            int ch  = ks * 2 + ((lid >> 3) & 1);
            b_addr[np][ks] = sbase + BOFF + row * 64 + 16 * (ch ^ ((row >> 1) & 3));
        }

    uint32_t a_rel[2], b_rel[2];
    const __half* a_base[2];
    const __half* b_base[2];
#pragma unroll
    for (int j = 0; j < 2; j++) {
        int id = tid + j * 256, r = id >> 2, c = id & 3;
        a_rel[j] = sbase + r * 64 + 16 * (c ^ ((r >> 1) & 3));
        a_base[j] = g_zh + ((size_t)(m0 + r) * NC + i) * HID + c * 8;
        b_rel[j] = sbase + BOFF + r * 64 + 16 * (c ^ ((r >> 1) & 3));
        b_base[j] = g_g3w2h + ((size_t)l * CIN + r) * 256 + c * 8;
    }

    float acc[4][4][4];
#pragma unroll
    for (int mt = 0; mt < 4; mt++)
#pragma unroll
        for (int nt = 0; nt < 4; nt++)
#pragma unroll
            for (int v = 0; v < 4; v++) acc[mt][nt][v] = 0.0f;

#pragma unroll
    for (int s = 0; s < 3; s++) {
        uint32_t so = s * STAGE;
#pragma unroll
        for (int j = 0; j < 2; j++) {
            cp_async16(a_rel[j] + so, a_base[j] + s * 32);
            cp_async16(b_rel[j] + so, b_base[j] + s * 32);
        }
        asm volatile("cp.async.commit_group;");
    }

#pragma unroll 1
    for (int kc = 0; kc < NITERO; kc++) {
        asm volatile("cp.async.wait_group 2;");
        __syncthreads();
        int pf = kc + 3;
        if (pf < NITERO) {
            uint32_t so = (pf & 3) * STAGE;
#pragma unroll
            for (int j = 0; j < 2; j++) {
                cp_async16(a_rel[j] + so, a_base[j] + pf * 32);
                cp_async16(b_rel[j] + so, b_base[j] + pf * 32);
            }
        }
        asm volatile("cp.async.commit_group;");

        const uint32_t so = (kc & 3) * STAGE;
#pragma unroll
        for (int ks = 0; ks < 2; ks++) {
            uint32_t af[4][4], bf[4][2];
#pragma unroll
            for (int mt = 0; mt < 4; mt++)
                ldsm_x4(af[mt][0], af[mt][1], af[mt][2], af[mt][3],
                        a_addr[mt][ks] + so);
#pragma unroll
            for (int np = 0; np < 2; np++)
                ldsm_x4(bf[2 * np][0], bf[2 * np][1], bf[2 * np + 1][0],
                        bf[2 * np + 1][1], b_addr[np][ks] + so);
#pragma unroll
            for (int mt = 0; mt < 4; mt++)
#pragma unroll
                for (int nt = 0; nt < 4; nt++)
                    mma_f16(acc[mt][nt], af[mt], bf[nt]);
        }
    }

    const int tq = lid >> 2;
    const int tr = lid & 3;
#pragma unroll
    for (int mt = 0; mt < 4; mt++) {
#pragma unroll
        for (int half = 0; half < 2; half++) {
            int node = m0 + wm * 64 + mt * 16 + tq + half * 8;
            float* row = out + ((size_t)node * NC + i) * CIN;
#pragma unroll
            for (int nt = 0; nt < 4; nt++) {
                int col = wn * 32 + nt * 8 + tr * 2;
                float2 v;
                v.x = acc[mt][nt][half * 2 + 0];
                v.y = acc[mt][nt][half * 2 + 1];
                *(float2*)&row[col] = v;
            }
        }
    }
}

// out[:,0,:] = gate @ w2[0] + b2  (SIMT, tiny)
__global__ void __launch_bounds__(256) k_out0(const float* __restrict__ w2,
                                              const float* __restrict__ b2,
                                              float* __restrict__ out) {
    gemm_tile<false, true>(g_gate, HID, w2, CIN, b2,
                           out, NC * CIN, N_NODES, CIN, HID);
}

// ---------------------------------------------------------------------------

extern "C" void kernel_launch(void* const* d_in, const int* in_sizes, int n_in,
                              void* d_out, int out_size) {
    const float* nf = (const float*)d_in[0];
    const float* w1 = (const float*)d_in[1];
    const float* b1 = (const float*)d_in[2];
    const float* w2 = (const float*)d_in[3];
    const float* b2 = (const float*)d_in[4];
    const float* ws = (const float*)d_in[5];
    const float* bs = (const float*)d_in[6];
    const float* g1 = (const float*)d_in[7];
    const float* g2 = (const float*)d_in[8];
    const float* g3 = (const float*)d_in[9];
    const float* Tg = (const float*)d_in[10];
    const float* Fg = (const float*)d_in[11];
    float* out = (float*)d_out;

    const int SMEMF = 49152 + 65536 + 65536;      // 180224 (fused)
    const int SMEMZ = 4 * (64 * 64 + BK * 512);   // 81920
    const int SMEMY = 4 * (BM * 64 + BN * 64);    // 98304
    const int SMEMO = 4 * (BM * 64 + CIN * 64);   // 65536
    cudaFuncSetAttribute(k_fused12, cudaFuncAttributeMaxDynamicSharedMemorySize, SMEMF);
    cudaFuncSetAttribute(k_z_mma,   cudaFuncAttributeMaxDynamicSharedMemorySize, SMEMZ);
    cudaFuncSetAttribute(k_y_mma,   cudaFuncAttributeMaxDynamicSharedMemorySize, SMEMY);
    cudaFuncSetAttribute(k_out_mma, cudaFuncAttributeMaxDynamicSharedMemorySize, SMEMO);

    // prologs
    k_w1g1<<<dim3(HID / 64, CIN / 64, NL), 256>>>(w1, g1);
    k_g3w2<<<dim3(CIN / 64, HID / 64, NL), 256>>>(g3, w2);
    k_b1g1<<<1, HID>>>(b1, g1);
    k_prepT<<<384, 64>>>(Tg);
    k_prepFT<<<64, PBLK>>>(Fg);
    k_prepg2<<<256, 256>>>(g2);
    k_prep_w1g1h<<<dim3(NL, HID), CIN>>>();
    k_prep_g3w2h<<<dim3(NL, CIN), HID>>>();
    k_prep_nfh<<<(int)((size_t)N_NODES * NC * CIN / 512), 256>>>(nf);
    k_pad_yb<<<dim3(15, N_NODES), 128>>>();
    k_pad_g2b<<<dim3(28, N_NODES), 128>>>();

    // scalar gating branch
    k_gate<<<dim3(HID / 64, N_NODES / 64), 256>>>(nf, ws, bs);

    // main pipeline (all MMA)
    k_y_mma<<<dim3(N_NODES / BM, NC), 256, SMEMY>>>();
    k_fused12<<<dim3(3, N_NODES), 512, SMEMF>>>();
    k_z_mma<<<N_NODES, 512, SMEMZ>>>();
    k_out_mma<<<dim3(N_NODES / BM, NC - 1), 256, SMEMO>>>(out);
    k_out0<<<dim3(CIN / 64, N_NODES / 64), 256>>>(w2, b2, out);
}

// round 11
// speedup vs baseline: 1.1676x; 1.1676x over previous
#include <cuda_runtime.h>
#include <cuda_fp16.h>
#include <cstdint>

// ---------------------------------------------------------------------------
// FeedForwardNetwork (SO(3) equivariant FFN), sm_103a — all-MMA plain-fp16
// Round 11: revert round-10 fusion (regressed); R9 split kernels + overhead
// pack: fp16 weight prep folded into prolog GEMMs, one mega-prep kernel,
// 10 launches total (6th = k_grid2_mma for ncu -s 5 capture).
// ---------------------------------------------------------------------------

#define N_NODES 1024
#define NC      49
#define CIN     128
#define HID     256
#define RES     18
#define NP      (RES*RES)   // 324
#define NL      7
#define MROWS   ((size_t)N_NODES * NP)   // 331776
#define PBLK    352
#define BM      128
#define BN      256
#define BK      32
#define NITER1  2            // grid1 K chunks (64/32)
#define NITER2  8            // grid2 K chunks (256/32)
#define NITERZ  11           // z K chunks (352/32)
#define NITERY  4            // y K chunks (128/32)
#define NITERO  8            // out K chunks (256/32)

// -------- scratch (static device globals; no runtime allocation) -----------
__device__ float g_b1g1[HID];
__device__ __half g_Tb[384 * 64];                    // to_grid hi [384x64]
__device__ __half g_FTb[64 * PBLK];                  // from_grid^T hi [64x352]
__device__ __half g_g2b[HID * 256];                  // g2^T hi [256x256]
__device__ __half g_w1g1h[NL * HID * 128];           // W1G1^T hi rows
__device__ __half g_g3w2h[NL * CIN * 256];           // (g3 w2)^T hi rows
__device__ __half g_nfh[(size_t)N_NODES * NC * CIN];       // 12.8 MB
__device__ __half g_yb[(size_t)N_NODES * 64 * HID];        // 34 MB
__device__ __half g_grid1b[MROWS * HID];                   // 170 MB
__device__ __half g_grid2b[(size_t)N_NODES * PBLK * HID];  // 185 MB
__device__ __half g_zh[(size_t)N_NODES * NC * HID];        // 25.7 MB
__device__ float g_gate[(size_t)N_NODES * HID];

__device__ __forceinline__ float silu_f(float x) {
    return x / (1.0f + __expf(-x));
}
__device__ __forceinline__ int deg_of(int i) {
    int l = 0;
    while ((l + 1) * (l + 1) <= i) ++l;
    return l;
}
__device__ __forceinline__ uint32_t smem_u32(const void* p) {
    uint32_t a;
    asm("{ .reg .u64 t; cvta.to.shared.u64 t, %1; cvt.u32.u64 %0, t; }"
        : "=r"(a) : "l"(p));
    return a;
}
__device__ __forceinline__ void cp_async16(uint32_t dst, const void* src) {
    asm volatile("cp.async.cg.shared.global [%0], [%1], 16;" :: "r"(dst), "l"(src));
}
__device__ __forceinline__ void ldsm_x4(uint32_t& r0, uint32_t& r1,
                                        uint32_t& r2, uint32_t& r3, uint32_t addr) {
    asm volatile("ldmatrix.sync.aligned.m8n8.x4.shared.b16 {%0,%1,%2,%3}, [%4];"
                 : "=r"(r0), "=r"(r1), "=r"(r2), "=r"(r3) : "r"(addr));
}
__device__ __forceinline__ void ldsm_x4_t(uint32_t& r0, uint32_t& r1,
                                          uint32_t& r2, uint32_t& r3, uint32_t addr) {
    asm volatile("ldmatrix.sync.aligned.m8n8.x4.trans.shared.b16 {%0,%1,%2,%3}, [%4];"
                 : "=r"(r0), "=r"(r1), "=r"(r2), "=r"(r3) : "r"(addr));
}
__device__ __forceinline__ void mma_f16(float* d, const uint32_t* a, const uint32_t* b) {
    asm volatile(
        "mma.sync.aligned.m16n8k16.row.col.f32.f16.f16.f32 "
        "{%0,%1,%2,%3}, {%4,%5,%6,%7}, {%8,%9}, {%0,%1,%2,%3};"
        : "+f"(d[0]), "+f"(d[1]), "+f"(d[2]), "+f"(d[3])
        : "r"(a[0]), "r"(a[1]), "r"(a[2]), "r"(a[3]), "r"(b[0]), "r"(b[1]));
}
__device__ __forceinline__ uint32_t pkh2(float x, float y) {
    __half hx = __float2half_rn(x), hy = __float2half_rn(y);
    uint16_t bx = *(uint16_t*)&hx, by = *(uint16_t*)&hy;
    return (uint32_t)bx | ((uint32_t)by << 16);
}

// ---------------------------------------------------------------------------
// Generic 64x64x16 SIMT tiled GEMM (gate / out0 only).
// ---------------------------------------------------------------------------
template<bool DO_SILU, bool HAS_BIAS>
__device__ __forceinline__ void gemm_tile(
    const float* __restrict__ A, int lda,
    const float* __restrict__ B, int ldb,
    const float* __restrict__ bias,
    float* __restrict__ C, int ldc,
    int M, int N, int K)
{
    __shared__ float As[16][64];
    __shared__ float Bs[16][64];

    const int tid = threadIdx.x;
    const int tx  = tid & 15;
    const int ty  = tid >> 4;
    const int m0  = blockIdx.y * 64;
    const int n0  = blockIdx.x * 64;

    float acc[4][4];
#pragma unroll
    for (int i = 0; i < 4; i++)
#pragma unroll
        for (int j = 0; j < 4; j++) acc[i][j] = 0.0f;

    for (int k0 = 0; k0 < K; k0 += 16) {
#pragma unroll
        for (int e = tid; e < 64 * 16; e += 256) {
            int m = e >> 4, k = e & 15;
            int gm = m0 + m, gk = k0 + k;
            As[k][m] = (gm < M && gk < K) ? A[(size_t)gm * lda + gk] : 0.0f;
        }
#pragma unroll
        for (int e = tid; e < 16 * 64; e += 256) {
            int k = e >> 6, n = e & 63;
            int gk = k0 + k, gn = n0 + n;
            Bs[k][n] = (gk < K && gn < N) ? B[(size_t)gk * ldb + gn] : 0.0f;
        }
        __syncthreads();

#pragma unroll
        for (int k = 0; k < 16; k++) {
            float4 av = *(const float4*)&As[k][ty * 4];
            float4 bv = *(const float4*)&Bs[k][tx * 4];
            float a4[4] = {av.x, av.y, av.z, av.w};
            float b4[4] = {bv.x, bv.y, bv.z, bv.w};
#pragma unroll
            for (int i = 0; i < 4; i++)
#pragma unroll
                for (int j = 0; j < 4; j++)
                    acc[i][j] += a4[i] * b4[j];
        }
        __syncthreads();
    }

#pragma unroll
    for (int i = 0; i < 4; i++) {
        int gm = m0 + ty * 4 + i;
        if (gm >= M) continue;
#pragma unroll
        for (int j = 0; j < 4; j++) {
            int gn = n0 + tx * 4 + j;
            if (gn >= N) continue;
            float v = acc[i][j];
            if (HAS_BIAS) v += bias[gn];
            if (DO_SILU)  v = silu_f(v);
            C[(size_t)gm * ldc + gn] = v;
        }
    }
}

// SIMT gemm body with custom fp16-transposed epilogue (weight prep).
// Writes OUT[(out_row_base + gn) * out_stride + gm] = fp16(C[gm][gn]).
__device__ __forceinline__ void gemm_tile_w16(
    const float* __restrict__ A, int lda,
    const float* __restrict__ B, int ldb,
    __half* __restrict__ OUT, int out_stride,
    int K)
{
    __shared__ float As[16][64];
    __shared__ float Bs[16][64];

    const int tid = threadIdx.x;
    const int tx  = tid & 15;
    const int ty  = tid >> 4;
    const int m0  = blockIdx.y * 64;
    const int n0  = blockIdx.x * 64;

    float acc[4][4];
#pragma unroll
    for (int i = 0; i < 4; i++)
#pragma unroll
        for (int j = 0; j < 4; j++) acc[i][j] = 0.0f;

    for (int k0 = 0; k0 < K; k0 += 16) {
#pragma unroll
        for (int e = tid; e < 64 * 16; e += 256) {
            int m = e >> 4, k = e & 15;
            As[k][m] = A[(size_t)(m0 + m) * lda + k0 + k];
        }
#pragma unroll
        for (int e = tid; e < 16 * 64; e += 256) {
            int k = e >> 6, n = e & 63;
            Bs[k][n] = B[(size_t)(k0 + k) * ldb + n0 + n];
        }
        __syncthreads();

#pragma unroll
        for (int k = 0; k < 16; k++) {
            float4 av = *(const float4*)&As[k][ty * 4];
            float4 bv = *(const float4*)&Bs[k][tx * 4];
            float a4[4] = {av.x, av.y, av.z, av.w};
            float b4[4] = {bv.x, bv.y, bv.z, bv.w};
#pragma unroll
            for (int i = 0; i < 4; i++)
#pragma unroll
                for (int j = 0; j < 4; j++)
                    acc[i][j] += a4[i] * b4[j];
        }
        __syncthreads();
    }

#pragma unroll
    for (int i = 0; i < 4; i++) {
        int gm = m0 + ty * 4 + i;
#pragma unroll
        for (int j = 0; j < 4; j++) {
            int gn = n0 + tx * 4 + j;
            OUT[(size_t)gn * out_stride + gm] = __float2half_rn(acc[i][j]);
        }
    }
}

// ---------------------------- prolog kernels --------------------------------

// z < NL: g_w1g1h[l][n][m] = fp16((w1[l] @ g1)[m][n]);  z == NL: b1g1.
__global__ void __launch_bounds__(256) k_w1g1_h(const float* __restrict__ w1,
                                                const float* __restrict__ g1,
                                                const float* __restrict__ b1) {
    if (blockIdx.z == NL) {
        if (blockIdx.x != 0 || blockIdx.y != 0) return;
        int k = threadIdx.x;
        float s = 0.0f;
        for (int h = 0; h < HID; h++) s += b1[h] * g1[(size_t)h * HID + k];
        g_b1g1[k] = s;
        return;
    }
    int l = blockIdx.z;
    gemm_tile_w16(w1 + (size_t)l * CIN * HID, HID, g1, HID,
                  g_w1g1h + (size_t)l * HID * 128, 128, HID);
}

// g_g3w2h[l][n][m] = fp16((g3 @ w2[l])[m][n])
__global__ void __launch_bounds__(256) k_g3w2_h(const float* __restrict__ g3,
                                                const float* __restrict__ w2) {
    int l = blockIdx.z;
    gemm_tile_w16(g3, HID, w2 + (size_t)l * HID * CIN, CIN,
                  g_g3w2h + (size_t)l * CIN * 256, 256, HID);
}

// Mega-prep: Tb | FTb | g2b | nfh | pad_yb | pad_g2b  (range dispatch).
#define PS_TB    96
#define PS_FTB   88
#define PS_G2B   256
#define PS_NFH   12544
#define PS_PADY  7680
#define PS_PADG  14336
__global__ void __launch_bounds__(256) k_prep_static(
    const float* __restrict__ nf, const float* __restrict__ T,
    const float* __restrict__ F,  const float* __restrict__ g2) {
    int b = blockIdx.x;
    int t = threadIdx.x;
    if (b < PS_TB) {                       // Tb [384 x 64]
        int idx = b * 256 + t;
        int p = idx >> 6, i = idx & 63;
        float v = (p < NP && i < NC) ? T[p * NC + i] : 0.0f;
        g_Tb[idx] = __float2half_rn(v);
        return;
    }
    b -= PS_TB;
    if (b < PS_FTB) {                      // FTb [64 x 352]
        int idx = b * 256 + t;
        int i = idx / PBLK, p = idx % PBLK;
        float v = (i < NC && p < NP) ? F[p * NC + i] : 0.0f;
        g_FTb[idx] = __float2half_rn(v);
        return;
    }
    b -= PS_FTB;
    if (b < PS_G2B) {                      // g2b [256 x 256] (transposed)
        int idx = b * 256 + t;
        int n = idx >> 8, k = idx & 255;
        g_g2b[idx] = __float2half_rn(g2[(size_t)k * HID + n]);
        return;
    }
    b -= PS_G2B;
    if (b < PS_NFH) {                      // nfh (2 floats / thread)
        size_t gi = ((size_t)b * 256 + t) * 2;
        float2 v = *(const float2*)(nf + gi);
        *(uint32_t*)&g_nfh[gi] = pkh2(v.x, v.y);
        return;
    }
    b -= PS_NFH;
    if (b < PS_PADY) {                     // zero yb rows [49,64)
        size_t w = (size_t)b * 256 + t;
        int node = (int)(w / 1920);
        int rem  = (int)(w % 1920);
        int row  = NC + rem / 128;
        int c2   = rem & 127;
        *(uint32_t*)&g_yb[((size_t)node * 64 + row) * HID + c2 * 2] = 0;
        return;
    }
    b -= PS_PADY;
    {                                      // zero grid2b rows [324,352)
        size_t w = (size_t)b * 256 + t;
        int node = (int)(w / 3584);
        int rem  = (int)(w % 3584);
        int row  = NP + rem / 128;
        int c2   = rem & 127;
        *(uint32_t*)&g_grid2b[((size_t)node * PBLK + row) * HID + c2 * 2] = 0;
    }
}

// ---------------------------- main stage kernels ----------------------------

__global__ void __launch_bounds__(256) k_gate(const float* __restrict__ nf,
                                              const float* __restrict__ ws,
                                              const float* __restrict__ bs) {
    gemm_tile<true, true>(nf, NC * CIN, ws, HID, bs, g_gate, HID,
                          N_NODES, HID, CIN);
}

// ---------------- y = nfh @ W1G1[l] : fp16 MMA, K=128, 256 thr --------------
__global__ void __launch_bounds__(256, 1) k_y_mma() {
    extern __shared__ __align__(128) char smem[];
    const uint32_t sbase = smem_u32(smem);
    const int tid = threadIdx.x;
    const int wid = tid >> 5;
    const int lid = tid & 31;
    const int wm  = wid & 1;
    const int wn  = wid >> 1;
    const int i   = blockIdx.y;
    const int l   = deg_of(i);
    const int m0  = blockIdx.x * BM;

    const uint32_t STAGE = BM * 64 + BN * 64;    // 24576
    const uint32_t BOFF  = BM * 64;

    uint32_t a_addr[4][2], b_addr[4][2];
#pragma unroll
    for (int mt = 0; mt < 4; mt++)
#pragma unroll
        for (int ks = 0; ks < 2; ks++) {
            int row = wm * 64 + mt * 16 + (lid & 7) + ((lid >> 3) & 1) * 8;
            int ch  = ks * 2 + (lid >> 4);
            a_addr[mt][ks] = sbase + row * 64 + 16 * (ch ^ ((row >> 1) & 3));
        }
#pragma unroll
    for (int np = 0; np < 4; np++)
#pragma unroll
        for (int ks = 0; ks < 2; ks++) {
            int row = wn * 64 + np * 16 + (lid & 7) + (lid >> 4) * 8;
            int ch  = ks * 2 + ((lid >> 3) & 1);
            b_addr[np][ks] = sbase + BOFF + row * 64 + 16 * (ch ^ ((row >> 1) & 3));
        }

    uint32_t a_rel[2], b_rel[4];
    const __half* a_base[2];
    const __half* b_base[4];
#pragma unroll
    for (int j = 0; j < 2; j++) {
        int id = tid + j * 256, r = id >> 2, c = id & 3;
        a_rel[j] = sbase + r * 64 + 16 * (c ^ ((r >> 1) & 3));
        a_base[j] = g_nfh + ((size_t)(m0 + r) * NC + i) * CIN + c * 8;
    }
#pragma unroll
    for (int j = 0; j < 4; j++) {
        int id = tid + j * 256, r = id >> 2, c = id & 3;
        b_rel[j] = sbase + BOFF + r * 64 + 16 * (c ^ ((r >> 1) & 3));
        b_base[j] = g_w1g1h + ((size_t)l * HID + r) * 128 + c * 8;
    }

    float acc[4][8][4];
#pragma unroll
    for (int mt = 0; mt < 4; mt++)
#pragma unroll
        for (int nt = 0; nt < 8; nt++)
#pragma unroll
            for (int v = 0; v < 4; v++) acc[mt][nt][v] = 0.0f;

#pragma unroll
    for (int s = 0; s < 3; s++) {
        uint32_t so = s * STAGE;
        if (s < NITERY) {
#pragma unroll
            for (int j = 0; j < 2; j++) cp_async16(a_rel[j] + so, a_base[j] + s * 32);
#pragma unroll
            for (int j = 0; j < 4; j++) cp_async16(b_rel[j] + so, b_base[j] + s * 32);
        }
        asm volatile("cp.async.commit_group;");
    }

#pragma unroll 1
    for (int kc = 0; kc < NITERY; kc++) {
        asm volatile("cp.async.wait_group 2;");
        __syncthreads();
        int pf = kc + 3;
        if (pf < NITERY) {
            uint32_t so = (pf & 3) * STAGE;
#pragma unroll
            for (int j = 0; j < 2; j++) cp_async16(a_rel[j] + so, a_base[j] + pf * 32);
#pragma unroll
            for (int j = 0; j < 4; j++) cp_async16(b_rel[j] + so, b_base[j] + pf * 32);
        }
        asm volatile("cp.async.commit_group;");

        const uint32_t so = (kc & 3) * STAGE;
#pragma unroll
        for (int ks = 0; ks < 2; ks++) {
            uint32_t af[4][4], bf[8][2];
#pragma unroll
            for (int mt = 0; mt < 4; mt++)
                ldsm_x4(af[mt][0], af[mt][1], af[mt][2], af[mt][3],
                        a_addr[mt][ks] + so);
#pragma unroll
            for (int np = 0; np < 4; np++)
                ldsm_x4(bf[2 * np][0], bf[2 * np][1], bf[2 * np + 1][0],
                        bf[2 * np + 1][1], b_addr[np][ks] + so);
#pragma unroll
            for (int mt = 0; mt < 4; mt++)
#pragma unroll
                for (int nt = 0; nt < 8; nt++)
                    mma_f16(acc[mt][nt], af[mt], bf[nt]);
        }
    }

    const int tq = lid >> 2;
    const int tr = lid & 3;
#pragma unroll
    for (int mt = 0; mt < 4; mt++) {
#pragma unroll
        for (int half = 0; half < 2; half++) {
            int node = m0 + wm * 64 + mt * 16 + tq + half * 8;
            __half* row = g_yb + ((size_t)node * 64 + i) * HID;
#pragma unroll
            for (int nt = 0; nt < 8; nt++) {
                int col = wn * 64 + nt * 8 + tr * 2;
                float v0 = acc[mt][nt][half * 2 + 0];
                float v1 = acc[mt][nt][half * 2 + 1];
                if (i == 0) { v0 += g_b1g1[col]; v1 += g_b1g1[col + 1]; }
                *(uint32_t*)&row[col] = pkh2(v0, v1);
            }
        }
    }
}

// -------- grid1 = silu(T @ y[n]) : fp16 MMA, K=64, trans-B, 512 thr ---------
__global__ void __launch_bounds__(512, 1) k_grid1_mma() {
    extern __shared__ __align__(128) char smem[];
    const uint32_t sbase = smem_u32(smem);
    const int tid = threadIdx.x;
    const int wid = tid >> 5;
    const int lid = tid & 31;
    const int wm  = wid & 1;
    const int wn  = wid >> 1;
    const int node = blockIdx.y;
    const int m0 = blockIdx.x * BM;

    const uint32_t STAGE = BM * 64 + BK * 512;   // 24576
    const uint32_t BOFF  = BM * 64;

    uint32_t a_addr[4][2], b_addr[2][2];
#pragma unroll
    for (int mt = 0; mt < 4; mt++)
#pragma unroll
        for (int ks = 0; ks < 2; ks++) {
            int row = wm * 64 + mt * 16 + (lid & 7) + ((lid >> 3) & 1) * 8;
            int ch  = ks * 2 + (lid >> 4);
            a_addr[mt][ks] = sbase + row * 64 + 16 * (ch ^ ((row >> 1) & 3));
        }
#pragma unroll
    for (int np = 0; np < 2; np++)
#pragma unroll
        for (int ks = 0; ks < 2; ks++) {
            int row = ks * 16 + (lid & 7) + 8 * ((lid >> 3) & 1);
            int cn  = wn * 4 + np * 2 + (lid >> 4);
            b_addr[np][ks] = sbase + BOFF + row * 512 + 16 * (cn ^ (row & 7));
        }

    uint32_t a_rel, b_rel[2];
    const __half* a_basep;
    const __half* b_base[2];
    const __half* ybn = g_yb + (size_t)node * (64 * HID);
    {
        int r = tid >> 2, c = tid & 3;
        a_rel = sbase + r * 64 + 16 * (c ^ ((r >> 1) & 3));
        a_basep = g_Tb + (m0 + r) * 64 + c * 8;
    }
#pragma unroll
    for (int j = 0; j < 2; j++) {
        int id = tid + j * 512, r = id >> 5, c = id & 31;
        b_rel[j] = sbase + BOFF + r * 512 + 16 * (c ^ (r & 7));
        b_base[j] = ybn + r * HID + c * 8;
    }

    float acc[4][4][4];
#pragma unroll
    for (int mt = 0; mt < 4; mt++)
#pragma unroll
        for (int nt = 0; nt < 4; nt++)
#pragma unroll
            for (int v = 0; v < 4; v++) acc[mt][nt][v] = 0.0f;

#pragma unroll
    for (int s = 0; s < 2; s++) {
        uint32_t so = s * STAGE;
        cp_async16(a_rel + so, a_basep + s * 32);
#pragma unroll
        for (int j = 0; j < 2; j++) cp_async16(b_rel[j] + so, b_base[j] + s * 32 * HID);
        asm volatile("cp.async.commit_group;");
    }

#pragma unroll 1
    for (int kc = 0; kc < NITER1; kc++) {
        asm volatile("cp.async.wait_group 1;");
        __syncthreads();
        asm volatile("cp.async.commit_group;");

        const uint32_t so = (kc % 3) * STAGE;
#pragma unroll
        for (int ks = 0; ks < 2; ks++) {
            uint32_t af[4][4], bf[4][2];
#pragma unroll
            for (int mt = 0; mt < 4; mt++)
                ldsm_x4(af[mt][0], af[mt][1], af[mt][2], af[mt][3],
                        a_addr[mt][ks] + so);
#pragma unroll
            for (int np = 0; np < 2; np++)
                ldsm_x4_t(bf[2 * np][0], bf[2 * np][1], bf[2 * np + 1][0],
                          bf[2 * np + 1][1], b_addr[np][ks] + so);
#pragma unroll
            for (int mt = 0; mt < 4; mt++)
#pragma unroll
                for (int nt = 0; nt < 4; nt++)
                    mma_f16(acc[mt][nt], af[mt], bf[nt]);
        }
    }

    const int tq = lid >> 2;
    const int tr = lid & 3;
#pragma unroll
    for (int mt = 0; mt < 4; mt++) {
#pragma unroll
        for (int half = 0; half < 2; half++) {
            int p = m0 + wm * 64 + mt * 16 + tq + half * 8;
            if (p >= NP) continue;
            __half* row = g_grid1b + ((size_t)node * NP + p) * HID;
#pragma unroll
            for (int nt = 0; nt < 4; nt++) {
                int col = wn * 32 + nt * 8 + tr * 2;
                *(uint32_t*)&row[col] = pkh2(silu_f(acc[mt][nt][half * 2 + 0]),
                                             silu_f(acc[mt][nt][half * 2 + 1]));
            }
        }
    }
}

// -------- grid2 = silu(grid1 @ g2): fp16 MMA, K=256, 512 thr ----------------
__global__ void __launch_bounds__(512, 1) k_grid2_mma() {
    extern __shared__ __align__(128) char smem[];
    const uint32_t sbase = smem_u32(smem);
    const int tid = threadIdx.x;
    const int wid = tid >> 5;
    const int lid = tid & 31;
    const int wm  = wid & 1;
    const int wn  = wid >> 1;
    const size_t m0 = (size_t)blockIdx.x * BM;

    const uint32_t STAGE = BM * 64 + BN * 64;    // 24576
    const uint32_t BOFF  = BM * 64;

    uint32_t a_addr[4][2], b_addr[2][2];
#pragma unroll
    for (int mt = 0; mt < 4; mt++)
#pragma unroll
        for (int ks = 0; ks < 2; ks++) {
            int row = wm * 64 + mt * 16 + (lid & 7) + ((lid >> 3) & 1) * 8;
            int ch  = ks * 2 + (lid >> 4);
            a_addr[mt][ks] = sbase + row * 64 + 16 * (ch ^ ((row >> 1) & 3));
        }
#pragma unroll
    for (int np = 0; np < 2; np++)
#pragma unroll
        for (int ks = 0; ks < 2; ks++) {
            int row = wn * 32 + np * 16 + (lid & 7) + (lid >> 4) * 8;
            int ch  = ks * 2 + ((lid >> 3) & 1);
            b_addr[np][ks] = sbase + BOFF + row * 64 + 16 * (ch ^ ((row >> 1) & 3));
        }

    uint32_t a_rel, b_rel[2];
    const __half* a_basep;
    const __half* b_base[2];
    {
        int r = tid >> 2, c = tid & 3;
        a_rel = sbase + r * 64 + 16 * (c ^ ((r >> 1) & 3));
        a_basep = g_grid1b + (m0 + r) * (size_t)HID + c * 8;
    }
#pragma unroll
    for (int j = 0; j < 2; j++) {
        int id = tid + j * 512, r = id >> 2, c = id & 3;
        b_rel[j] = sbase + BOFF + r * 64 + 16 * (c ^ ((r >> 1) & 3));
        b_base[j] = g_g2b + r * (size_t)256 + c * 8;
    }

    float acc[4][4][4];
#pragma unroll
    for (int mt = 0; mt < 4; mt++)
#pragma unroll
        for (int nt = 0; nt < 4; nt++)
#pragma unroll
            for (int v = 0; v < 4; v++) acc[mt][nt][v] = 0.0f;

#pragma unroll
    for (int s = 0; s < 3; s++) {
        uint32_t so = s * STAGE;
        cp_async16(a_rel + so, a_basep + s * 32);
#pragma unroll
        for (int j = 0; j < 2; j++) cp_async16(b_rel[j] + so, b_base[j] + s * 32);
        asm volatile("cp.async.commit_group;");
    }

#pragma unroll 1
    for (int kc = 0; kc < NITER2; kc++) {
        asm volatile("cp.async.wait_group 2;");
        __syncthreads();
        int pf = kc + 3;
        if (pf < NITER2) {
            uint32_t so = (pf & 3) * STAGE;
            cp_async16(a_rel + so, a_basep + pf * 32);
#pragma unroll
            for (int j = 0; j < 2; j++) cp_async16(b_rel[j] + so, b_base[j] + pf * 32);
        }
        asm volatile("cp.async.commit_group;");

        const uint32_t so = (kc & 3) * STAGE;
#pragma unroll
        for (int ks = 0; ks < 2; ks++) {
            uint32_t af[4][4], bf[4][2];
#pragma unroll
            for (int mt = 0; mt < 4; mt++)
                ldsm_x4(af[mt][0], af[mt][1], af[mt][2], af[mt][3],
                        a_addr[mt][ks] + so);
#pragma unroll
            for (int np = 0; np < 2; np++)
                ldsm_x4(bf[2 * np][0], bf[2 * np][1], bf[2 * np + 1][0],
                        bf[2 * np + 1][1], b_addr[np][ks] + so);
#pragma unroll
            for (int mt = 0; mt < 4; mt++)
#pragma unroll
                for (int nt = 0; nt < 4; nt++)
                    mma_f16(acc[mt][nt], af[mt], bf[nt]);
        }
    }

    const int tq = lid >> 2;
    const int tr = lid & 3;
#pragma unroll
    for (int mt = 0; mt < 4; mt++) {
#pragma unroll
        for (int half = 0; half < 2; half++) {
            size_t r = m0 + wm * 64 + mt * 16 + tq + half * 8;
            uint32_t n = (uint32_t)(r / NP);
            uint32_t p = (uint32_t)(r - (size_t)n * NP);
            __half* row = g_grid2b + ((size_t)n * PBLK + p) * HID;
#pragma unroll
            for (int nt = 0; nt < 4; nt++) {
                int col = wn * 32 + nt * 8 + tr * 2;
                *(uint32_t*)&row[col] = pkh2(silu_f(acc[mt][nt][half * 2 + 0]),
                                             silu_f(acc[mt][nt][half * 2 + 1]));
            }
        }
    }
}

// -------- z = F^T @ grid2[n] : fp16 MMA, K=352, trans-B, 512 thr ------------
__global__ void __launch_bounds__(512, 1) k_z_mma() {
    extern __shared__ __align__(128) char smem[];
    const uint32_t sbase = smem_u32(smem);
    const int tid = threadIdx.x;
    const int wid = tid >> 5;
    const int lid = tid & 31;
    const int node = blockIdx.x;

    const uint32_t STAGE = 64 * 64 + BK * 512;   // 20480
    const uint32_t BOFF  = 64 * 64;

    uint32_t a_addr[4][2], b_addr[2];
#pragma unroll
    for (int mt = 0; mt < 4; mt++)
#pragma unroll
        for (int ks = 0; ks < 2; ks++) {
            int row = mt * 16 + (lid & 7) + ((lid >> 3) & 1) * 8;
            int ch  = ks * 2 + (lid >> 4);
            a_addr[mt][ks] = sbase + row * 64 + 16 * (ch ^ ((row >> 1) & 3));
        }
#pragma unroll
    for (int ks = 0; ks < 2; ks++) {
        int row = ks * 16 + (lid & 7) + 8 * ((lid >> 3) & 1);
        int cn  = wid * 2 + (lid >> 4);
        b_addr[ks] = sbase + BOFF + row * 512 + 16 * (cn ^ (row & 7));
    }

    uint32_t a_rel = 0, b_rel[2];
    const __half* a_basep = nullptr;
    const __half* b_base[2];
    const __half* g2bn = g_grid2b + (size_t)node * (PBLK * HID);
    if (tid < 256) {
        int r = tid >> 2, c = tid & 3;
        a_rel = sbase + r * 64 + 16 * (c ^ ((r >> 1) & 3));
        a_basep = g_FTb + r * PBLK + c * 8;
    }
#pragma unroll
    for (int j = 0; j < 2; j++) {
        int id = tid + j * 512, r = id >> 5, c = id & 31;
        b_rel[j] = sbase + BOFF + r * 512 + 16 * (c ^ (r & 7));
        b_base[j] = g2bn + r * HID + c * 8;
    }

    float acc[4][2][4];
#pragma unroll
    for (int mt = 0; mt < 4; mt++)
#pragma unroll
        for (int nt = 0; nt < 2; nt++)
#pragma unroll
            for (int v = 0; v < 4; v++) acc[mt][nt][v] = 0.0f;

#pragma unroll
    for (int s = 0; s < 3; s++) {
        uint32_t so = s * STAGE;
        if (tid < 256) cp_async16(a_rel + so, a_basep + s * 32);
#pragma unroll
        for (int j = 0; j < 2; j++) cp_async16(b_rel[j] + so, b_base[j] + s * 32 * HID);
        asm volatile("cp.async.commit_group;");
    }

#pragma unroll 1
    for (int kc = 0; kc < NITERZ; kc++) {
        asm volatile("cp.async.wait_group 2;");
        __syncthreads();
        int pf = kc + 3;
        if (pf < NITERZ) {
            uint32_t so = (pf & 3) * STAGE;
            if (tid < 256) cp_async16(a_rel + so, a_basep + pf * 32);
#pragma unroll
            for (int j = 0; j < 2; j++) cp_async16(b_rel[j] + so, b_base[j] + pf * 32 * HID);
        }
        asm volatile("cp.async.commit_group;");

        const uint32_t so = (kc & 3) * STAGE;
#pragma unroll
        for (int ks = 0; ks < 2; ks++) {
            uint32_t af[4][4], bf[2][2];
#pragma unroll
            for (int mt = 0; mt < 4; mt++)
                ldsm_x4(af[mt][0], af[mt][1], af[mt][2], af[mt][3],
                        a_addr[mt][ks] + so);
            ldsm_x4_t(bf[0][0], bf[0][1], bf[1][0], bf[1][1], b_addr[ks] + so);
#pragma unroll
            for (int mt = 0; mt < 4; mt++)
#pragma unroll
                for (int nt = 0; nt < 2; nt++)
                    mma_f16(acc[mt][nt], af[mt], bf[nt]);
        }
    }

    const int tq = lid >> 2;
    const int tr = lid & 3;
#pragma unroll
    for (int mt = 0; mt < 4; mt++) {
#pragma unroll
        for (int half = 0; half < 2; half++) {
            int i = mt * 16 + tq + half * 8;
            if (i >= NC) continue;
            __half* row = g_zh + ((size_t)node * NC + i) * HID;
#pragma unroll
            for (int nt = 0; nt < 2; nt++) {
                int col = wid * 16 + nt * 8 + tr * 2;
                *(uint32_t*)&row[col] = pkh2(acc[mt][nt][half * 2 + 0],
                                             acc[mt][nt][half * 2 + 1]);
            }
        }
    }
}

// ---------------- out[:,i,:] = z[:,i,:] @ G3W2[l]: fp16 MMA (i>=1) ----------
__global__ void __launch_bounds__(256, 1) k_out_mma(float* __restrict__ out) {
    extern __shared__ __align__(128) char smem[];
    const uint32_t sbase = smem_u32(smem);
    const int tid = threadIdx.x;
    const int wid = tid >> 5;
    const int lid = tid & 31;
    const int wm  = wid & 1;
    const int wn  = wid >> 1;
    const int i   = blockIdx.y + 1;
    const int l   = deg_of(i);
    const int m0  = blockIdx.x * BM;

    const uint32_t STAGE = BM * 64 + CIN * 64;   // 16384
    const uint32_t BOFF  = BM * 64;

    uint32_t a_addr[4][2], b_addr[2][2];
#pragma unroll
    for (int mt = 0; mt < 4; mt++)
#pragma unroll
        for (int ks = 0; ks < 2; ks++) {
            int row = wm * 64 + mt * 16 + (lid & 7) + ((lid >> 3) & 1) * 8;
            int ch  = ks * 2 + (lid >> 4);
            a_addr[mt][ks] = sbase + row * 64 + 16 * (ch ^ ((row >> 1) & 3));
        }
#pragma unroll
    for (int np = 0; np < 2; np++)
#pragma unroll
        for (int ks = 0; ks < 2; ks++) {
            int row = wn * 32 + np * 16 + (lid & 7) + (lid >> 4) * 8;
            int ch  = ks * 2 + ((lid >> 3) & 1);
            b_addr[np][ks] = sbase + BOFF + row * 64 + 16 * (ch ^ ((row >> 1) & 3));
        }

    uint32_t a_rel[2], b_rel[2];
    const __half* a_base[2];
    const __half* b_base[2];
#pragma unroll
    for (int j = 0; j < 2; j++) {
        int id = tid + j * 256, r = id >> 2, c = id & 3;
        a_rel[j] = sbase + r * 64 + 16 * (c ^ ((r >> 1) & 3));
        a_base[j] = g_zh + ((size_t)(m0 + r) * NC + i) * HID + c * 8;
        b_rel[j] = sbase + BOFF + r * 64 + 16 * (c ^ ((r >> 1) & 3));
        b_base[j] = g_g3w2h + ((size_t)l * CIN + r) * 256 + c * 8;
    }

    float acc[4][4][4];
#pragma unroll
    for (int mt = 0; mt < 4; mt++)
#pragma unroll
        for (int nt = 0; nt < 4; nt++)
#pragma unroll
            for (int v = 0; v < 4; v++) acc[mt][nt][v] = 0.0f;

#pragma unroll
    for (int s = 0; s < 3; s++) {
        uint32_t so = s * STAGE;
#pragma unroll
        for (int j = 0; j < 2; j++) {
            cp_async16(a_rel[j] + so, a_base[j] + s * 32);
            cp_async16(b_rel[j] + so, b_base[j] + s * 32);
        }
        asm volatile("cp.async.commit_group;");
    }

#pragma unroll 1
    for (int kc = 0; kc < NITERO; kc++) {
        asm volatile("cp.async.wait_group 2;");
        __syncthreads();
        int pf = kc + 3;
        if (pf < NITERO) {
            uint32_t so = (pf & 3) * STAGE;
#pragma unroll
            for (int j = 0; j < 2; j++) {
                cp_async16(a_rel[j] + so, a_base[j] + pf * 32);
                cp_async16(b_rel[j] + so, b_base[j] + pf * 32);
            }
        }
        asm volatile("cp.async.commit_group;");

        const uint32_t so = (kc & 3) * STAGE;
#pragma unroll
        for (int ks = 0; ks < 2; ks++) {
            uint32_t af[4][4], bf[4][2];
#pragma unroll
            for (int mt = 0; mt < 4; mt++)
                ldsm_x4(af[mt][0], af[mt][1], af[mt][2], af[mt][3],
                        a_addr[mt][ks] + so);
#pragma unroll
            for (int np = 0; np < 2; np++)
                ldsm_x4(bf[2 * np][0], bf[2 * np][1], bf[2 * np + 1][0],
                        bf[2 * np + 1][1], b_addr[np][ks] + so);
#pragma unroll
            for (int mt = 0; mt < 4; mt++)
#pragma unroll
                for (int nt = 0; nt < 4; nt++)
                    mma_f16(acc[mt][nt], af[mt], bf[nt]);
        }
    }

    const int tq = lid >> 2;
    const int tr = lid & 3;
#pragma unroll
    for (int mt = 0; mt < 4; mt++) {
#pragma unroll
        for (int half = 0; half < 2; half++) {
            int node = m0 + wm * 64 + mt * 16 + tq + half * 8;
            float* row = out + ((size_t)node * NC + i) * CIN;
#pragma unroll
            for (int nt = 0; nt < 4; nt++) {
                int col = wn * 32 + nt * 8 + tr * 2;
                float2 v;
                v.x = acc[mt][nt][half * 2 + 0];
                v.y = acc[mt][nt][half * 2 + 1];
                *(float2*)&row[col] = v;
            }
        }
    }
}

// out[:,0,:] = gate @ w2[0] + b2  (SIMT, tiny)
__global__ void __launch_bounds__(256) k_out0(const float* __restrict__ w2,
                                              const float* __restrict__ b2,
                                              float* __restrict__ out) {
    gemm_tile<false, true>(g_gate, HID, w2, CIN, b2,
                           out, NC * CIN, N_NODES, CIN, HID);
}

// ---------------------------------------------------------------------------

extern "C" void kernel_launch(void* const* d_in, const int* in_sizes, int n_in,
                              void* d_out, int out_size) {
    const float* nf = (const float*)d_in[0];
    const float* w1 = (const float*)d_in[1];
    const float* b1 = (const float*)d_in[2];
    const float* w2 = (const float*)d_in[3];
    const float* b2 = (const float*)d_in[4];
    const float* ws = (const float*)d_in[5];
    const float* bs = (const float*)d_in[6];
    const float* g1 = (const float*)d_in[7];
    const float* g2 = (const float*)d_in[8];
    const float* g3 = (const float*)d_in[9];
    const float* Tg = (const float*)d_in[10];
    const float* Fg = (const float*)d_in[11];
    float* out = (float*)d_out;

    const int SMEM1 = 3 * (BM * 64 + BK * 512);   // 73728
    const int SMEM2 = 4 * (BM * 64 + BN * 64);    // 98304
    const int SMEMZ = 4 * (64 * 64 + BK * 512);   // 81920
    const int SMEMY = 4 * (BM * 64 + BN * 64);    // 98304
    const int SMEMO = 4 * (BM * 64 + CIN * 64);   // 65536
    cudaFuncSetAttribute(k_grid1_mma, cudaFuncAttributeMaxDynamicSharedMemorySize, SMEM1);
    cudaFuncSetAttribute(k_grid2_mma, cudaFuncAttributeMaxDynamicSharedMemorySize, SMEM2);
    cudaFuncSetAttribute(k_z_mma,     cudaFuncAttributeMaxDynamicSharedMemorySize, SMEMZ);
    cudaFuncSetAttribute(k_y_mma,     cudaFuncAttributeMaxDynamicSharedMemorySize, SMEMY);
    cudaFuncSetAttribute(k_out_mma,   cudaFuncAttributeMaxDynamicSharedMemorySize, SMEMO);

    const int PS_BLOCKS = PS_TB + PS_FTB + PS_G2B + PS_NFH + PS_PADY + PS_PADG;

    // prologs (3 launches)
    k_w1g1_h<<<dim3(HID / 64, CIN / 64, NL + 1), 256>>>(w1, g1, b1);
    k_g3w2_h<<<dim3(CIN / 64, HID / 64, NL), 256>>>(g3, w2);
    k_prep_static<<<PS_BLOCKS, 256>>>(nf, Tg, Fg, g2);

    // main pipeline (6th launch overall = k_grid2_mma, for ncu -s 5)
    k_y_mma<<<dim3(N_NODES / BM, NC), 256, SMEMY>>>();
    k_grid1_mma<<<dim3(3, N_NODES), 512, SMEM1>>>();
    k_grid2_mma<<<(int)(MROWS / BM), 512, SMEM2>>>();
    k_z_mma<<<N_NODES, 512, SMEMZ>>>();
    k_out_mma<<<dim3(N_NODES / BM, NC - 1), 256, SMEMO>>>(out);

    // scalar gating branch (independent; feeds out0 only)
    k_gate<<<dim3(HID / 64, N_NODES / 64), 256>>>(nf, ws, bs);
    k_out0<<<dim3(CIN / 64, N_NODES / 64), 256>>>(w2, b2, out);
}

// round 12
// speedup vs baseline: 1.2986x; 1.1123x over previous
#include <cuda_runtime.h>
#include <cuda_fp16.h>
#include <cstdint>

// ---------------------------------------------------------------------------
// FeedForwardNetwork (SO(3) equivariant FFN), sm_103a — all-MMA plain-fp16
// Round 12: k_y_mma -> 512 threads; gate branch converted to MMA
// (k_gate_mma + i=0 case merged into k_out_mma). 9 launches.
// ---------------------------------------------------------------------------

#define N_NODES 1024
#define NC      49
#define CIN     128
#define HID     256
#define RES     18
#define NP      (RES*RES)   // 324
#define NL      7
#define MROWS   ((size_t)N_NODES * NP)   // 331776
#define PBLK    352
#define BM      128
#define BN      256
#define BK      32
#define NITER1  2            // grid1 K chunks (64/32)
#define NITER2  8            // grid2 K chunks (256/32)
#define NITERZ  11           // z K chunks (352/32)
#define NITERY  4            // y / gate K chunks (128/32)
#define NITERO  8            // out K chunks (256/32)

// -------- scratch (static device globals; no runtime allocation) -----------
__device__ float g_b1g1[HID];
__device__ __half g_Tb[384 * 64];                    // to_grid hi [384x64]
__device__ __half g_FTb[64 * PBLK];                  // from_grid^T hi [64x352]
__device__ __half g_g2b[HID * 256];                  // g2^T hi [256x256]
__device__ __half g_w1g1h[NL * HID * 128];           // W1G1^T hi rows
__device__ __half g_g3w2h[NL * CIN * 256];           // (g3 w2)^T hi rows
__device__ __half g_wsh[HID * 128];                  // ws^T hi [256x128]
__device__ __half g_w2h0[CIN * 256];                 // w2[0]^T hi [128x256]
__device__ __half g_nfh[(size_t)N_NODES * NC * CIN];       // 12.8 MB
__device__ __half g_yb[(size_t)N_NODES * 64 * HID];        // 34 MB
__device__ __half g_grid1b[MROWS * HID];                   // 170 MB
__device__ __half g_grid2b[(size_t)N_NODES * PBLK * HID];  // 185 MB
__device__ __half g_zh[(size_t)N_NODES * NC * HID];        // 25.7 MB
__device__ __half g_gateh[(size_t)N_NODES * HID];          // fp16 gate

__device__ __forceinline__ float silu_f(float x) {
    return x / (1.0f + __expf(-x));
}
__device__ __forceinline__ int deg_of(int i) {
    int l = 0;
    while ((l + 1) * (l + 1) <= i) ++l;
    return l;
}
__device__ __forceinline__ uint32_t smem_u32(const void* p) {
    uint32_t a;
    asm("{ .reg .u64 t; cvta.to.shared.u64 t, %1; cvt.u32.u64 %0, t; }"
        : "=r"(a) : "l"(p));
    return a;
}
__device__ __forceinline__ void cp_async16(uint32_t dst, const void* src) {
    asm volatile("cp.async.cg.shared.global [%0], [%1], 16;" :: "r"(dst), "l"(src));
}
__device__ __forceinline__ void ldsm_x4(uint32_t& r0, uint32_t& r1,
                                        uint32_t& r2, uint32_t& r3, uint32_t addr) {
    asm volatile("ldmatrix.sync.aligned.m8n8.x4.shared.b16 {%0,%1,%2,%3}, [%4];"
                 : "=r"(r0), "=r"(r1), "=r"(r2), "=r"(r3) : "r"(addr));
}
__device__ __forceinline__ void ldsm_x4_t(uint32_t& r0, uint32_t& r1,
                                          uint32_t& r2, uint32_t& r3, uint32_t addr) {
    asm volatile("ldmatrix.sync.aligned.m8n8.x4.trans.shared.b16 {%0,%1,%2,%3}, [%4];"
                 : "=r"(r0), "=r"(r1), "=r"(r2), "=r"(r3) : "r"(addr));
}
__device__ __forceinline__ void mma_f16(float* d, const uint32_t* a, const uint32_t* b) {
    asm volatile(
        "mma.sync.aligned.m16n8k16.row.col.f32.f16.f16.f32 "
        "{%0,%1,%2,%3}, {%4,%5,%6,%7}, {%8,%9}, {%0,%1,%2,%3};"
        : "+f"(d[0]), "+f"(d[1]), "+f"(d[2]), "+f"(d[3])
        : "r"(a[0]), "r"(a[1]), "r"(a[2]), "r"(a[3]), "r"(b[0]), "r"(b[1]));
}
__device__ __forceinline__ uint32_t pkh2(float x, float y) {
    __half hx = __float2half_rn(x), hy = __float2half_rn(y);
    uint16_t bx = *(uint16_t*)&hx, by = *(uint16_t*)&hy;
    return (uint32_t)bx | ((uint32_t)by << 16);
}

// ---------------------------------------------------------------------------
// SIMT gemm body with fp16-transposed epilogue (weight prep only).
// ---------------------------------------------------------------------------
__device__ __forceinline__ void gemm_tile_w16(
    const float* __restrict__ A, int lda,
    const float* __restrict__ B, int ldb,
    __half* __restrict__ OUT, int out_stride,
    int K)
{
    __shared__ float As[16][64];
    __shared__ float Bs[16][64];

    const int tid = threadIdx.x;
    const int tx  = tid & 15;
    const int ty  = tid >> 4;
    const int m0  = blockIdx.y * 64;
    const int n0  = blockIdx.x * 64;

    float acc[4][4];
#pragma unroll
    for (int i = 0; i < 4; i++)
#pragma unroll
        for (int j = 0; j < 4; j++) acc[i][j] = 0.0f;

    for (int k0 = 0; k0 < K; k0 += 16) {
#pragma unroll
        for (int e = tid; e < 64 * 16; e += 256) {
            int m = e >> 4, k = e & 15;
            As[k][m] = A[(size_t)(m0 + m) * lda + k0 + k];
        }
#pragma unroll
        for (int e = tid; e < 16 * 64; e += 256) {
            int k = e >> 6, n = e & 63;
            Bs[k][n] = B[(size_t)(k0 + k) * ldb + n0 + n];
        }
        __syncthreads();

#pragma unroll
        for (int k = 0; k < 16; k++) {
            float4 av = *(const float4*)&As[k][ty * 4];
            float4 bv = *(const float4*)&Bs[k][tx * 4];
            float a4[4] = {av.x, av.y, av.z, av.w};
            float b4[4] = {bv.x, bv.y, bv.z, bv.w};
#pragma unroll
            for (int i = 0; i < 4; i++)
#pragma unroll
                for (int j = 0; j < 4; j++)
                    acc[i][j] += a4[i] * b4[j];
        }
        __syncthreads();
    }

#pragma unroll
    for (int i = 0; i < 4; i++) {
        int gm = m0 + ty * 4 + i;
#pragma unroll
        for (int j = 0; j < 4; j++) {
            int gn = n0 + tx * 4 + j;
            OUT[(size_t)gn * out_stride + gm] = __float2half_rn(acc[i][j]);
        }
    }
}

// ---------------------------- prolog kernels --------------------------------

// z < NL: g_w1g1h[l][n][m] = fp16((w1[l] @ g1)[m][n]);  z == NL: b1g1.
__global__ void __launch_bounds__(256) k_w1g1_h(const float* __restrict__ w1,
                                                const float* __restrict__ g1,
                                                const float* __restrict__ b1) {
    if (blockIdx.z == NL) {
        if (blockIdx.x != 0 || blockIdx.y != 0) return;
        int k = threadIdx.x;
        float s = 0.0f;
        for (int h = 0; h < HID; h++) s += b1[h] * g1[(size_t)h * HID + k];
        g_b1g1[k] = s;
        return;
    }
    int l = blockIdx.z;
    gemm_tile_w16(w1 + (size_t)l * CIN * HID, HID, g1, HID,
                  g_w1g1h + (size_t)l * HID * 128, 128, HID);
}

// g_g3w2h[l][n][m] = fp16((g3 @ w2[l])[m][n])
__global__ void __launch_bounds__(256) k_g3w2_h(const float* __restrict__ g3,
                                                const float* __restrict__ w2) {
    int l = blockIdx.z;
    gemm_tile_w16(g3, HID, w2 + (size_t)l * HID * CIN, CIN,
                  g_g3w2h + (size_t)l * CIN * 256, 256, HID);
}

// Mega-prep: Tb | FTb | g2b | nfh | pad_yb | pad_g2b | wsh | w2h0.
#define PS_TB    96
#define PS_FTB   88
#define PS_G2B   256
#define PS_NFH   12544
#define PS_PADY  7680
#define PS_PADG  14336
#define PS_WSH   128
#define PS_W2H   128
__global__ void __launch_bounds__(256) k_prep_static(
    const float* __restrict__ nf, const float* __restrict__ T,
    const float* __restrict__ F,  const float* __restrict__ g2,
    const float* __restrict__ ws, const float* __restrict__ w2) {
    int b = blockIdx.x;
    int t = threadIdx.x;
    if (b < PS_TB) {                       // Tb [384 x 64]
        int idx = b * 256 + t;
        int p = idx >> 6, i = idx & 63;
        float v = (p < NP && i < NC) ? T[p * NC + i] : 0.0f;
        g_Tb[idx] = __float2half_rn(v);
        return;
    }
    b -= PS_TB;
    if (b < PS_FTB) {                      // FTb [64 x 352]
        int idx = b * 256 + t;
        int i = idx / PBLK, p = idx % PBLK;
        float v = (i < NC && p < NP) ? F[p * NC + i] : 0.0f;
        g_FTb[idx] = __float2half_rn(v);
        return;
    }
    b -= PS_FTB;
    if (b < PS_G2B) {                      // g2b [256 x 256] (transposed)
        int idx = b * 256 + t;
        int n = idx >> 8, k = idx & 255;
        g_g2b[idx] = __float2half_rn(g2[(size_t)k * HID + n]);
        return;
    }
    b -= PS_G2B;
    if (b < PS_NFH) {                      // nfh (2 floats / thread)
        size_t gi = ((size_t)b * 256 + t) * 2;
        float2 v = *(const float2*)(nf + gi);
        *(uint32_t*)&g_nfh[gi] = pkh2(v.x, v.y);
        return;
    }
    b -= PS_NFH;
    if (b < PS_PADY) {                     // zero yb rows [49,64)
        size_t w = (size_t)b * 256 + t;
        int node = (int)(w / 1920);
        int rem  = (int)(w % 1920);
        int row  = NC + rem / 128;
        int c2   = rem & 127;
        *(uint32_t*)&g_yb[((size_t)node * 64 + row) * HID + c2 * 2] = 0;
        return;
    }
    b -= PS_PADY;
    if (b < PS_PADG) {                     // zero grid2b rows [324,352)
        size_t w = (size_t)b * 256 + t;
        int node = (int)(w / 3584);
        int rem  = (int)(w % 3584);
        int row  = NP + rem / 128;
        int c2   = rem & 127;
        *(uint32_t*)&g_grid2b[((size_t)node * PBLK + row) * HID + c2 * 2] = 0;
        return;
    }
    b -= PS_PADG;
    if (b < PS_WSH) {                      // wsh[n][k] = fp16(ws[k][n]), [256x128]
        int idx = b * 256 + t;
        int n = idx >> 7, k = idx & 127;
        g_wsh[idx] = __float2half_rn(ws[(size_t)k * HID + n]);
        return;
    }
    b -= PS_WSH;
    {                                      // w2h0[n][k] = fp16(w2[0][k][n]), [128x256]
        int idx = b * 256 + t;
        int n = idx >> 8, k = idx & 255;
        g_w2h0[idx] = __float2half_rn(w2[(size_t)k * CIN + n]);
    }
}

// ---------------------------- main stage kernels ----------------------------

// ---- y = nfh @ W1G1[l] : fp16 MMA, K=128, 512 thr --------------------------
__global__ void __launch_bounds__(512, 1) k_y_mma() {
    extern __shared__ __align__(128) char smem[];
    const uint32_t sbase = smem_u32(smem);
    const int tid = threadIdx.x;
    const int wid = tid >> 5;
    const int lid = tid & 31;
    const int wm  = wid & 1;
    const int wn  = wid >> 1;          // 0..7, 32 cols each
    const int i   = blockIdx.y;
    const int l   = deg_of(i);
    const int m0  = blockIdx.x * BM;

    const uint32_t STAGE = BM * 64 + BN * 64;    // 24576
    const uint32_t BOFF  = BM * 64;

    uint32_t a_addr[4][2], b_addr[2][2];
#pragma unroll
    for (int mt = 0; mt < 4; mt++)
#pragma unroll
        for (int ks = 0; ks < 2; ks++) {
            int row = wm * 64 + mt * 16 + (lid & 7) + ((lid >> 3) & 1) * 8;
            int ch  = ks * 2 + (lid >> 4);
            a_addr[mt][ks] = sbase + row * 64 + 16 * (ch ^ ((row >> 1) & 3));
        }
#pragma unroll
    for (int np = 0; np < 2; np++)
#pragma unroll
        for (int ks = 0; ks < 2; ks++) {
            int row = wn * 32 + np * 16 + (lid & 7) + (lid >> 4) * 8;
            int ch  = ks * 2 + ((lid >> 3) & 1);
            b_addr[np][ks] = sbase + BOFF + row * 64 + 16 * (ch ^ ((row >> 1) & 3));
        }

    uint32_t a_rel, b_rel[2];
    const __half* a_basep;
    const __half* b_base[2];
    {
        int r = tid >> 2, c = tid & 3;
        a_rel = sbase + r * 64 + 16 * (c ^ ((r >> 1) & 3));
        a_basep = g_nfh + ((size_t)(m0 + r) * NC + i) * CIN + c * 8;
    }
#pragma unroll
    for (int j = 0; j < 2; j++) {
        int id = tid + j * 512, r = id >> 2, c = id & 3;
        b_rel[j] = sbase + BOFF + r * 64 + 16 * (c ^ ((r >> 1) & 3));
        b_base[j] = g_w1g1h + ((size_t)l * HID + r) * 128 + c * 8;
    }

    float acc[4][4][4];
#pragma unroll
    for (int mt = 0; mt < 4; mt++)
#pragma unroll
        for (int nt = 0; nt < 4; nt++)
#pragma unroll
            for (int v = 0; v < 4; v++) acc[mt][nt][v] = 0.0f;

#pragma unroll
    for (int s = 0; s < 3; s++) {
        uint32_t so = s * STAGE;
        cp_async16(a_rel + so, a_basep + s * 32);
#pragma unroll
        for (int j = 0; j < 2; j++) cp_async16(b_rel[j] + so, b_base[j] + s * 32);
        asm volatile("cp.async.commit_group;");
    }

#pragma unroll 1
    for (int kc = 0; kc < NITERY; kc++) {
        asm volatile("cp.async.wait_group 2;");
        __syncthreads();
        int pf = kc + 3;
        if (pf < NITERY) {
            uint32_t so = (pf & 3) * STAGE;
            cp_async16(a_rel + so, a_basep + pf * 32);
#pragma unroll
            for (int j = 0; j < 2; j++) cp_async16(b_rel[j] + so, b_base[j] + pf * 32);
        }
        asm volatile("cp.async.commit_group;");

        const uint32_t so = (kc & 3) * STAGE;
#pragma unroll
        for (int ks = 0; ks < 2; ks++) {
            uint32_t af[4][4], bf[4][2];
#pragma unroll
            for (int mt = 0; mt < 4; mt++)
                ldsm_x4(af[mt][0], af[mt][1], af[mt][2], af[mt][3],
                        a_addr[mt][ks] + so);
#pragma unroll
            for (int np = 0; np < 2; np++)
                ldsm_x4(bf[2 * np][0], bf[2 * np][1], bf[2 * np + 1][0],
                        bf[2 * np + 1][1], b_addr[np][ks] + so);
#pragma unroll
            for (int mt = 0; mt < 4; mt++)
#pragma unroll
                for (int nt = 0; nt < 4; nt++)
                    mma_f16(acc[mt][nt], af[mt], bf[nt]);
        }
    }

    const int tq = lid >> 2;
    const int tr = lid & 3;
#pragma unroll
    for (int mt = 0; mt < 4; mt++) {
#pragma unroll
        for (int half = 0; half < 2; half++) {
            int node = m0 + wm * 64 + mt * 16 + tq + half * 8;
            __half* row = g_yb + ((size_t)node * 64 + i) * HID;
#pragma unroll
            for (int nt = 0; nt < 4; nt++) {
                int col = wn * 32 + nt * 8 + tr * 2;
                float v0 = acc[mt][nt][half * 2 + 0];
                float v1 = acc[mt][nt][half * 2 + 1];
                if (i == 0) { v0 += g_b1g1[col]; v1 += g_b1g1[col + 1]; }
                *(uint32_t*)&row[col] = pkh2(v0, v1);
            }
        }
    }
}

// ---- gate = silu(nfh[:,0,:] @ wsh + bs) : fp16 MMA, K=128, 512 thr ---------
__global__ void __launch_bounds__(512, 1) k_gate_mma(const float* __restrict__ bs) {
    extern __shared__ __align__(128) char smem[];
    const uint32_t sbase = smem_u32(smem);
    const int tid = threadIdx.x;
    const int wid = tid >> 5;
    const int lid = tid & 31;
    const int wm  = wid & 1;
    const int wn  = wid >> 1;
    const int m0  = blockIdx.x * BM;

    const uint32_t STAGE = BM * 64 + BN * 64;    // 24576
    const uint32_t BOFF  = BM * 64;

    uint32_t a_addr[4][2], b_addr[2][2];
#pragma unroll
    for (int mt = 0; mt < 4; mt++)
#pragma unroll
        for (int ks = 0; ks < 2; ks++) {
            int row = wm * 64 + mt * 16 + (lid & 7) + ((lid >> 3) & 1) * 8;
            int ch  = ks * 2 + (lid >> 4);
            a_addr[mt][ks] = sbase + row * 64 + 16 * (ch ^ ((row >> 1) & 3));
        }
#pragma unroll
    for (int np = 0; np < 2; np++)
#pragma unroll
        for (int ks = 0; ks < 2; ks++) {
            int row = wn * 32 + np * 16 + (lid & 7) + (lid >> 4) * 8;
            int ch  = ks * 2 + ((lid >> 3) & 1);
            b_addr[np][ks] = sbase + BOFF + row * 64 + 16 * (ch ^ ((row >> 1) & 3));
        }

    uint32_t a_rel, b_rel[2];
    const __half* a_basep;
    const __half* b_base[2];
    {
        int r = tid >> 2, c = tid & 3;
        a_rel = sbase + r * 64 + 16 * (c ^ ((r >> 1) & 3));
        a_basep = g_nfh + ((size_t)(m0 + r) * NC) * CIN + c * 8;   // i = 0
    }
#pragma unroll
    for (int j = 0; j < 2; j++) {
        int id = tid + j * 512, r = id >> 2, c = id & 3;
        b_rel[j] = sbase + BOFF + r * 64 + 16 * (c ^ ((r >> 1) & 3));
        b_base[j] = g_wsh + (size_t)r * 128 + c * 8;
    }

    float acc[4][4][4];
#pragma unroll
    for (int mt = 0; mt < 4; mt++)
#pragma unroll
        for (int nt = 0; nt < 4; nt++)
#pragma unroll
            for (int v = 0; v < 4; v++) acc[mt][nt][v] = 0.0f;

#pragma unroll
    for (int s = 0; s < 3; s++) {
        uint32_t so = s * STAGE;
        cp_async16(a_rel + so, a_basep + s * 32);
#pragma unroll
        for (int j = 0; j < 2; j++) cp_async16(b_rel[j] + so, b_base[j] + s * 32);
        asm volatile("cp.async.commit_group;");
    }

#pragma unroll 1
    for (int kc = 0; kc < NITERY; kc++) {
        asm volatile("cp.async.wait_group 2;");
        __syncthreads();
        int pf = kc + 3;
        if (pf < NITERY) {
            uint32_t so = (pf & 3) * STAGE;
            cp_async16(a_rel + so, a_basep + pf * 32);
#pragma unroll
            for (int j = 0; j < 2; j++) cp_async16(b_rel[j] + so, b_base[j] + pf * 32);
        }
        asm volatile("cp.async.commit_group;");

        const uint32_t so = (kc & 3) * STAGE;
#pragma unroll
        for (int ks = 0; ks < 2; ks++) {
            uint32_t af[4][4], bf[4][2];
#pragma unroll
            for (int mt = 0; mt < 4; mt++)
                ldsm_x4(af[mt][0], af[mt][1], af[mt][2], af[mt][3],
                        a_addr[mt][ks] + so);
#pragma unroll
            for (int np = 0; np < 2; np++)
                ldsm_x4(bf[2 * np][0], bf[2 * np][1], bf[2 * np + 1][0],
                        bf[2 * np + 1][1], b_addr[np][ks] + so);
#pragma unroll
            for (int mt = 0; mt < 4; mt++)
#pragma unroll
                for (int nt = 0; nt < 4; nt++)
                    mma_f16(acc[mt][nt], af[mt], bf[nt]);
        }
    }

    const int tq = lid >> 2;
    const int tr = lid & 3;
#pragma unroll
    for (int mt = 0; mt < 4; mt++) {
#pragma unroll
        for (int half = 0; half < 2; half++) {
            int node = m0 + wm * 64 + mt * 16 + tq + half * 8;
            __half* row = g_gateh + (size_t)node * HID;
#pragma unroll
            for (int nt = 0; nt < 4; nt++) {
                int col = wn * 32 + nt * 8 + tr * 2;
                float v0 = silu_f(acc[mt][nt][half * 2 + 0] + bs[col]);
                float v1 = silu_f(acc[mt][nt][half * 2 + 1] + bs[col + 1]);
                *(uint32_t*)&row[col] = pkh2(v0, v1);
            }
        }
    }
}

// -------- grid1 = silu(T @ y[n]) : fp16 MMA, K=64, trans-B, 512 thr ---------
__global__ void __launch_bounds__(512, 1) k_grid1_mma() {
    extern __shared__ __align__(128) char smem[];
    const uint32_t sbase = smem_u32(smem);
    const int tid = threadIdx.x;
    const int wid = tid >> 5;
    const int lid = tid & 31;
    const int wm  = wid & 1;
    const int wn  = wid >> 1;
    const int node = blockIdx.y;
    const int m0 = blockIdx.x * BM;

    const uint32_t STAGE = BM * 64 + BK * 512;   // 24576
    const uint32_t BOFF  = BM * 64;

    uint32_t a_addr[4][2], b_addr[2][2];
#pragma unroll
    for (int mt = 0; mt < 4; mt++)
#pragma unroll
        for (int ks = 0; ks < 2; ks++) {
            int row = wm * 64 + mt * 16 + (lid & 7) + ((lid >> 3) & 1) * 8;
            int ch  = ks * 2 + (lid >> 4);
            a_addr[mt][ks] = sbase + row * 64 + 16 * (ch ^ ((row >> 1) & 3));
        }
#pragma unroll
    for (int np = 0; np < 2; np++)
#pragma unroll
        for (int ks = 0; ks < 2; ks++) {
            int row = ks * 16 + (lid & 7) + 8 * ((lid >> 3) & 1);
            int cn  = wn * 4 + np * 2 + (lid >> 4);
            b_addr[np][ks] = sbase + BOFF + row * 512 + 16 * (cn ^ (row & 7));
        }

    uint32_t a_rel, b_rel[2];
    const __half* a_basep;
    const __half* b_base[2];
    const __half* ybn = g_yb + (size_t)node * (64 * HID);
    {
        int r = tid >> 2, c = tid & 3;
        a_rel = sbase + r * 64 + 16 * (c ^ ((r >> 1) & 3));
        a_basep = g_Tb + (m0 + r) * 64 + c * 8;
    }
#pragma unroll
    for (int j = 0; j < 2; j++) {
        int id = tid + j * 512, r = id >> 5, c = id & 31;
        b_rel[j] = sbase + BOFF + r * 512 + 16 * (c ^ (r & 7));
        b_base[j] = ybn + r * HID + c * 8;
    }

    float acc[4][4][4];
#pragma unroll
    for (int mt = 0; mt < 4; mt++)
#pragma unroll
        for (int nt = 0; nt < 4; nt++)
#pragma unroll
            for (int v = 0; v < 4; v++) acc[mt][nt][v] = 0.0f;

#pragma unroll
    for (int s = 0; s < 2; s++) {
        uint32_t so = s * STAGE;
        cp_async16(a_rel + so, a_basep + s * 32);
#pragma unroll
        for (int j = 0; j < 2; j++) cp_async16(b_rel[j] + so, b_base[j] + s * 32 * HID);
        asm volatile("cp.async.commit_group;");
    }

#pragma unroll 1
    for (int kc = 0; kc < NITER1; kc++) {
        asm volatile("cp.async.wait_group 1;");
        __syncthreads();
        asm volatile("cp.async.commit_group;");

        const uint32_t so = (kc % 3) * STAGE;
#pragma unroll
        for (int ks = 0; ks < 2; ks++) {
            uint32_t af[4][4], bf[4][2];
#pragma unroll
            for (int mt = 0; mt < 4; mt++)
                ldsm_x4(af[mt][0], af[mt][1], af[mt][2], af[mt][3],
                        a_addr[mt][ks] + so);
#pragma unroll
            for (int np = 0; np < 2; np++)
                ldsm_x4_t(bf[2 * np][0], bf[2 * np][1], bf[2 * np + 1][0],
                          bf[2 * np + 1][1], b_addr[np][ks] + so);
#pragma unroll
            for (int mt = 0; mt < 4; mt++)
#pragma unroll
                for (int nt = 0; nt < 4; nt++)
                    mma_f16(acc[mt][nt], af[mt], bf[nt]);
        }
    }

    const int tq = lid >> 2;
    const int tr = lid & 3;
#pragma unroll
    for (int mt = 0; mt < 4; mt++) {
#pragma unroll
        for (int half = 0; half < 2; half++) {
            int p = m0 + wm * 64 + mt * 16 + tq + half * 8;
            if (p >= NP) continue;
            __half* row = g_grid1b + ((size_t)node * NP + p) * HID;
#pragma unroll
            for (int nt = 0; nt < 4; nt++) {
                int col = wn * 32 + nt * 8 + tr * 2;
                *(uint32_t*)&row[col] = pkh2(silu_f(acc[mt][nt][half * 2 + 0]),
                                             silu_f(acc[mt][nt][half * 2 + 1]));
            }
        }
    }
}

// -------- grid2 = silu(grid1 @ g2): fp16 MMA, K=256, 512 thr ----------------
__global__ void __launch_bounds__(512, 1) k_grid2_mma() {
    extern __shared__ __align__(128) char smem[];
    const uint32_t sbase = smem_u32(smem);
    const int tid = threadIdx.x;
    const int wid = tid >> 5;
    const int lid = tid & 31;
    const int wm  = wid & 1;
    const int wn  = wid >> 1;
    const size_t m0 = (size_t)blockIdx.x * BM;

    const uint32_t STAGE = BM * 64 + BN * 64;    // 24576
    const uint32_t BOFF  = BM * 64;

    uint32_t a_addr[4][2], b_addr[2][2];
#pragma unroll
    for (int mt = 0; mt < 4; mt++)
#pragma unroll
        for (int ks = 0; ks < 2; ks++) {
            int row = wm * 64 + mt * 16 + (lid & 7) + ((lid >> 3) & 1) * 8;
            int ch  = ks * 2 + (lid >> 4);
            a_addr[mt][ks] = sbase + row * 64 + 16 * (ch ^ ((row >> 1) & 3));
        }
#pragma unroll
    for (int np = 0; np < 2; np++)
#pragma unroll
        for (int ks = 0; ks < 2; ks++) {
            int row = wn * 32 + np * 16 + (lid & 7) + (lid >> 4) * 8;
            int ch  = ks * 2 + ((lid >> 3) & 1);
            b_addr[np][ks] = sbase + BOFF + row * 64 + 16 * (ch ^ ((row >> 1) & 3));
        }

    uint32_t a_rel, b_rel[2];
    const __half* a_basep;
    const __half* b_base[2];
    {
        int r = tid >> 2, c = tid & 3;
        a_rel = sbase + r * 64 + 16 * (c ^ ((r >> 1) & 3));
        a_basep = g_grid1b + (m0 + r) * (size_t)HID + c * 8;
    }
#pragma unroll
    for (int j = 0; j < 2; j++) {
        int id = tid + j * 512, r = id >> 2, c = id & 3;
        b_rel[j] = sbase + BOFF + r * 64 + 16 * (c ^ ((r >> 1) & 3));
        b_base[j] = g_g2b + r * (size_t)256 + c * 8;
    }

    float acc[4][4][4];
#pragma unroll
    for (int mt = 0; mt < 4; mt++)
#pragma unroll
        for (int nt = 0; nt < 4; nt++)
#pragma unroll
            for (int v = 0; v < 4; v++) acc[mt][nt][v] = 0.0f;

#pragma unroll
    for (int s = 0; s < 3; s++) {
        uint32_t so = s * STAGE;
        cp_async16(a_rel + so, a_basep + s * 32);
#pragma unroll
        for (int j = 0; j < 2; j++) cp_async16(b_rel[j] + so, b_base[j] + s * 32);
        asm volatile("cp.async.commit_group;");
    }

#pragma unroll 1
    for (int kc = 0; kc < NITER2; kc++) {
        asm volatile("cp.async.wait_group 2;");
        __syncthreads();
        int pf = kc + 3;
        if (pf < NITER2) {
            uint32_t so = (pf & 3) * STAGE;
            cp_async16(a_rel + so, a_basep + pf * 32);
#pragma unroll
            for (int j = 0; j < 2; j++) cp_async16(b_rel[j] + so, b_base[j] + pf * 32);
        }
        asm volatile("cp.async.commit_group;");

        const uint32_t so = (kc & 3) * STAGE;
#pragma unroll
        for (int ks = 0; ks < 2; ks++) {
            uint32_t af[4][4], bf[4][2];
#pragma unroll
            for (int mt = 0; mt < 4; mt++)
                ldsm_x4(af[mt][0], af[mt][1], af[mt][2], af[mt][3],
                        a_addr[mt][ks] + so);
#pragma unroll
            for (int np = 0; np < 2; np++)
                ldsm_x4(bf[2 * np][0], bf[2 * np][1], bf[2 * np + 1][0],
                        bf[2 * np + 1][1], b_addr[np][ks] + so);
#pragma unroll
            for (int mt = 0; mt < 4; mt++)
#pragma unroll
                for (int nt = 0; nt < 4; nt++)
                    mma_f16(acc[mt][nt], af[mt], bf[nt]);
        }
    }

    const int tq = lid >> 2;
    const int tr = lid & 3;
#pragma unroll
    for (int mt = 0; mt < 4; mt++) {
#pragma unroll
        for (int half = 0; half < 2; half++) {
            size_t r = m0 + wm * 64 + mt * 16 + tq + half * 8;
            uint32_t n = (uint32_t)(r / NP);
            uint32_t p = (uint32_t)(r - (size_t)n * NP);
            __half* row = g_grid2b + ((size_t)n * PBLK + p) * HID;
#pragma unroll
            for (int nt = 0; nt < 4; nt++) {
                int col = wn * 32 + nt * 8 + tr * 2;
                *(uint32_t*)&row[col] = pkh2(silu_f(acc[mt][nt][half * 2 + 0]),
                                             silu_f(acc[mt][nt][half * 2 + 1]));
            }
        }
    }
}

// -------- z = F^T @ grid2[n] : fp16 MMA, K=352, trans-B, 512 thr ------------
__global__ void __launch_bounds__(512, 1) k_z_mma() {
    extern __shared__ __align__(128) char smem[];
    const uint32_t sbase = smem_u32(smem);
    const int tid = threadIdx.x;
    const int wid = tid >> 5;
    const int lid = tid & 31;
    const int node = blockIdx.x;

    const uint32_t STAGE = 64 * 64 + BK * 512;   // 20480
    const uint32_t BOFF  = 64 * 64;

    uint32_t a_addr[4][2], b_addr[2];
#pragma unroll
    for (int mt = 0; mt < 4; mt++)
#pragma unroll
        for (int ks = 0; ks < 2; ks++) {
            int row = mt * 16 + (lid & 7) + ((lid >> 3) & 1) * 8;
            int ch  = ks * 2 + (lid >> 4);
            a_addr[mt][ks] = sbase + row * 64 + 16 * (ch ^ ((row >> 1) & 3));
        }
#pragma unroll
    for (int ks = 0; ks < 2; ks++) {
        int row = ks * 16 + (lid & 7) + 8 * ((lid >> 3) & 1);
        int cn  = wid * 2 + (lid >> 4);
        b_addr[ks] = sbase + BOFF + row * 512 + 16 * (cn ^ (row & 7));
    }

    uint32_t a_rel = 0, b_rel[2];
    const __half* a_basep = nullptr;
    const __half* b_base[2];
    const __half* g2bn = g_grid2b + (size_t)node * (PBLK * HID);
    if (tid < 256) {
        int r = tid >> 2, c = tid & 3;
        a_rel = sbase + r * 64 + 16 * (c ^ ((r >> 1) & 3));
        a_basep = g_FTb + r * PBLK + c * 8;
    }
#pragma unroll
    for (int j = 0; j < 2; j++) {
        int id = tid + j * 512, r = id >> 5, c = id & 31;
        b_rel[j] = sbase + BOFF + r * 512 + 16 * (c ^ (r & 7));
        b_base[j] = g2bn + r * HID + c * 8;
    }

    float acc[4][2][4];
#pragma unroll
    for (int mt = 0; mt < 4; mt++)
#pragma unroll
        for (int nt = 0; nt < 2; nt++)
#pragma unroll
            for (int v = 0; v < 4; v++) acc[mt][nt][v] = 0.0f;

#pragma unroll
    for (int s = 0; s < 3; s++) {
        uint32_t so = s * STAGE;
        if (tid < 256) cp_async16(a_rel + so, a_basep + s * 32);
#pragma unroll
        for (int j = 0; j < 2; j++) cp_async16(b_rel[j] + so, b_base[j] + s * 32 * HID);
        asm volatile("cp.async.commit_group;");
    }

#pragma unroll 1
    for (int kc = 0; kc < NITERZ; kc++) {
        asm volatile("cp.async.wait_group 2;");
        __syncthreads();
        int pf = kc + 3;
        if (pf < NITERZ) {
            uint32_t so = (pf & 3) * STAGE;
            if (tid < 256) cp_async16(a_rel + so, a_basep + pf * 32);
#pragma unroll
            for (int j = 0; j < 2; j++) cp_async16(b_rel[j] + so, b_base[j] + pf * 32 * HID);
        }
        asm volatile("cp.async.commit_group;");

        const uint32_t so = (kc & 3) * STAGE;
#pragma unroll
        for (int ks = 0; ks < 2; ks++) {
            uint32_t af[4][4], bf[2][2];
#pragma unroll
            for (int mt = 0; mt < 4; mt++)
                ldsm_x4(af[mt][0], af[mt][1], af[mt][2], af[mt][3],
                        a_addr[mt][ks] + so);
            ldsm_x4_t(bf[0][0], bf[0][1], bf[1][0], bf[1][1], b_addr[ks] + so);
#pragma unroll
            for (int mt = 0; mt < 4; mt++)
#pragma unroll
                for (int nt = 0; nt < 2; nt++)
                    mma_f16(acc[mt][nt], af[mt], bf[nt]);
        }
    }

    const int tq = lid >> 2;
    const int tr = lid & 3;
#pragma unroll
    for (int mt = 0; mt < 4; mt++) {
#pragma unroll
        for (int half = 0; half < 2; half++) {
            int i = mt * 16 + tq + half * 8;
            if (i >= NC) continue;
            __half* row = g_zh + ((size_t)node * NC + i) * HID;
#pragma unroll
            for (int nt = 0; nt < 2; nt++) {
                int col = wid * 16 + nt * 8 + tr * 2;
                *(uint32_t*)&row[col] = pkh2(acc[mt][nt][half * 2 + 0],
                                             acc[mt][nt][half * 2 + 1]);
            }
        }
    }
}

// ---- out[:,i,:] : fp16 MMA. i==0: gateh @ w2h0 + b2; i>=1: zh @ g3w2h[l] ---
__global__ void __launch_bounds__(256, 1) k_out_mma(const float* __restrict__ b2,
                                                    float* __restrict__ out) {
    extern __shared__ __align__(128) char smem[];
    const uint32_t sbase = smem_u32(smem);
    const int tid = threadIdx.x;
    const int wid = tid >> 5;
    const int lid = tid & 31;
    const int wm  = wid & 1;
    const int wn  = wid >> 1;
    const int i   = blockIdx.y;
    const int m0  = blockIdx.x * BM;

    const uint32_t STAGE = BM * 64 + CIN * 64;   // 16384
    const uint32_t BOFF  = BM * 64;

    uint32_t a_addr[4][2], b_addr[2][2];
#pragma unroll
    for (int mt = 0; mt < 4; mt++)
#pragma unroll
        for (int ks = 0; ks < 2; ks++) {
            int row = wm * 64 + mt * 16 + (lid & 7) + ((lid >> 3) & 1) * 8;
            int ch  = ks * 2 + (lid >> 4);
            a_addr[mt][ks] = sbase + row * 64 + 16 * (ch ^ ((row >> 1) & 3));
        }
#pragma unroll
    for (int np = 0; np < 2; np++)
#pragma unroll
        for (int ks = 0; ks < 2; ks++) {
            int row = wn * 32 + np * 16 + (lid & 7) + (lid >> 4) * 8;
            int ch  = ks * 2 + ((lid >> 3) & 1);
            b_addr[np][ks] = sbase + BOFF + row * 64 + 16 * (ch ^ ((row >> 1) & 3));
        }

    uint32_t a_rel[2], b_rel[2];
    const __half* a_base[2];
    const __half* b_base[2];
#pragma unroll
    for (int j = 0; j < 2; j++) {
        int id = tid + j * 256, r = id >> 2, c = id & 3;
        a_rel[j] = sbase + r * 64 + 16 * (c ^ ((r >> 1) & 3));
        b_rel[j] = sbase + BOFF + r * 64 + 16 * (c ^ ((r >> 1) & 3));
        if (i == 0) {
            a_base[j] = g_gateh + (size_t)(m0 + r) * HID + c * 8;
            b_base[j] = g_w2h0 + (size_t)r * 256 + c * 8;
        } else {
            int l = deg_of(i);
            a_base[j] = g_zh + ((size_t)(m0 + r) * NC + i) * HID + c * 8;
            b_base[j] = g_g3w2h + ((size_t)l * CIN + r) * 256 + c * 8;
        }
    }

    float acc[4][4][4];
#pragma unroll
    for (int mt = 0; mt < 4; mt++)
#pragma unroll
        for (int nt = 0; nt < 4; nt++)
#pragma unroll
            for (int v = 0; v < 4; v++) acc[mt][nt][v] = 0.0f;

#pragma unroll
    for (int s = 0; s < 3; s++) {
        uint32_t so = s * STAGE;
#pragma unroll
        for (int j = 0; j < 2; j++) {
            cp_async16(a_rel[j] + so, a_base[j] + s * 32);
            cp_async16(b_rel[j] + so, b_base[j] + s * 32);
        }
        asm volatile("cp.async.commit_group;");
    }

#pragma unroll 1
    for (int kc = 0; kc < NITERO; kc++) {
        asm volatile("cp.async.wait_group 2;");
        __syncthreads();
        int pf = kc + 3;
        if (pf < NITERO) {
            uint32_t so = (pf & 3) * STAGE;
#pragma unroll
            for (int j = 0; j < 2; j++) {
                cp_async16(a_rel[j] + so, a_base[j] + pf * 32);
                cp_async16(b_rel[j] + so, b_base[j] + pf * 32);
            }
        }
        asm volatile("cp.async.commit_group;");

        const uint32_t so = (kc & 3) * STAGE;
#pragma unroll
        for (int ks = 0; ks < 2; ks++) {
            uint32_t af[4][4], bf[4][2];
#pragma unroll
            for (int mt = 0; mt < 4; mt++)
                ldsm_x4(af[mt][0], af[mt][1], af[mt][2], af[mt][3],
                        a_addr[mt][ks] + so);
#pragma unroll
            for (int np = 0; np < 2; np++)
                ldsm_x4(bf[2 * np][0], bf[2 * np][1], bf[2 * np + 1][0],
                        bf[2 * np + 1][1], b_addr[np][ks] + so);
#pragma unroll
            for (int mt = 0; mt < 4; mt++)
#pragma unroll
                for (int nt = 0; nt < 4; nt++)
                    mma_f16(acc[mt][nt], af[mt], bf[nt]);
        }
    }

    const int tq = lid >> 2;
    const int tr = lid & 3;
#pragma unroll
    for (int mt = 0; mt < 4; mt++) {
#pragma unroll
        for (int half = 0; half < 2; half++) {
            int node = m0 + wm * 64 + mt * 16 + tq + half * 8;
            float* row = out + ((size_t)node * NC + i) * CIN;
#pragma unroll
            for (int nt = 0; nt < 4; nt++) {
                int col = wn * 32 + nt * 8 + tr * 2;
                float2 v;
                v.x = acc[mt][nt][half * 2 + 0];
                v.y = acc[mt][nt][half * 2 + 1];
                if (i == 0) { v.x += b2[col]; v.y += b2[col + 1]; }
                *(float2*)&row[col] = v;
            }
        }
    }
}

// ---------------------------------------------------------------------------

extern "C" void kernel_launch(void* const* d_in, const int* in_sizes, int n_in,
                              void* d_out, int out_size) {
    const float* nf = (const float*)d_in[0];
    const float* w1 = (const float*)d_in[1];
    const float* b1 = (const float*)d_in[2];
    const float* w2 = (const float*)d_in[3];
    const float* b2 = (const float*)d_in[4];
    const float* ws = (const float*)d_in[5];
    const float* bs = (const float*)d_in[6];
    const float* g1 = (const float*)d_in[7];
    const float* g2 = (const float*)d_in[8];
    const float* g3 = (const float*)d_in[9];
    const float* Tg = (const float*)d_in[10];
    const float* Fg = (const float*)d_in[11];
    float* out = (float*)d_out;

    const int SMEM1 = 3 * (BM * 64 + BK * 512);   // 73728
    const int SMEM2 = 4 * (BM * 64 + BN * 64);    // 98304
    const int SMEMZ = 4 * (64 * 64 + BK * 512);   // 81920
    const int SMEMO = 4 * (BM * 64 + CIN * 64);   // 65536
    cudaFuncSetAttribute(k_grid1_mma, cudaFuncAttributeMaxDynamicSharedMemorySize, SMEM1);
    cudaFuncSetAttribute(k_grid2_mma, cudaFuncAttributeMaxDynamicSharedMemorySize, SMEM2);
    cudaFuncSetAttribute(k_z_mma,     cudaFuncAttributeMaxDynamicSharedMemorySize, SMEMZ);
    cudaFuncSetAttribute(k_y_mma,     cudaFuncAttributeMaxDynamicSharedMemorySize, SMEM2);
    cudaFuncSetAttribute(k_gate_mma,  cudaFuncAttributeMaxDynamicSharedMemorySize, SMEM2);
    cudaFuncSetAttribute(k_out_mma,   cudaFuncAttributeMaxDynamicSharedMemorySize, SMEMO);

    const int PS_BLOCKS = PS_TB + PS_FTB + PS_G2B + PS_NFH + PS_PADY + PS_PADG
                        + PS_WSH + PS_W2H;

    // prologs (3 launches)
    k_w1g1_h<<<dim3(HID / 64, CIN / 64, NL + 1), 256>>>(w1, g1, b1);
    k_g3w2_h<<<dim3(CIN / 64, HID / 64, NL), 256>>>(g3, w2);
    k_prep_static<<<PS_BLOCKS, 256>>>(nf, Tg, Fg, g2, ws, w2);

    // main pipeline (all MMA)
    k_y_mma<<<dim3(N_NODES / BM, NC), 512, SMEM2>>>();
    k_gate_mma<<<N_NODES / BM, 512, SMEM2>>>(bs);
    k_grid1_mma<<<dim3(3, N_NODES), 512, SMEM1>>>();
    k_grid2_mma<<<(int)(MROWS / BM), 512, SMEM2>>>();
    k_z_mma<<<N_NODES, 512, SMEMZ>>>();
    k_out_mma<<<dim3(N_NODES / BM, NC), 256, SMEMO>>>(b2, out);
}

// round 13
// speedup vs baseline: 1.3779x; 1.0610x over previous
#include <cuda_runtime.h>
#include <cuda_fp16.h>
#include <cstdint>

// ---------------------------------------------------------------------------
// FeedForwardNetwork (SO(3) equivariant FFN), sm_103a — all-MMA plain-fp16
// Round 13: resident-operand mainloops. All K-chunks cp.async'd up front
// (grid2: 192KB smem, y/gate: 96KB, out: 128KB, grid1: 48KB); compute runs
// in two phases with only two wait+sync pairs per block. z unchanged.
// ---------------------------------------------------------------------------

#define N_NODES 1024
#define NC      49
#define CIN     128
#define HID     256
#define RES     18
#define NP      (RES*RES)   // 324
#define NL      7
#define MROWS   ((size_t)N_NODES * NP)   // 331776
#define PBLK    352
#define BM      128
#define BN      256
#define BK      32
#define NITERZ  11           // z K chunks (352/32)

// -------- scratch (static device globals; no runtime allocation) -----------
__device__ float g_b1g1[HID];
__device__ __half g_Tb[384 * 64];                    // to_grid hi [384x64]
__device__ __half g_FTb[64 * PBLK];                  // from_grid^T hi [64x352]
__device__ __half g_g2b[HID * 256];                  // g2^T hi [256x256]
__device__ __half g_w1g1h[NL * HID * 128];           // W1G1^T hi rows
__device__ __half g_g3w2h[NL * CIN * 256];           // (g3 w2)^T hi rows
__device__ __half g_wsh[HID * 128];                  // ws^T hi [256x128]
__device__ __half g_w2h0[CIN * 256];                 // w2[0]^T hi [128x256]
__device__ __half g_nfh[(size_t)N_NODES * NC * CIN];       // 12.8 MB
__device__ __half g_yb[(size_t)N_NODES * 64 * HID];        // 34 MB
__device__ __half g_grid1b[MROWS * HID];                   // 170 MB
__device__ __half g_grid2b[(size_t)N_NODES * PBLK * HID];  // 185 MB
__device__ __half g_zh[(size_t)N_NODES * NC * HID];        // 25.7 MB
__device__ __half g_gateh[(size_t)N_NODES * HID];          // fp16 gate

__device__ __forceinline__ float silu_f(float x) {
    return x / (1.0f + __expf(-x));
}
__device__ __forceinline__ int deg_of(int i) {
    int l = 0;
    while ((l + 1) * (l + 1) <= i) ++l;
    return l;
}
__device__ __forceinline__ uint32_t smem_u32(const void* p) {
    uint32_t a;
    asm("{ .reg .u64 t; cvta.to.shared.u64 t, %1; cvt.u32.u64 %0, t; }"
        : "=r"(a) : "l"(p));
    return a;
}
__device__ __forceinline__ void cp_async16(uint32_t dst, const void* src) {
    asm volatile("cp.async.cg.shared.global [%0], [%1], 16;" :: "r"(dst), "l"(src));
}
template<int N>
__device__ __forceinline__ void waitg() {
    asm volatile("cp.async.wait_group %0;" :: "n"(N));
}
__device__ __forceinline__ void ldsm_x4(uint32_t& r0, uint32_t& r1,
                                        uint32_t& r2, uint32_t& r3, uint32_t addr) {
    asm volatile("ldmatrix.sync.aligned.m8n8.x4.shared.b16 {%0,%1,%2,%3}, [%4];"
                 : "=r"(r0), "=r"(r1), "=r"(r2), "=r"(r3) : "r"(addr));
}
__device__ __forceinline__ void ldsm_x4_t(uint32_t& r0, uint32_t& r1,
                                          uint32_t& r2, uint32_t& r3, uint32_t addr) {
    asm volatile("ldmatrix.sync.aligned.m8n8.x4.trans.shared.b16 {%0,%1,%2,%3}, [%4];"
                 : "=r"(r0), "=r"(r1), "=r"(r2), "=r"(r3) : "r"(addr));
}
__device__ __forceinline__ void mma_f16(float* d, const uint32_t* a, const uint32_t* b) {
    asm volatile(
        "mma.sync.aligned.m16n8k16.row.col.f32.f16.f16.f32 "
        "{%0,%1,%2,%3}, {%4,%5,%6,%7}, {%8,%9}, {%0,%1,%2,%3};"
        : "+f"(d[0]), "+f"(d[1]), "+f"(d[2]), "+f"(d[3])
        : "r"(a[0]), "r"(a[1]), "r"(a[2]), "r"(a[3]), "r"(b[0]), "r"(b[1]));
}
__device__ __forceinline__ uint32_t pkh2(float x, float y) {
    __half hx = __float2half_rn(x), hy = __float2half_rn(y);
    uint16_t bx = *(uint16_t*)&hx, by = *(uint16_t*)&hy;
    return (uint32_t)bx | ((uint32_t)by << 16);
}

// ---------------------------------------------------------------------------
// SIMT gemm body with fp16-transposed epilogue (weight prep only).
// ---------------------------------------------------------------------------
__device__ __forceinline__ void gemm_tile_w16(
    const float* __restrict__ A, int lda,
    const float* __restrict__ B, int ldb,
    __half* __restrict__ OUT, int out_stride,
    int K)
{
    __shared__ float As[16][64];
    __shared__ float Bs[16][64];

    const int tid = threadIdx.x;
    const int tx  = tid & 15;
    const int ty  = tid >> 4;
    const int m0  = blockIdx.y * 64;
    const int n0  = blockIdx.x * 64;

    float acc[4][4];
#pragma unroll
    for (int i = 0; i < 4; i++)
#pragma unroll
        for (int j = 0; j < 4; j++) acc[i][j] = 0.0f;

    for (int k0 = 0; k0 < K; k0 += 16) {
#pragma unroll
        for (int e = tid; e < 64 * 16; e += 256) {
            int m = e >> 4, k = e & 15;
            As[k][m] = A[(size_t)(m0 + m) * lda + k0 + k];
        }
#pragma unroll
        for (int e = tid; e < 16 * 64; e += 256) {
            int k = e >> 6, n = e & 63;
            Bs[k][n] = B[(size_t)(k0 + k) * ldb + n0 + n];
        }
        __syncthreads();

#pragma unroll
        for (int k = 0; k < 16; k++) {
            float4 av = *(const float4*)&As[k][ty * 4];
            float4 bv = *(const float4*)&Bs[k][tx * 4];
            float a4[4] = {av.x, av.y, av.z, av.w};
            float b4[4] = {bv.x, bv.y, bv.z, bv.w};
#pragma unroll
            for (int i = 0; i < 4; i++)
#pragma unroll
                for (int j = 0; j < 4; j++)
                    acc[i][j] += a4[i] * b4[j];
        }
        __syncthreads();
    }

#pragma unroll
    for (int i = 0; i < 4; i++) {
        int gm = m0 + ty * 4 + i;
#pragma unroll
        for (int j = 0; j < 4; j++) {
            int gn = n0 + tx * 4 + j;
            OUT[(size_t)gn * out_stride + gm] = __float2half_rn(acc[i][j]);
        }
    }
}

// ---------------------------- prolog kernels --------------------------------

__global__ void __launch_bounds__(256) k_w1g1_h(const float* __restrict__ w1,
                                                const float* __restrict__ g1,
                                                const float* __restrict__ b1) {
    if (blockIdx.z == NL) {
        if (blockIdx.x != 0 || blockIdx.y != 0) return;
        int k = threadIdx.x;
        float s = 0.0f;
        for (int h = 0; h < HID; h++) s += b1[h] * g1[(size_t)h * HID + k];
        g_b1g1[k] = s;
        return;
    }
    int l = blockIdx.z;
    gemm_tile_w16(w1 + (size_t)l * CIN * HID, HID, g1, HID,
                  g_w1g1h + (size_t)l * HID * 128, 128, HID);
}

__global__ void __launch_bounds__(256) k_g3w2_h(const float* __restrict__ g3,
                                                const float* __restrict__ w2) {
    int l = blockIdx.z;
    gemm_tile_w16(g3, HID, w2 + (size_t)l * HID * CIN, CIN,
                  g_g3w2h + (size_t)l * CIN * 256, 256, HID);
}

// Mega-prep: Tb | FTb | g2b | nfh | pad_yb | pad_g2b | wsh | w2h0.
#define PS_TB    96
#define PS_FTB   88
#define PS_G2B   256
#define PS_NFH   12544
#define PS_PADY  7680
#define PS_PADG  14336
#define PS_WSH   128
#define PS_W2H   128
__global__ void __launch_bounds__(256) k_prep_static(
    const float* __restrict__ nf, const float* __restrict__ T,
    const float* __restrict__ F,  const float* __restrict__ g2,
    const float* __restrict__ ws, const float* __restrict__ w2) {
    int b = blockIdx.x;
    int t = threadIdx.x;
    if (b < PS_TB) {
        int idx = b * 256 + t;
        int p = idx >> 6, i = idx & 63;
        float v = (p < NP && i < NC) ? T[p * NC + i] : 0.0f;
        g_Tb[idx] = __float2half_rn(v);
        return;
    }
    b -= PS_TB;
    if (b < PS_FTB) {
        int idx = b * 256 + t;
        int i = idx / PBLK, p = idx % PBLK;
        float v = (i < NC && p < NP) ? F[p * NC + i] : 0.0f;
        g_FTb[idx] = __float2half_rn(v);
        return;
    }
    b -= PS_FTB;
    if (b < PS_G2B) {
        int idx = b * 256 + t;
        int n = idx >> 8, k = idx & 255;
        g_g2b[idx] = __float2half_rn(g2[(size_t)k * HID + n]);
        return;
    }
    b -= PS_G2B;
    if (b < PS_NFH) {
        size_t gi = ((size_t)b * 256 + t) * 2;
        float2 v = *(const float2*)(nf + gi);
        *(uint32_t*)&g_nfh[gi] = pkh2(v.x, v.y);
        return;
    }
    b -= PS_NFH;
    if (b < PS_PADY) {
        size_t w = (size_t)b * 256 + t;
        int node = (int)(w / 1920);
        int rem  = (int)(w % 1920);
        int row  = NC + rem / 128;
        int c2   = rem & 127;
        *(uint32_t*)&g_yb[((size_t)node * 64 + row) * HID + c2 * 2] = 0;
        return;
    }
    b -= PS_PADY;
    if (b < PS_PADG) {
        size_t w = (size_t)b * 256 + t;
        int node = (int)(w / 3584);
        int rem  = (int)(w % 3584);
        int row  = NP + rem / 128;
        int c2   = rem & 127;
        *(uint32_t*)&g_grid2b[((size_t)node * PBLK + row) * HID + c2 * 2] = 0;
        return;
    }
    b -= PS_PADG;
    if (b < PS_WSH) {
        int idx = b * 256 + t;
        int n = idx >> 7, k = idx & 127;
        g_wsh[idx] = __float2half_rn(ws[(size_t)k * HID + n]);
        return;
    }
    b -= PS_WSH;
    {
        int idx = b * 256 + t;
        int n = idx >> 8, k = idx & 255;
        g_w2h0[idx] = __float2half_rn(w2[(size_t)k * CIN + n]);
    }
}

// ---------------------------- main stage kernels ----------------------------
// Common 512-thread shape: BM=128, warp tile 64x32 over N=256 (wn 0..7).

// ---- y / gate shared skeleton: K=128, 4 resident chunks --------------------
template<bool IS_GATE>
__device__ __forceinline__ void ygate_body(const float* __restrict__ bs) {
    extern __shared__ __align__(128) char smem[];
    const uint32_t sbase = smem_u32(smem);
    const int tid = threadIdx.x;
    const int wid = tid >> 5;
    const int lid = tid & 31;
    const int wm  = wid & 1;
    const int wn  = wid >> 1;
    const int i   = IS_GATE ? 0 : blockIdx.y;
    const int l   = deg_of(i);
    const int m0  = blockIdx.x * BM;

    const uint32_t STAGE = BM * 64 + BN * 64;    // 24576
    const uint32_t BOFF  = BM * 64;

    uint32_t a_addr[4][2], b_addr[2][2];
#pragma unroll
    for (int mt = 0; mt < 4; mt++)
#pragma unroll
        for (int ks = 0; ks < 2; ks++) {
            int row = wm * 64 + mt * 16 + (lid & 7) + ((lid >> 3) & 1) * 8;
            int ch  = ks * 2 + (lid >> 4);
            a_addr[mt][ks] = sbase + row * 64 + 16 * (ch ^ ((row >> 1) & 3));
        }
#pragma unroll
    for (int np = 0; np < 2; np++)
#pragma unroll
        for (int ks = 0; ks < 2; ks++) {
            int row = wn * 32 + np * 16 + (lid & 7) + (lid >> 4) * 8;
            int ch  = ks * 2 + ((lid >> 3) & 1);
            b_addr[np][ks] = sbase + BOFF + row * 64 + 16 * (ch ^ ((row >> 1) & 3));
        }

    uint32_t a_rel, b_rel[2];
    const __half* a_basep;
    const __half* b_base[2];
    {
        int r = tid >> 2, c = tid & 3;
        a_rel = sbase + r * 64 + 16 * (c ^ ((r >> 1) & 3));
        a_basep = g_nfh + ((size_t)(m0 + r) * NC + i) * CIN + c * 8;
    }
#pragma unroll
    for (int j = 0; j < 2; j++) {
        int id = tid + j * 512, r = id >> 2, c = id & 3;
        b_rel[j] = sbase + BOFF + r * 64 + 16 * (c ^ ((r >> 1) & 3));
        b_base[j] = (IS_GATE ? g_wsh + (size_t)r * 128
                             : g_w1g1h + ((size_t)l * HID + r) * 128) + c * 8;
    }

    // issue all 4 chunks
#pragma unroll
    for (int s = 0; s < 4; s++) {
        uint32_t so = s * STAGE;
        cp_async16(a_rel + so, a_basep + s * 32);
#pragma unroll
        for (int j = 0; j < 2; j++) cp_async16(b_rel[j] + so, b_base[j] + s * 32);
        asm volatile("cp.async.commit_group;");
    }

    float acc[4][4][4];
#pragma unroll
    for (int mt = 0; mt < 4; mt++)
#pragma unroll
        for (int nt = 0; nt < 4; nt++)
#pragma unroll
            for (int v = 0; v < 4; v++) acc[mt][nt][v] = 0.0f;

    auto compute = [&](int kc) {
        const uint32_t so = kc * STAGE;
#pragma unroll
        for (int ks = 0; ks < 2; ks++) {
            uint32_t af[4][4], bf[4][2];
#pragma unroll
            for (int mt = 0; mt < 4; mt++)
                ldsm_x4(af[mt][0], af[mt][1], af[mt][2], af[mt][3],
                        a_addr[mt][ks] + so);
#pragma unroll
            for (int np = 0; np < 2; np++)
                ldsm_x4(bf[2 * np][0], bf[2 * np][1], bf[2 * np + 1][0],
                        bf[2 * np + 1][1], b_addr[np][ks] + so);
#pragma unroll
            for (int mt = 0; mt < 4; mt++)
#pragma unroll
                for (int nt = 0; nt < 4; nt++)
                    mma_f16(acc[mt][nt], af[mt], bf[nt]);
        }
    };

    waitg<2>(); __syncthreads();
    compute(0); compute(1);
    waitg<0>(); __syncthreads();
    compute(2); compute(3);

    const int tq = lid >> 2;
    const int tr = lid & 3;
#pragma unroll
    for (int mt = 0; mt < 4; mt++) {
#pragma unroll
        for (int half = 0; half < 2; half++) {
            int node = m0 + wm * 64 + mt * 16 + tq + half * 8;
#pragma unroll
            for (int nt = 0; nt < 4; nt++) {
                int col = wn * 32 + nt * 8 + tr * 2;
                float v0 = acc[mt][nt][half * 2 + 0];
                float v1 = acc[mt][nt][half * 2 + 1];
                if (IS_GATE) {
                    v0 = silu_f(v0 + bs[col]);
                    v1 = silu_f(v1 + bs[col + 1]);
                    *(uint32_t*)&g_gateh[(size_t)node * HID + col] = pkh2(v0, v1);
                } else {
                    if (i == 0) { v0 += g_b1g1[col]; v1 += g_b1g1[col + 1]; }
                    *(uint32_t*)&g_yb[((size_t)node * 64 + i) * HID + col] = pkh2(v0, v1);
                }
            }
        }
    }
}

__global__ void __launch_bounds__(512, 1) k_y_mma() { ygate_body<false>(nullptr); }
__global__ void __launch_bounds__(512, 1) k_gate_mma(const float* __restrict__ bs) {
    ygate_body<true>(bs);
}

// -------- grid1 = silu(T @ y[n]) : K=64, 2 resident chunks, trans-B ---------
__global__ void __launch_bounds__(512, 1) k_grid1_mma() {
    extern __shared__ __align__(128) char smem[];
    const uint32_t sbase = smem_u32(smem);
    const int tid = threadIdx.x;
    const int wid = tid >> 5;
    const int lid = tid & 31;
    const int wm  = wid & 1;
    const int wn  = wid >> 1;
    const int node = blockIdx.y;
    const int m0 = blockIdx.x * BM;

    const uint32_t STAGE = BM * 64 + BK * 512;   // 24576
    const uint32_t BOFF  = BM * 64;

    uint32_t a_addr[4][2], b_addr[2][2];
#pragma unroll
    for (int mt = 0; mt < 4; mt++)
#pragma unroll
        for (int ks = 0; ks < 2; ks++) {
            int row = wm * 64 + mt * 16 + (lid & 7) + ((lid >> 3) & 1) * 8;
            int ch  = ks * 2 + (lid >> 4);
            a_addr[mt][ks] = sbase + row * 64 + 16 * (ch ^ ((row >> 1) & 3));
        }
#pragma unroll
    for (int np = 0; np < 2; np++)
#pragma unroll
        for (int ks = 0; ks < 2; ks++) {
            int row = ks * 16 + (lid & 7) + 8 * ((lid >> 3) & 1);
            int cn  = wn * 4 + np * 2 + (lid >> 4);
            b_addr[np][ks] = sbase + BOFF + row * 512 + 16 * (cn ^ (row & 7));
        }

    uint32_t a_rel, b_rel[2];
    const __half* a_basep;
    const __half* b_base[2];
    const __half* ybn = g_yb + (size_t)node * (64 * HID);
    {
        int r = tid >> 2, c = tid & 3;
        a_rel = sbase + r * 64 + 16 * (c ^ ((r >> 1) & 3));
        a_basep = g_Tb + (m0 + r) * 64 + c * 8;
    }
#pragma unroll
    for (int j = 0; j < 2; j++) {
        int id = tid + j * 512, r = id >> 5, c = id & 31;
        b_rel[j] = sbase + BOFF + r * 512 + 16 * (c ^ (r & 7));
        b_base[j] = ybn + r * HID + c * 8;
    }

#pragma unroll
    for (int s = 0; s < 2; s++) {
        uint32_t so = s * STAGE;
        cp_async16(a_rel + so, a_basep + s * 32);
#pragma unroll
        for (int j = 0; j < 2; j++) cp_async16(b_rel[j] + so, b_base[j] + s * 32 * HID);
        asm volatile("cp.async.commit_group;");
    }

    float acc[4][4][4];
#pragma unroll
    for (int mt = 0; mt < 4; mt++)
#pragma unroll
        for (int nt = 0; nt < 4; nt++)
#pragma unroll
            for (int v = 0; v < 4; v++) acc[mt][nt][v] = 0.0f;

    auto compute = [&](int kc) {
        const uint32_t so = kc * STAGE;
#pragma unroll
        for (int ks = 0; ks < 2; ks++) {
            uint32_t af[4][4], bf[4][2];
#pragma unroll
            for (int mt = 0; mt < 4; mt++)
                ldsm_x4(af[mt][0], af[mt][1], af[mt][2], af[mt][3],
                        a_addr[mt][ks] + so);
#pragma unroll
            for (int np = 0; np < 2; np++)
                ldsm_x4_t(bf[2 * np][0], bf[2 * np][1], bf[2 * np + 1][0],
                          bf[2 * np + 1][1], b_addr[np][ks] + so);
#pragma unroll
            for (int mt = 0; mt < 4; mt++)
#pragma unroll
                for (int nt = 0; nt < 4; nt++)
                    mma_f16(acc[mt][nt], af[mt], bf[nt]);
        }
    };

    waitg<1>(); __syncthreads();
    compute(0);
    waitg<0>(); __syncthreads();
    compute(1);

    const int tq = lid >> 2;
    const int tr = lid & 3;
#pragma unroll
    for (int mt = 0; mt < 4; mt++) {
#pragma unroll
        for (int half = 0; half < 2; half++) {
            int p = m0 + wm * 64 + mt * 16 + tq + half * 8;
            if (p >= NP) continue;
            __half* row = g_grid1b + ((size_t)node * NP + p) * HID;
#pragma unroll
            for (int nt = 0; nt < 4; nt++) {
                int col = wn * 32 + nt * 8 + tr * 2;
                *(uint32_t*)&row[col] = pkh2(silu_f(acc[mt][nt][half * 2 + 0]),
                                             silu_f(acc[mt][nt][half * 2 + 1]));
            }
        }
    }
}

// -------- grid2 = silu(grid1 @ g2): K=256, 8 resident chunks (192KB) --------
__global__ void __launch_bounds__(512, 1) k_grid2_mma() {
    extern __shared__ __align__(128) char smem[];
    const uint32_t sbase = smem_u32(smem);
    const int tid = threadIdx.x;
    const int wid = tid >> 5;
    const int lid = tid & 31;
    const int wm  = wid & 1;
    const int wn  = wid >> 1;
    const size_t m0 = (size_t)blockIdx.x * BM;

    const uint32_t STAGE = BM * 64 + BN * 64;    // 24576
    const uint32_t BOFF  = BM * 64;

    uint32_t a_addr[4][2], b_addr[2][2];
#pragma unroll
    for (int mt = 0; mt < 4; mt++)
#pragma unroll
        for (int ks = 0; ks < 2; ks++) {
            int row = wm * 64 + mt * 16 + (lid & 7) + ((lid >> 3) & 1) * 8;
            int ch  = ks * 2 + (lid >> 4);
            a_addr[mt][ks] = sbase + row * 64 + 16 * (ch ^ ((row >> 1) & 3));
        }
#pragma unroll
    for (int np = 0; np < 2; np++)
#pragma unroll
        for (int ks = 0; ks < 2; ks++) {
            int row = wn * 32 + np * 16 + (lid & 7) + (lid >> 4) * 8;
            int ch  = ks * 2 + ((lid >> 3) & 1);
            b_addr[np][ks] = sbase + BOFF + row * 64 + 16 * (ch ^ ((row >> 1) & 3));
        }

    uint32_t a_rel, b_rel[2];
    const __half* a_basep;
    const __half* b_base[2];
    {
        int r = tid >> 2, c = tid & 3;
        a_rel = sbase + r * 64 + 16 * (c ^ ((r >> 1) & 3));
        a_basep = g_grid1b + (m0 + r) * (size_t)HID + c * 8;
    }
#pragma unroll
    for (int j = 0; j < 2; j++) {
        int id = tid + j * 512, r = id >> 2, c = id & 3;
        b_rel[j] = sbase + BOFF + r * 64 + 16 * (c ^ ((r >> 1) & 3));
        b_base[j] = g_g2b + r * (size_t)256 + c * 8;
    }

    // issue all 8 chunks
#pragma unroll
    for (int s = 0; s < 8; s++) {
        uint32_t so = s * STAGE;
        cp_async16(a_rel + so, a_basep + s * 32);
#pragma unroll
        for (int j = 0; j < 2; j++) cp_async16(b_rel[j] + so, b_base[j] + s * 32);
        asm volatile("cp.async.commit_group;");
    }

    float acc[4][4][4];
#pragma unroll
    for (int mt = 0; mt < 4; mt++)
#pragma unroll
        for (int nt = 0; nt < 4; nt++)
#pragma unroll
            for (int v = 0; v < 4; v++) acc[mt][nt][v] = 0.0f;

    auto compute = [&](int kc) {
        const uint32_t so = kc * STAGE;
#pragma unroll
        for (int ks = 0; ks < 2; ks++) {
            uint32_t af[4][4], bf[4][2];
#pragma unroll
            for (int mt = 0; mt < 4; mt++)
                ldsm_x4(af[mt][0], af[mt][1], af[mt][2], af[mt][3],
                        a_addr[mt][ks] + so);
#pragma unroll
            for (int np = 0; np < 2; np++)
                ldsm_x4(bf[2 * np][0], bf[2 * np][1], bf[2 * np + 1][0],
                        bf[2 * np + 1][1], b_addr[np][ks] + so);
#pragma unroll
            for (int mt = 0; mt < 4; mt++)
#pragma unroll
                for (int nt = 0; nt < 4; nt++)
                    mma_f16(acc[mt][nt], af[mt], bf[nt]);
        }
    };

    waitg<4>(); __syncthreads();
    compute(0); compute(1); compute(2); compute(3);
    waitg<0>(); __syncthreads();
    compute(4); compute(5); compute(6); compute(7);

    const int tq = lid >> 2;
    const int tr = lid & 3;
#pragma unroll
    for (int mt = 0; mt < 4; mt++) {
#pragma unroll
        for (int half = 0; half < 2; half++) {
            size_t r = m0 + wm * 64 + mt * 16 + tq + half * 8;
            uint32_t n = (uint32_t)(r / NP);
            uint32_t p = (uint32_t)(r - (size_t)n * NP);
            __half* row = g_grid2b + ((size_t)n * PBLK + p) * HID;
#pragma unroll
            for (int nt = 0; nt < 4; nt++) {
                int col = wn * 32 + nt * 8 + tr * 2;
                *(uint32_t*)&row[col] = pkh2(silu_f(acc[mt][nt][half * 2 + 0]),
                                             silu_f(acc[mt][nt][half * 2 + 1]));
            }
        }
    }
}

// -------- z = F^T @ grid2[n] : fp16 MMA, K=352, trans-B, 4-stage (R12) ------
__global__ void __launch_bounds__(512, 1) k_z_mma() {
    extern __shared__ __align__(128) char smem[];
    const uint32_t sbase = smem_u32(smem);
    const int tid = threadIdx.x;
    const int wid = tid >> 5;
    const int lid = tid & 31;
    const int node = blockIdx.x;

    const uint32_t STAGE = 64 * 64 + BK * 512;   // 20480
    const uint32_t BOFF  = 64 * 64;

    uint32_t a_addr[4][2], b_addr[2];
#pragma unroll
    for (int mt = 0; mt < 4; mt++)
#pragma unroll
        for (int ks = 0; ks < 2; ks++) {
            int row = mt * 16 + (lid & 7) + ((lid >> 3) & 1) * 8;
            int ch  = ks * 2 + (lid >> 4);
            a_addr[mt][ks] = sbase + row * 64 + 16 * (ch ^ ((row >> 1) & 3));
        }
#pragma unroll
    for (int ks = 0; ks < 2; ks++) {
        int row = ks * 16 + (lid & 7) + 8 * ((lid >> 3) & 1);
        int cn  = wid * 2 + (lid >> 4);
        b_addr[ks] = sbase + BOFF + row * 512 + 16 * (cn ^ (row & 7));
    }

    uint32_t a_rel = 0, b_rel[2];
    const __half* a_basep = nullptr;
    const __half* b_base[2];
    const __half* g2bn = g_grid2b + (size_t)node * (PBLK * HID);
    if (tid < 256) {
        int r = tid >> 2, c = tid & 3;
        a_rel = sbase + r * 64 + 16 * (c ^ ((r >> 1) & 3));
        a_basep = g_FTb + r * PBLK + c * 8;
    }
#pragma unroll
    for (int j = 0; j < 2; j++) {
        int id = tid + j * 512, r = id >> 5, c = id & 31;
        b_rel[j] = sbase + BOFF + r * 512 + 16 * (c ^ (r & 7));
        b_base[j] = g2bn + r * HID + c * 8;
    }

    float acc[4][2][4];
#pragma unroll
    for (int mt = 0; mt < 4; mt++)
#pragma unroll
        for (int nt = 0; nt < 2; nt++)
#pragma unroll
            for (int v = 0; v < 4; v++) acc[mt][nt][v] = 0.0f;

#pragma unroll
    for (int s = 0; s < 3; s++) {
        uint32_t so = s * STAGE;
        if (tid < 256) cp_async16(a_rel + so, a_basep + s * 32);
#pragma unroll
        for (int j = 0; j < 2; j++) cp_async16(b_rel[j] + so, b_base[j] + s * 32 * HID);
        asm volatile("cp.async.commit_group;");
    }

#pragma unroll 1
    for (int kc = 0; kc < NITERZ; kc++) {
        asm volatile("cp.async.wait_group 2;");
        __syncthreads();
        int pf = kc + 3;
        if (pf < NITERZ) {
            uint32_t so = (pf & 3) * STAGE;
            if (tid < 256) cp_async16(a_rel + so, a_basep + pf * 32);
#pragma unroll
            for (int j = 0; j < 2; j++) cp_async16(b_rel[j] + so, b_base[j] + pf * 32 * HID);
        }
        asm volatile("cp.async.commit_group;");

        const uint32_t so = (kc & 3) * STAGE;
#pragma unroll
        for (int ks = 0; ks < 2; ks++) {
            uint32_t af[4][4], bf[2][2];
#pragma unroll
            for (int mt = 0; mt < 4; mt++)
                ldsm_x4(af[mt][0], af[mt][1], af[mt][2], af[mt][3],
                        a_addr[mt][ks] + so);
            ldsm_x4_t(bf[0][0], bf[0][1], bf[1][0], bf[1][1], b_addr[ks] + so);
#pragma unroll
            for (int mt = 0; mt < 4; mt++)
#pragma unroll
                for (int nt = 0; nt < 2; nt++)
                    mma_f16(acc[mt][nt], af[mt], bf[nt]);
        }
    }

    const int tq = lid >> 2;
    const int tr = lid & 3;
#pragma unroll
    for (int mt = 0; mt < 4; mt++) {
#pragma unroll
        for (int half = 0; half < 2; half++) {
            int i = mt * 16 + tq + half * 8;
            if (i >= NC) continue;
            __half* row = g_zh + ((size_t)node * NC + i) * HID;
#pragma unroll
            for (int nt = 0; nt < 2; nt++) {
                int col = wid * 16 + nt * 8 + tr * 2;
                *(uint32_t*)&row[col] = pkh2(acc[mt][nt][half * 2 + 0],
                                             acc[mt][nt][half * 2 + 1]);
            }
        }
    }
}

// ---- out[:,i,:] : K=256, 8 resident chunks (128KB), 256 thr ----------------
__global__ void __launch_bounds__(256, 1) k_out_mma(const float* __restrict__ b2,
                                                    float* __restrict__ out) {
    extern __shared__ __align__(128) char smem[];
    const uint32_t sbase = smem_u32(smem);
    const int tid = threadIdx.x;
    const int wid = tid >> 5;
    const int lid = tid & 31;
    const int wm  = wid & 1;
    const int wn  = wid >> 1;
    const int i   = blockIdx.y;
    const int m0  = blockIdx.x * BM;

    const uint32_t STAGE = BM * 64 + CIN * 64;   // 16384
    const uint32_t BOFF  = BM * 64;

    uint32_t a_addr[4][2], b_addr[2][2];
#pragma unroll
    for (int mt = 0; mt < 4; mt++)
#pragma unroll
        for (int ks = 0; ks < 2; ks++) {
            int row = wm * 64 + mt * 16 + (lid & 7) + ((lid >> 3) & 1) * 8;
            int ch  = ks * 2 + (lid >> 4);
            a_addr[mt][ks] = sbase + row * 64 + 16 * (ch ^ ((row >> 1) & 3));
        }
#pragma unroll
    for (int np = 0; np < 2; np++)
#pragma unroll
        for (int ks = 0; ks < 2; ks++) {
            int row = wn * 32 + np * 16 + (lid & 7) + (lid >> 4) * 8;
            int ch  = ks * 2 + ((lid >> 3) & 1);
            b_addr[np][ks] = sbase + BOFF + row * 64 + 16 * (ch ^ ((row >> 1) & 3));
        }

    uint32_t a_rel[2], b_rel[2];
    const __half* a_base[2];
    const __half* b_base[2];
#pragma unroll
    for (int j = 0; j < 2; j++) {
        int id = tid + j * 256, r = id >> 2, c = id & 3;
        a_rel[j] = sbase + r * 64 + 16 * (c ^ ((r >> 1) & 3));
        b_rel[j] = sbase + BOFF + r * 64 + 16 * (c ^ ((r >> 1) & 3));
        if (i == 0) {
            a_base[j] = g_gateh + (size_t)(m0 + r) * HID + c * 8;
            b_base[j] = g_w2h0 + (size_t)r * 256 + c * 8;
        } else {
            int l = deg_of(i);
            a_base[j] = g_zh + ((size_t)(m0 + r) * NC + i) * HID + c * 8;
            b_base[j] = g_g3w2h + ((size_t)l * CIN + r) * 256 + c * 8;
        }
    }

#pragma unroll
    for (int s = 0; s < 8; s++) {
        uint32_t so = s * STAGE;
#pragma unroll
        for (int j = 0; j < 2; j++) {
            cp_async16(a_rel[j] + so, a_base[j] + s * 32);
            cp_async16(b_rel[j] + so, b_base[j] + s * 32);
        }
        asm volatile("cp.async.commit_group;");
    }

    float acc[4][4][4];
#pragma unroll
    for (int mt = 0; mt < 4; mt++)
#pragma unroll
        for (int nt = 0; nt < 4; nt++)
#pragma unroll
            for (int v = 0; v < 4; v++) acc[mt][nt][v] = 0.0f;

    auto compute = [&](int kc) {
        const uint32_t so = kc * STAGE;
#pragma unroll
        for (int ks = 0; ks < 2; ks++) {
            uint32_t af[4][4], bf[4][2];
#pragma unroll
            for (int mt = 0; mt < 4; mt++)
                ldsm_x4(af[mt][0], af[mt][1], af[mt][2], af[mt][3],
                        a_addr[mt][ks] + so);
#pragma unroll
            for (int np = 0; np < 2; np++)
                ldsm_x4(bf[2 * np][0], bf[2 * np][1], bf[2 * np + 1][0],
                        bf[2 * np + 1][1], b_addr[np][ks] + so);
#pragma unroll
            for (int mt = 0; mt < 4; mt++)
#pragma unroll
                for (int nt = 0; nt < 4; nt++)
                    mma_f16(acc[mt][nt], af[mt], bf[nt]);
        }
    };

    waitg<4>(); __syncthreads();
    compute(0); compute(1); compute(2); compute(3);
    waitg<0>(); __syncthreads();
    compute(4); compute(5); compute(6); compute(7);

    const int tq = lid >> 2;
    const int tr = lid & 3;
#pragma unroll
    for (int mt = 0; mt < 4; mt++) {
#pragma unroll
        for (int half = 0; half < 2; half++) {
            int node = m0 + wm * 64 + mt * 16 + tq + half * 8;
            float* row = out + ((size_t)node * NC + i) * CIN;
#pragma unroll
            for (int nt = 0; nt < 4; nt++) {
                int col = wn * 32 + nt * 8 + tr * 2;
                float2 v;
                v.x = acc[mt][nt][half * 2 + 0];
                v.y = acc[mt][nt][half * 2 + 1];
                if (i == 0) { v.x += b2[col]; v.y += b2[col + 1]; }
                *(float2*)&row[col] = v;
            }
        }
    }
}

// ---------------------------------------------------------------------------

extern "C" void kernel_launch(void* const* d_in, const int* in_sizes, int n_in,
                              void* d_out, int out_size) {
    const float* nf = (const float*)d_in[0];
    const float* w1 = (const float*)d_in[1];
    const float* b1 = (const float*)d_in[2];
    const float* w2 = (const float*)d_in[3];
    const float* b2 = (const float*)d_in[4];
    const float* ws = (const float*)d_in[5];
    const float* bs = (const float*)d_in[6];
    const float* g1 = (const float*)d_in[7];
    const float* g2 = (const float*)d_in[8];
    const float* g3 = (const float*)d_in[9];
    const float* Tg = (const float*)d_in[10];
    const float* Fg = (const float*)d_in[11];
    float* out = (float*)d_out;

    const int SMEM1 = 2 * 24576;   // 49152  (grid1)
    const int SMEM2 = 8 * 24576;   // 196608 (grid2)
    const int SMEMY = 4 * 24576;   // 98304  (y / gate)
    const int SMEMZ = 4 * 20480;   // 81920  (z)
    const int SMEMO = 8 * 16384;   // 131072 (out)
    cudaFuncSetAttribute(k_grid1_mma, cudaFuncAttributeMaxDynamicSharedMemorySize, SMEM1);
    cudaFuncSetAttribute(k_grid2_mma, cudaFuncAttributeMaxDynamicSharedMemorySize, SMEM2);
    cudaFuncSetAttribute(k_z_mma,     cudaFuncAttributeMaxDynamicSharedMemorySize, SMEMZ);
    cudaFuncSetAttribute(k_y_mma,     cudaFuncAttributeMaxDynamicSharedMemorySize, SMEMY);
    cudaFuncSetAttribute(k_gate_mma,  cudaFuncAttributeMaxDynamicSharedMemorySize, SMEMY);
    cudaFuncSetAttribute(k_out_mma,   cudaFuncAttributeMaxDynamicSharedMemorySize, SMEMO);

    const int PS_BLOCKS = PS_TB + PS_FTB + PS_G2B + PS_NFH + PS_PADY + PS_PADG
                        + PS_WSH + PS_W2H;

    // prologs (3 launches)
    k_w1g1_h<<<dim3(HID / 64, CIN / 64, NL + 1), 256>>>(w1, g1, b1);
    k_g3w2_h<<<dim3(CIN / 64, HID / 64, NL), 256>>>(g3, w2);
    k_prep_static<<<PS_BLOCKS, 256>>>(nf, Tg, Fg, g2, ws, w2);

    // main pipeline (all MMA)
    k_y_mma<<<dim3(N_NODES / BM, NC), 512, SMEMY>>>();
    k_gate_mma<<<N_NODES / BM, 512, SMEMY>>>(bs);
    k_grid1_mma<<<dim3(3, N_NODES), 512, SMEM1>>>();
    k_grid2_mma<<<(int)(MROWS / BM), 512, SMEM2>>>();
    k_z_mma<<<N_NODES, 512, SMEMZ>>>();
    k_out_mma<<<dim3(N_NODES / BM, NC), 256, SMEMO>>>(b2, out);
}

// round 14
// speedup vs baseline: 1.3934x; 1.0112x over previous
#include <cuda_runtime.h>
#include <cuda_fp16.h>
#include <cstdint>

// ---------------------------------------------------------------------------
// FeedForwardNetwork (SO(3) equivariant FFN), sm_103a — all-MMA plain-fp16
// Round 14: z_mma made fully resident (11 K-chunks, 225KB smem, 2 barrier
// pairs); gate merged into k_y_mma (blockIdx.y == NC). 8 launches.
// ---------------------------------------------------------------------------

#define N_NODES 1024
#define NC      49
#define CIN     128
#define HID     256
#define RES     18
#define NP      (RES*RES)   // 324
#define NL      7
#define MROWS   ((size_t)N_NODES * NP)   // 331776
#define PBLK    352
#define BM      128
#define BN      256
#define BK      32

// -------- scratch (static device globals; no runtime allocation) -----------
__device__ float g_b1g1[HID];
__device__ __half g_Tb[384 * 64];                    // to_grid hi [384x64]
__device__ __half g_FTb[64 * PBLK];                  // from_grid^T hi [64x352]
__device__ __half g_g2b[HID * 256];                  // g2^T hi [256x256]
__device__ __half g_w1g1h[NL * HID * 128];           // W1G1^T hi rows
__device__ __half g_g3w2h[NL * CIN * 256];           // (g3 w2)^T hi rows
__device__ __half g_wsh[HID * 128];                  // ws^T hi [256x128]
__device__ __half g_w2h0[CIN * 256];                 // w2[0]^T hi [128x256]
__device__ __half g_nfh[(size_t)N_NODES * NC * CIN];       // 12.8 MB
__device__ __half g_yb[(size_t)N_NODES * 64 * HID];        // 34 MB
__device__ __half g_grid1b[MROWS * HID];                   // 170 MB
__device__ __half g_grid2b[(size_t)N_NODES * PBLK * HID];  // 185 MB
__device__ __half g_zh[(size_t)N_NODES * NC * HID];        // 25.7 MB
__device__ __half g_gateh[(size_t)N_NODES * HID];          // fp16 gate

__device__ __forceinline__ float silu_f(float x) {
    return x / (1.0f + __expf(-x));
}
__device__ __forceinline__ int deg_of(int i) {
    int l = 0;
    while ((l + 1) * (l + 1) <= i) ++l;
    return l;
}
__device__ __forceinline__ uint32_t smem_u32(const void* p) {
    uint32_t a;
    asm("{ .reg .u64 t; cvta.to.shared.u64 t, %1; cvt.u32.u64 %0, t; }"
        : "=r"(a) : "l"(p));
    return a;
}
__device__ __forceinline__ void cp_async16(uint32_t dst, const void* src) {
    asm volatile("cp.async.cg.shared.global [%0], [%1], 16;" :: "r"(dst), "l"(src));
}
template<int N>
__device__ __forceinline__ void waitg() {
    asm volatile("cp.async.wait_group %0;" :: "n"(N));
}
__device__ __forceinline__ void ldsm_x4(uint32_t& r0, uint32_t& r1,
                                        uint32_t& r2, uint32_t& r3, uint32_t addr) {
    asm volatile("ldmatrix.sync.aligned.m8n8.x4.shared.b16 {%0,%1,%2,%3}, [%4];"
                 : "=r"(r0), "=r"(r1), "=r"(r2), "=r"(r3) : "r"(addr));
}
__device__ __forceinline__ void ldsm_x4_t(uint32_t& r0, uint32_t& r1,
                                          uint32_t& r2, uint32_t& r3, uint32_t addr) {
    asm volatile("ldmatrix.sync.aligned.m8n8.x4.trans.shared.b16 {%0,%1,%2,%3}, [%4];"
                 : "=r"(r0), "=r"(r1), "=r"(r2), "=r"(r3) : "r"(addr));
}
__device__ __forceinline__ void mma_f16(float* d, const uint32_t* a, const uint32_t* b) {
    asm volatile(
        "mma.sync.aligned.m16n8k16.row.col.f32.f16.f16.f32 "
        "{%0,%1,%2,%3}, {%4,%5,%6,%7}, {%8,%9}, {%0,%1,%2,%3};"
        : "+f"(d[0]), "+f"(d[1]), "+f"(d[2]), "+f"(d[3])
        : "r"(a[0]), "r"(a[1]), "r"(a[2]), "r"(a[3]), "r"(b[0]), "r"(b[1]));
}
__device__ __forceinline__ uint32_t pkh2(float x, float y) {
    __half hx = __float2half_rn(x), hy = __float2half_rn(y);
    uint16_t bx = *(uint16_t*)&hx, by = *(uint16_t*)&hy;
    return (uint32_t)bx | ((uint32_t)by << 16);
}

// ---------------------------------------------------------------------------
// SIMT gemm body with fp16-transposed epilogue (weight prep only).
// ---------------------------------------------------------------------------
__device__ __forceinline__ void gemm_tile_w16(
    const float* __restrict__ A, int lda,
    const float* __restrict__ B, int ldb,
    __half* __restrict__ OUT, int out_stride,
    int K)
{
    __shared__ float As[16][64];
    __shared__ float Bs[16][64];

    const int tid = threadIdx.x;
    const int tx  = tid & 15;
    const int ty  = tid >> 4;
    const int m0  = blockIdx.y * 64;
    const int n0  = blockIdx.x * 64;

    float acc[4][4];
#pragma unroll
    for (int i = 0; i < 4; i++)
#pragma unroll
        for (int j = 0; j < 4; j++) acc[i][j] = 0.0f;

    for (int k0 = 0; k0 < K; k0 += 16) {
#pragma unroll
        for (int e = tid; e < 64 * 16; e += 256) {
            int m = e >> 4, k = e & 15;
            As[k][m] = A[(size_t)(m0 + m) * lda + k0 + k];
        }
#pragma unroll
        for (int e = tid; e < 16 * 64; e += 256) {
            int k = e >> 6, n = e & 63;
            Bs[k][n] = B[(size_t)(k0 + k) * ldb + n0 + n];
        }
        __syncthreads();

#pragma unroll
        for (int k = 0; k < 16; k++) {
            float4 av = *(const float4*)&As[k][ty * 4];
            float4 bv = *(const float4*)&Bs[k][tx * 4];
            float a4[4] = {av.x, av.y, av.z, av.w};
            float b4[4] = {bv.x, bv.y, bv.z, bv.w};
#pragma unroll
            for (int i = 0; i < 4; i++)
#pragma unroll
                for (int j = 0; j < 4; j++)
                    acc[i][j] += a4[i] * b4[j];
        }
        __syncthreads();
    }

#pragma unroll
    for (int i = 0; i < 4; i++) {
        int gm = m0 + ty * 4 + i;
#pragma unroll
        for (int j = 0; j < 4; j++) {
            int gn = n0 + tx * 4 + j;
            OUT[(size_t)gn * out_stride + gm] = __float2half_rn(acc[i][j]);
        }
    }
}

// ---------------------------- prolog kernels --------------------------------

__global__ void __launch_bounds__(256) k_w1g1_h(const float* __restrict__ w1,
                                                const float* __restrict__ g1,
                                                const float* __restrict__ b1) {
    if (blockIdx.z == NL) {
        if (blockIdx.x != 0 || blockIdx.y != 0) return;
        int k = threadIdx.x;
        float s = 0.0f;
        for (int h = 0; h < HID; h++) s += b1[h] * g1[(size_t)h * HID + k];
        g_b1g1[k] = s;
        return;
    }
    int l = blockIdx.z;
    gemm_tile_w16(w1 + (size_t)l * CIN * HID, HID, g1, HID,
                  g_w1g1h + (size_t)l * HID * 128, 128, HID);
}

__global__ void __launch_bounds__(256) k_g3w2_h(const float* __restrict__ g3,
                                                const float* __restrict__ w2) {
    int l = blockIdx.z;
    gemm_tile_w16(g3, HID, w2 + (size_t)l * HID * CIN, CIN,
                  g_g3w2h + (size_t)l * CIN * 256, 256, HID);
}

// Mega-prep: Tb | FTb | g2b | nfh | pad_yb | pad_g2b | wsh | w2h0.
#define PS_TB    96
#define PS_FTB   88
#define PS_G2B   256
#define PS_NFH   12544
#define PS_PADY  7680
#define PS_PADG  14336
#define PS_WSH   128
#define PS_W2H   128
__global__ void __launch_bounds__(256) k_prep_static(
    const float* __restrict__ nf, const float* __restrict__ T,
    const float* __restrict__ F,  const float* __restrict__ g2,
    const float* __restrict__ ws, const float* __restrict__ w2) {
    int b = blockIdx.x;
    int t = threadIdx.x;
    if (b < PS_TB) {
        int idx = b * 256 + t;
        int p = idx >> 6, i = idx & 63;
        float v = (p < NP && i < NC) ? T[p * NC + i] : 0.0f;
        g_Tb[idx] = __float2half_rn(v);
        return;
    }
    b -= PS_TB;
    if (b < PS_FTB) {
        int idx = b * 256 + t;
        int i = idx / PBLK, p = idx % PBLK;
        float v = (i < NC && p < NP) ? F[p * NC + i] : 0.0f;
        g_FTb[idx] = __float2half_rn(v);
        return;
    }
    b -= PS_FTB;
    if (b < PS_G2B) {
        int idx = b * 256 + t;
        int n = idx >> 8, k = idx & 255;
        g_g2b[idx] = __float2half_rn(g2[(size_t)k * HID + n]);
        return;
    }
    b -= PS_G2B;
    if (b < PS_NFH) {
        size_t gi = ((size_t)b * 256 + t) * 2;
        float2 v = *(const float2*)(nf + gi);
        *(uint32_t*)&g_nfh[gi] = pkh2(v.x, v.y);
        return;
    }
    b -= PS_NFH;
    if (b < PS_PADY) {
        size_t w = (size_t)b * 256 + t;
        int node = (int)(w / 1920);
        int rem  = (int)(w % 1920);
        int row  = NC + rem / 128;
        int c2   = rem & 127;
        *(uint32_t*)&g_yb[((size_t)node * 64 + row) * HID + c2 * 2] = 0;
        return;
    }
    b -= PS_PADY;
    if (b < PS_PADG) {
        size_t w = (size_t)b * 256 + t;
        int node = (int)(w / 3584);
        int rem  = (int)(w % 3584);
        int row  = NP + rem / 128;
        int c2   = rem & 127;
        *(uint32_t*)&g_grid2b[((size_t)node * PBLK + row) * HID + c2 * 2] = 0;
        return;
    }
    b -= PS_PADG;
    if (b < PS_WSH) {
        int idx = b * 256 + t;
        int n = idx >> 7, k = idx & 127;
        g_wsh[idx] = __float2half_rn(ws[(size_t)k * HID + n]);
        return;
    }
    b -= PS_WSH;
    {
        int idx = b * 256 + t;
        int n = idx >> 8, k = idx & 255;
        g_w2h0[idx] = __float2half_rn(w2[(size_t)k * CIN + n]);
    }
}

// ---------------------------- main stage kernels ----------------------------
// Common 512-thread shape: BM=128, warp tile 64x32 over N=256 (wn 0..7).

// ---- y (blockIdx.y < NC) or gate (blockIdx.y == NC): K=128, 4 resident -----
__global__ void __launch_bounds__(512, 1) k_y_mma(const float* __restrict__ bs) {
    extern __shared__ __align__(128) char smem[];
    const uint32_t sbase = smem_u32(smem);
    const int tid = threadIdx.x;
    const int wid = tid >> 5;
    const int lid = tid & 31;
    const int wm  = wid & 1;
    const int wn  = wid >> 1;
    const bool is_gate = (blockIdx.y == NC);
    const int i   = is_gate ? 0 : blockIdx.y;
    const int l   = deg_of(i);
    const int m0  = blockIdx.x * BM;

    const uint32_t STAGE = BM * 64 + BN * 64;    // 24576
    const uint32_t BOFF  = BM * 64;

    uint32_t a_addr[4][2], b_addr[2][2];
#pragma unroll
    for (int mt = 0; mt < 4; mt++)
#pragma unroll
        for (int ks = 0; ks < 2; ks++) {
            int row = wm * 64 + mt * 16 + (lid & 7) + ((lid >> 3) & 1) * 8;
            int ch  = ks * 2 + (lid >> 4);
            a_addr[mt][ks] = sbase + row * 64 + 16 * (ch ^ ((row >> 1) & 3));
        }
#pragma unroll
    for (int np = 0; np < 2; np++)
#pragma unroll
        for (int ks = 0; ks < 2; ks++) {
            int row = wn * 32 + np * 16 + (lid & 7) + (lid >> 4) * 8;
            int ch  = ks * 2 + ((lid >> 3) & 1);
            b_addr[np][ks] = sbase + BOFF + row * 64 + 16 * (ch ^ ((row >> 1) & 3));
        }

    uint32_t a_rel, b_rel[2];
    const __half* a_basep;
    const __half* b_base[2];
    {
        int r = tid >> 2, c = tid & 3;
        a_rel = sbase + r * 64 + 16 * (c ^ ((r >> 1) & 3));
        a_basep = g_nfh + ((size_t)(m0 + r) * NC + i) * CIN + c * 8;
    }
#pragma unroll
    for (int j = 0; j < 2; j++) {
        int id = tid + j * 512, r = id >> 2, c = id & 3;
        b_rel[j] = sbase + BOFF + r * 64 + 16 * (c ^ ((r >> 1) & 3));
        b_base[j] = (is_gate ? g_wsh + (size_t)r * 128
                             : g_w1g1h + ((size_t)l * HID + r) * 128) + c * 8;
    }

#pragma unroll
    for (int s = 0; s < 4; s++) {
        uint32_t so = s * STAGE;
        cp_async16(a_rel + so, a_basep + s * 32);
#pragma unroll
        for (int j = 0; j < 2; j++) cp_async16(b_rel[j] + so, b_base[j] + s * 32);
        asm volatile("cp.async.commit_group;");
    }

    float acc[4][4][4];
#pragma unroll
    for (int mt = 0; mt < 4; mt++)
#pragma unroll
        for (int nt = 0; nt < 4; nt++)
#pragma unroll
            for (int v = 0; v < 4; v++) acc[mt][nt][v] = 0.0f;

    auto compute = [&](int kc) {
        const uint32_t so = kc * STAGE;
#pragma unroll
        for (int ks = 0; ks < 2; ks++) {
            uint32_t af[4][4], bf[4][2];
#pragma unroll
            for (int mt = 0; mt < 4; mt++)
                ldsm_x4(af[mt][0], af[mt][1], af[mt][2], af[mt][3],
                        a_addr[mt][ks] + so);
#pragma unroll
            for (int np = 0; np < 2; np++)
                ldsm_x4(bf[2 * np][0], bf[2 * np][1], bf[2 * np + 1][0],
                        bf[2 * np + 1][1], b_addr[np][ks] + so);
#pragma unroll
            for (int mt = 0; mt < 4; mt++)
#pragma unroll
                for (int nt = 0; nt < 4; nt++)
                    mma_f16(acc[mt][nt], af[mt], bf[nt]);
        }
    };

    waitg<2>(); __syncthreads();
    compute(0); compute(1);
    waitg<0>(); __syncthreads();
    compute(2); compute(3);

    const int tq = lid >> 2;
    const int tr = lid & 3;
#pragma unroll
    for (int mt = 0; mt < 4; mt++) {
#pragma unroll
        for (int half = 0; half < 2; half++) {
            int node = m0 + wm * 64 + mt * 16 + tq + half * 8;
#pragma unroll
            for (int nt = 0; nt < 4; nt++) {
                int col = wn * 32 + nt * 8 + tr * 2;
                float v0 = acc[mt][nt][half * 2 + 0];
                float v1 = acc[mt][nt][half * 2 + 1];
                if (is_gate) {
                    v0 = silu_f(v0 + bs[col]);
                    v1 = silu_f(v1 + bs[col + 1]);
                    *(uint32_t*)&g_gateh[(size_t)node * HID + col] = pkh2(v0, v1);
                } else {
                    if (i == 0) { v0 += g_b1g1[col]; v1 += g_b1g1[col + 1]; }
                    *(uint32_t*)&g_yb[((size_t)node * 64 + i) * HID + col] = pkh2(v0, v1);
                }
            }
        }
    }
}

// -------- grid1 = silu(T @ y[n]) : K=64, 2 resident chunks, trans-B ---------
__global__ void __launch_bounds__(512, 1) k_grid1_mma() {
    extern __shared__ __align__(128) char smem[];
    const uint32_t sbase = smem_u32(smem);
    const int tid = threadIdx.x;
    const int wid = tid >> 5;
    const int lid = tid & 31;
    const int wm  = wid & 1;
    const int wn  = wid >> 1;
    const int node = blockIdx.y;
    const int m0 = blockIdx.x * BM;

    const uint32_t STAGE = BM * 64 + BK * 512;   // 24576
    const uint32_t BOFF  = BM * 64;

    uint32_t a_addr[4][2], b_addr[2][2];
#pragma unroll
    for (int mt = 0; mt < 4; mt++)
#pragma unroll
        for (int ks = 0; ks < 2; ks++) {
            int row = wm * 64 + mt * 16 + (lid & 7) + ((lid >> 3) & 1) * 8;
            int ch  = ks * 2 + (lid >> 4);
            a_addr[mt][ks] = sbase + row * 64 + 16 * (ch ^ ((row >> 1) & 3));
        }
#pragma unroll
    for (int np = 0; np < 2; np++)
#pragma unroll
        for (int ks = 0; ks < 2; ks++) {
            int row = ks * 16 + (lid & 7) + 8 * ((lid >> 3) & 1);
            int cn  = wn * 4 + np * 2 + (lid >> 4);
            b_addr[np][ks] = sbase + BOFF + row * 512 + 16 * (cn ^ (row & 7));
        }

    uint32_t a_rel, b_rel[2];
    const __half* a_basep;
    const __half* b_base[2];
    const __half* ybn = g_yb + (size_t)node * (64 * HID);
    {
        int r = tid >> 2, c = tid & 3;
        a_rel = sbase + r * 64 + 16 * (c ^ ((r >> 1) & 3));
        a_basep = g_Tb + (m0 + r) * 64 + c * 8;
    }
#pragma unroll
    for (int j = 0; j < 2; j++) {
        int id = tid + j * 512, r = id >> 5, c = id & 31;
        b_rel[j] = sbase + BOFF + r * 512 + 16 * (c ^ (r & 7));
        b_base[j] = ybn + r * HID + c * 8;
    }

#pragma unroll
    for (int s = 0; s < 2; s++) {
        uint32_t so = s * STAGE;
        cp_async16(a_rel + so, a_basep + s * 32);
#pragma unroll
        for (int j = 0; j < 2; j++) cp_async16(b_rel[j] + so, b_base[j] + s * 32 * HID);
        asm volatile("cp.async.commit_group;");
    }

    float acc[4][4][4];
#pragma unroll
    for (int mt = 0; mt < 4; mt++)
#pragma unroll
        for (int nt = 0; nt < 4; nt++)
#pragma unroll
            for (int v = 0; v < 4; v++) acc[mt][nt][v] = 0.0f;

    auto compute = [&](int kc) {
        const uint32_t so = kc * STAGE;
#pragma unroll
        for (int ks = 0; ks < 2; ks++) {
            uint32_t af[4][4], bf[4][2];
#pragma unroll
            for (int mt = 0; mt < 4; mt++)
                ldsm_x4(af[mt][0], af[mt][1], af[mt][2], af[mt][3],
                        a_addr[mt][ks] + so);
#pragma unroll
            for (int np = 0; np < 2; np++)
                ldsm_x4_t(bf[2 * np][0], bf[2 * np][1], bf[2 * np + 1][0],
                          bf[2 * np + 1][1], b_addr[np][ks] + so);
#pragma unroll
            for (int mt = 0; mt < 4; mt++)
#pragma unroll
                for (int nt = 0; nt < 4; nt++)
                    mma_f16(acc[mt][nt], af[mt], bf[nt]);
        }
    };

    waitg<1>(); __syncthreads();
    compute(0);
    waitg<0>(); __syncthreads();
    compute(1);

    const int tq = lid >> 2;
    const int tr = lid & 3;
#pragma unroll
    for (int mt = 0; mt < 4; mt++) {
#pragma unroll
        for (int half = 0; half < 2; half++) {
            int p = m0 + wm * 64 + mt * 16 + tq + half * 8;
            if (p >= NP) continue;
            __half* row = g_grid1b + ((size_t)node * NP + p) * HID;
#pragma unroll
            for (int nt = 0; nt < 4; nt++) {
                int col = wn * 32 + nt * 8 + tr * 2;
                *(uint32_t*)&row[col] = pkh2(silu_f(acc[mt][nt][half * 2 + 0]),
                                             silu_f(acc[mt][nt][half * 2 + 1]));
            }
        }
    }
}

// -------- grid2 = silu(grid1 @ g2): K=256, 8 resident chunks (192KB) --------
__global__ void __launch_bounds__(512, 1) k_grid2_mma() {
    extern __shared__ __align__(128) char smem[];
    const uint32_t sbase = smem_u32(smem);
    const int tid = threadIdx.x;
    const int wid = tid >> 5;
    const int lid = tid & 31;
    const int wm  = wid & 1;
    const int wn  = wid >> 1;
    const size_t m0 = (size_t)blockIdx.x * BM;

    const uint32_t STAGE = BM * 64 + BN * 64;    // 24576
    const uint32_t BOFF  = BM * 64;

    uint32_t a_addr[4][2], b_addr[2][2];
#pragma unroll
    for (int mt = 0; mt < 4; mt++)
#pragma unroll
        for (int ks = 0; ks < 2; ks++) {
            int row = wm * 64 + mt * 16 + (lid & 7) + ((lid >> 3) & 1) * 8;
            int ch  = ks * 2 + (lid >> 4);
            a_addr[mt][ks] = sbase + row * 64 + 16 * (ch ^ ((row >> 1) & 3));
        }
#pragma unroll
    for (int np = 0; np < 2; np++)
#pragma unroll
        for (int ks = 0; ks < 2; ks++) {
            int row = wn * 32 + np * 16 + (lid & 7) + (lid >> 4) * 8;
            int ch  = ks * 2 + ((lid >> 3) & 1);
            b_addr[np][ks] = sbase + BOFF + row * 64 + 16 * (ch ^ ((row >> 1) & 3));
        }

    uint32_t a_rel, b_rel[2];
    const __half* a_basep;
    const __half* b_base[2];
    {
        int r = tid >> 2, c = tid & 3;
        a_rel = sbase + r * 64 + 16 * (c ^ ((r >> 1) & 3));
        a_basep = g_grid1b + (m0 + r) * (size_t)HID + c * 8;
    }
#pragma unroll
    for (int j = 0; j < 2; j++) {
        int id = tid + j * 512, r = id >> 2, c = id & 3;
        b_rel[j] = sbase + BOFF + r * 64 + 16 * (c ^ ((r >> 1) & 3));
        b_base[j] = g_g2b + r * (size_t)256 + c * 8;
    }

#pragma unroll
    for (int s = 0; s < 8; s++) {
        uint32_t so = s * STAGE;
        cp_async16(a_rel + so, a_basep + s * 32);
#pragma unroll
        for (int j = 0; j < 2; j++) cp_async16(b_rel[j] + so, b_base[j] + s * 32);
        asm volatile("cp.async.commit_group;");
    }

    float acc[4][4][4];
#pragma unroll
    for (int mt = 0; mt < 4; mt++)
#pragma unroll
        for (int nt = 0; nt < 4; nt++)
#pragma unroll
            for (int v = 0; v < 4; v++) acc[mt][nt][v] = 0.0f;

    auto compute = [&](int kc) {
        const uint32_t so = kc * STAGE;
#pragma unroll
        for (int ks = 0; ks < 2; ks++) {
            uint32_t af[4][4], bf[4][2];
#pragma unroll
            for (int mt = 0; mt < 4; mt++)
                ldsm_x4(af[mt][0], af[mt][1], af[mt][2], af[mt][3],
                        a_addr[mt][ks] + so);
#pragma unroll
            for (int np = 0; np < 2; np++)
                ldsm_x4(bf[2 * np][0], bf[2 * np][1], bf[2 * np + 1][0],
                        bf[2 * np + 1][1], b_addr[np][ks] + so);
#pragma unroll
            for (int mt = 0; mt < 4; mt++)
#pragma unroll
                for (int nt = 0; nt < 4; nt++)
                    mma_f16(acc[mt][nt], af[mt], bf[nt]);
        }
    };

    waitg<4>(); __syncthreads();
    compute(0); compute(1); compute(2); compute(3);
    waitg<0>(); __syncthreads();
    compute(4); compute(5); compute(6); compute(7);

    const int tq = lid >> 2;
    const int tr = lid & 3;
#pragma unroll
    for (int mt = 0; mt < 4; mt++) {
#pragma unroll
        for (int half = 0; half < 2; half++) {
            size_t r = m0 + wm * 64 + mt * 16 + tq + half * 8;
            uint32_t n = (uint32_t)(r / NP);
            uint32_t p = (uint32_t)(r - (size_t)n * NP);
            __half* row = g_grid2b + ((size_t)n * PBLK + p) * HID;
#pragma unroll
            for (int nt = 0; nt < 4; nt++) {
                int col = wn * 32 + nt * 8 + tr * 2;
                *(uint32_t*)&row[col] = pkh2(silu_f(acc[mt][nt][half * 2 + 0]),
                                             silu_f(acc[mt][nt][half * 2 + 1]));
            }
        }
    }
}

// -------- z = F^T @ grid2[n] : K=352, 11 resident chunks (225KB) ------------
__global__ void __launch_bounds__(512, 1) k_z_mma() {
    extern __shared__ __align__(128) char smem[];
    const uint32_t sbase = smem_u32(smem);
    const int tid = threadIdx.x;
    const int wid = tid >> 5;           // 0..15, 16 cols each
    const int lid = tid & 31;
    const int node = blockIdx.x;

    const uint32_t STAGE = 64 * 64 + BK * 512;   // 20480; x11 = 225280
    const uint32_t BOFF  = 64 * 64;

    uint32_t a_addr[4][2], b_addr[2];
#pragma unroll
    for (int mt = 0; mt < 4; mt++)
#pragma unroll
        for (int ks = 0; ks < 2; ks++) {
            int row = mt * 16 + (lid & 7) + ((lid >> 3) & 1) * 8;
            int ch  = ks * 2 + (lid >> 4);
            a_addr[mt][ks] = sbase + row * 64 + 16 * (ch ^ ((row >> 1) & 3));
        }
#pragma unroll
    for (int ks = 0; ks < 2; ks++) {
        int row = ks * 16 + (lid & 7) + 8 * ((lid >> 3) & 1);
        int cn  = wid * 2 + (lid >> 4);
        b_addr[ks] = sbase + BOFF + row * 512 + 16 * (cn ^ (row & 7));
    }

    uint32_t a_rel = 0, b_rel[2];
    const __half* a_basep = nullptr;
    const __half* b_base[2];
    const __half* g2bn = g_grid2b + (size_t)node * (PBLK * HID);
    if (tid < 256) {
        int r = tid >> 2, c = tid & 3;
        a_rel = sbase + r * 64 + 16 * (c ^ ((r >> 1) & 3));
        a_basep = g_FTb + r * PBLK + c * 8;
    }
#pragma unroll
    for (int j = 0; j < 2; j++) {
        int id = tid + j * 512, r = id >> 5, c = id & 31;
        b_rel[j] = sbase + BOFF + r * 512 + 16 * (c ^ (r & 7));
        b_base[j] = g2bn + r * HID + c * 8;
    }

    // issue all 11 chunks
#pragma unroll
    for (int s = 0; s < 11; s++) {
        uint32_t so = s * STAGE;
        if (tid < 256) cp_async16(a_rel + so, a_basep + s * 32);
#pragma unroll
        for (int j = 0; j < 2; j++) cp_async16(b_rel[j] + so, b_base[j] + s * 32 * HID);
        asm volatile("cp.async.commit_group;");
    }

    float acc[4][2][4];
#pragma unroll
    for (int mt = 0; mt < 4; mt++)
#pragma unroll
        for (int nt = 0; nt < 2; nt++)
#pragma unroll
            for (int v = 0; v < 4; v++) acc[mt][nt][v] = 0.0f;

    auto compute = [&](int kc) {
        const uint32_t so = kc * STAGE;
#pragma unroll
        for (int ks = 0; ks < 2; ks++) {
            uint32_t af[4][4], bf[2][2];
#pragma unroll
            for (int mt = 0; mt < 4; mt++)
                ldsm_x4(af[mt][0], af[mt][1], af[mt][2], af[mt][3],
                        a_addr[mt][ks] + so);
            ldsm_x4_t(bf[0][0], bf[0][1], bf[1][0], bf[1][1], b_addr[ks] + so);
#pragma unroll
            for (int mt = 0; mt < 4; mt++)
#pragma unroll
                for (int nt = 0; nt < 2; nt++)
                    mma_f16(acc[mt][nt], af[mt], bf[nt]);
        }
    };

    waitg<6>(); __syncthreads();
    compute(0); compute(1); compute(2); compute(3); compute(4);
    waitg<0>(); __syncthreads();
    compute(5); compute(6); compute(7); compute(8); compute(9); compute(10);

    const int tq = lid >> 2;
    const int tr = lid & 3;
#pragma unroll
    for (int mt = 0; mt < 4; mt++) {
#pragma unroll
        for (int half = 0; half < 2; half++) {
            int i = mt * 16 + tq + half * 8;
            if (i >= NC) continue;
            __half* row = g_zh + ((size_t)node * NC + i) * HID;
#pragma unroll
            for (int nt = 0; nt < 2; nt++) {
                int col = wid * 16 + nt * 8 + tr * 2;
                *(uint32_t*)&row[col] = pkh2(acc[mt][nt][half * 2 + 0],
                                             acc[mt][nt][half * 2 + 1]);
            }
        }
    }
}

// ---- out[:,i,:] : K=256, 8 resident chunks (128KB), 256 thr ----------------
__global__ void __launch_bounds__(256, 1) k_out_mma(const float* __restrict__ b2,
                                                    float* __restrict__ out) {
    extern __shared__ __align__(128) char smem[];
    const uint32_t sbase = smem_u32(smem);
    const int tid = threadIdx.x;
    const int wid = tid >> 5;
    const int lid = tid & 31;
    const int wm  = wid & 1;
    const int wn  = wid >> 1;
    const int i   = blockIdx.y;
    const int m0  = blockIdx.x * BM;

    const uint32_t STAGE = BM * 64 + CIN * 64;   // 16384
    const uint32_t BOFF  = BM * 64;

    uint32_t a_addr[4][2], b_addr[2][2];
#pragma unroll
    for (int mt = 0; mt < 4; mt++)
#pragma unroll
        for (int ks = 0; ks < 2; ks++) {
            int row = wm * 64 + mt * 16 + (lid & 7) + ((lid >> 3) & 1) * 8;
            int ch  = ks * 2 + (lid >> 4);
            a_addr[mt][ks] = sbase + row * 64 + 16 * (ch ^ ((row >> 1) & 3));
        }
#pragma unroll
    for (int np = 0; np < 2; np++)
#pragma unroll
        for (int ks = 0; ks < 2; ks++) {
            int row = wn * 32 + np * 16 + (lid & 7) + (lid >> 4) * 8;
            int ch  = ks * 2 + ((lid >> 3) & 1);
            b_addr[np][ks] = sbase + BOFF + row * 64 + 16 * (ch ^ ((row >> 1) & 3));
        }

    uint32_t a_rel[2], b_rel[2];
    const __half* a_base[2];
    const __half* b_base[2];
#pragma unroll
    for (int j = 0; j < 2; j++) {
        int id = tid + j * 256, r = id >> 2, c = id & 3;
        a_rel[j] = sbase + r * 64 + 16 * (c ^ ((r >> 1) & 3));
        b_rel[j] = sbase + BOFF + r * 64 + 16 * (c ^ ((r >> 1) & 3));
        if (i == 0) {
            a_base[j] = g_gateh + (size_t)(m0 + r) * HID + c * 8;
            b_base[j] = g_w2h0 + (size_t)r * 256 + c * 8;
        } else {
            int l = deg_of(i);
            a_base[j] = g_zh + ((size_t)(m0 + r) * NC + i) * HID + c * 8;
            b_base[j] = g_g3w2h + ((size_t)l * CIN + r) * 256 + c * 8;
        }
    }

#pragma unroll
    for (int s = 0; s < 8; s++) {
        uint32_t so = s * STAGE;
#pragma unroll
        for (int j = 0; j < 2; j++) {
            cp_async16(a_rel[j] + so, a_base[j] + s * 32);
            cp_async16(b_rel[j] + so, b_base[j] + s * 32);
        }
        asm volatile("cp.async.commit_group;");
    }

    float acc[4][4][4];
#pragma unroll
    for (int mt = 0; mt < 4; mt++)
#pragma unroll
        for (int nt = 0; nt < 4; nt++)
#pragma unroll
            for (int v = 0; v < 4; v++) acc[mt][nt][v] = 0.0f;

    auto compute = [&](int kc) {
        const uint32_t so = kc * STAGE;
#pragma unroll
        for (int ks = 0; ks < 2; ks++) {
            uint32_t af[4][4], bf[4][2];
#pragma unroll
            for (int mt = 0; mt < 4; mt++)
                ldsm_x4(af[mt][0], af[mt][1], af[mt][2], af[mt][3],
                        a_addr[mt][ks] + so);
#pragma unroll
            for (int np = 0; np < 2; np++)
                ldsm_x4(bf[2 * np][0], bf[2 * np][1], bf[2 * np + 1][0],
                        bf[2 * np + 1][1], b_addr[np][ks] + so);
#pragma unroll
            for (int mt = 0; mt < 4; mt++)
#pragma unroll
                for (int nt = 0; nt < 4; nt++)
                    mma_f16(acc[mt][nt], af[mt], bf[nt]);
        }
    };

    waitg<4>(); __syncthreads();
    compute(0); compute(1); compute(2); compute(3);
    waitg<0>(); __syncthreads();
    compute(4); compute(5); compute(6); compute(7);

    const int tq = lid >> 2;
    const int tr = lid & 3;
#pragma unroll
    for (int mt = 0; mt < 4; mt++) {
#pragma unroll
        for (int half = 0; half < 2; half++) {
            int node = m0 + wm * 64 + mt * 16 + tq + half * 8;
            float* row = out + ((size_t)node * NC + i) * CIN;
#pragma unroll
            for (int nt = 0; nt < 4; nt++) {
                int col = wn * 32 + nt * 8 + tr * 2;
                float2 v;
                v.x = acc[mt][nt][half * 2 + 0];
                v.y = acc[mt][nt][half * 2 + 1];
                if (i == 0) { v.x += b2[col]; v.y += b2[col + 1]; }
                *(float2*)&row[col] = v;
            }
        }
    }
}

// ---------------------------------------------------------------------------

extern "C" void kernel_launch(void* const* d_in, const int* in_sizes, int n_in,
                              void* d_out, int out_size) {
    const float* nf = (const float*)d_in[0];
    const float* w1 = (const float*)d_in[1];
    const float* b1 = (const float*)d_in[2];
    const float* w2 = (const float*)d_in[3];
    const float* b2 = (const float*)d_in[4];
    const float* ws = (const float*)d_in[5];
    const float* bs = (const float*)d_in[6];
    const float* g1 = (const float*)d_in[7];
    const float* g2 = (const float*)d_in[8];
    const float* g3 = (const float*)d_in[9];
    const float* Tg = (const float*)d_in[10];
    const float* Fg = (const float*)d_in[11];
    float* out = (float*)d_out;

    const int SMEM1 = 2 * 24576;    // 49152  (grid1)
    const int SMEM2 = 8 * 24576;    // 196608 (grid2)
    const int SMEMY = 4 * 24576;    // 98304  (y / gate)
    const int SMEMZ = 11 * 20480;   // 225280 (z, fully resident)
    const int SMEMO = 8 * 16384;    // 131072 (out)
    cudaFuncSetAttribute(k_grid1_mma, cudaFuncAttributeMaxDynamicSharedMemorySize, SMEM1);
    cudaFuncSetAttribute(k_grid2_mma, cudaFuncAttributeMaxDynamicSharedMemorySize, SMEM2);
    cudaFuncSetAttribute(k_z_mma,     cudaFuncAttributeMaxDynamicSharedMemorySize, SMEMZ);
    cudaFuncSetAttribute(k_y_mma,     cudaFuncAttributeMaxDynamicSharedMemorySize, SMEMY);
    cudaFuncSetAttribute(k_out_mma,   cudaFuncAttributeMaxDynamicSharedMemorySize, SMEMO);

    const int PS_BLOCKS = PS_TB + PS_FTB + PS_G2B + PS_NFH + PS_PADY + PS_PADG
                        + PS_WSH + PS_W2H;

    // prologs (3 launches)
    k_w1g1_h<<<dim3(HID / 64, CIN / 64, NL + 1), 256>>>(w1, g1, b1);
    k_g3w2_h<<<dim3(CIN / 64, HID / 64, NL), 256>>>(g3, w2);
    k_prep_static<<<PS_BLOCKS, 256>>>(nf, Tg, Fg, g2, ws, w2);

    // main pipeline (all MMA, 5 launches)
    k_y_mma<<<dim3(N_NODES / BM, NC + 1), 512, SMEMY>>>(bs);   // y + gate
    k_grid1_mma<<<dim3(3, N_NODES), 512, SMEM1>>>();
    k_grid2_mma<<<(int)(MROWS / BM), 512, SMEM2>>>();
    k_z_mma<<<N_NODES, 512, SMEMZ>>>();
    k_out_mma<<<dim3(N_NODES / BM, NC), 256, SMEMO>>>(b2, out);
}

// round 15
// speedup vs baseline: 1.4306x; 1.0267x over previous
#include <cuda_runtime.h>
#include <cuda_fp16.h>
#include <cstdint>

// ---------------------------------------------------------------------------
// FeedForwardNetwork (SO(3) equivariant FFN), sm_103a — all-MMA plain-fp16
// Round 15: grid2 rebuilt for 2 CTAs/SM (256 thr, BM=64, warp tile 32x64,
// 4-stage 80KB pipeline) so independent CTAs cover each other's stalls.
// All other stages identical to round 14.
// ---------------------------------------------------------------------------

#define N_NODES 1024
#define NC      49
#define CIN     128
#define HID     256
#define RES     18
#define NP      (RES*RES)   // 324
#define NL      7
#define MROWS   ((size_t)N_NODES * NP)   // 331776
#define PBLK    352
#define BM      128
#define BN      256
#define BK      32

// -------- scratch (static device globals; no runtime allocation) -----------
__device__ float g_b1g1[HID];
__device__ __half g_Tb[384 * 64];                    // to_grid hi [384x64]
__device__ __half g_FTb[64 * PBLK];                  // from_grid^T hi [64x352]
__device__ __half g_g2b[HID * 256];                  // g2^T hi [256x256]
__device__ __half g_w1g1h[NL * HID * 128];           // W1G1^T hi rows
__device__ __half g_g3w2h[NL * CIN * 256];           // (g3 w2)^T hi rows
__device__ __half g_wsh[HID * 128];                  // ws^T hi [256x128]
__device__ __half g_w2h0[CIN * 256];                 // w2[0]^T hi [128x256]
__device__ __half g_nfh[(size_t)N_NODES * NC * CIN];       // 12.8 MB
__device__ __half g_yb[(size_t)N_NODES * 64 * HID];        // 34 MB
__device__ __half g_grid1b[MROWS * HID];                   // 170 MB
__device__ __half g_grid2b[(size_t)N_NODES * PBLK * HID];  // 185 MB
__device__ __half g_zh[(size_t)N_NODES * NC * HID];        // 25.7 MB
__device__ __half g_gateh[(size_t)N_NODES * HID];          // fp16 gate

__device__ __forceinline__ float silu_f(float x) {
    return x / (1.0f + __expf(-x));
}
__device__ __forceinline__ int deg_of(int i) {
    int l = 0;
    while ((l + 1) * (l + 1) <= i) ++l;
    return l;
}
__device__ __forceinline__ uint32_t smem_u32(const void* p) {
    uint32_t a;
    asm("{ .reg .u64 t; cvta.to.shared.u64 t, %1; cvt.u32.u64 %0, t; }"
        : "=r"(a) : "l"(p));
    return a;
}
__device__ __forceinline__ void cp_async16(uint32_t dst, const void* src) {
    asm volatile("cp.async.cg.shared.global [%0], [%1], 16;" :: "r"(dst), "l"(src));
}
template<int N>
__device__ __forceinline__ void waitg() {
    asm volatile("cp.async.wait_group %0;" :: "n"(N));
}
__device__ __forceinline__ void ldsm_x4(uint32_t& r0, uint32_t& r1,
                                        uint32_t& r2, uint32_t& r3, uint32_t addr) {
    asm volatile("ldmatrix.sync.aligned.m8n8.x4.shared.b16 {%0,%1,%2,%3}, [%4];"
                 : "=r"(r0), "=r"(r1), "=r"(r2), "=r"(r3) : "r"(addr));
}
__device__ __forceinline__ void ldsm_x4_t(uint32_t& r0, uint32_t& r1,
                                          uint32_t& r2, uint32_t& r3, uint32_t addr) {
    asm volatile("ldmatrix.sync.aligned.m8n8.x4.trans.shared.b16 {%0,%1,%2,%3}, [%4];"
                 : "=r"(r0), "=r"(r1), "=r"(r2), "=r"(r3) : "r"(addr));
}
__device__ __forceinline__ void mma_f16(float* d, const uint32_t* a, const uint32_t* b) {
    asm volatile(
        "mma.sync.aligned.m16n8k16.row.col.f32.f16.f16.f32 "
        "{%0,%1,%2,%3}, {%4,%5,%6,%7}, {%8,%9}, {%0,%1,%2,%3};"
        : "+f"(d[0]), "+f"(d[1]), "+f"(d[2]), "+f"(d[3])
        : "r"(a[0]), "r"(a[1]), "r"(a[2]), "r"(a[3]), "r"(b[0]), "r"(b[1]));
}
__device__ __forceinline__ uint32_t pkh2(float x, float y) {
    __half hx = __float2half_rn(x), hy = __float2half_rn(y);
    uint16_t bx = *(uint16_t*)&hx, by = *(uint16_t*)&hy;
    return (uint32_t)bx | ((uint32_t)by << 16);
}

// ---------------------------------------------------------------------------
// SIMT gemm body with fp16-transposed epilogue (weight prep only).
// ---------------------------------------------------------------------------
__device__ __forceinline__ void gemm_tile_w16(
    const float* __restrict__ A, int lda,
    const float* __restrict__ B, int ldb,
    __half* __restrict__ OUT, int out_stride,
    int K)
{
    __shared__ float As[16][64];
    __shared__ float Bs[16][64];

    const int tid = threadIdx.x;
    const int tx  = tid & 15;
    const int ty  = tid >> 4;
    const int m0  = blockIdx.y * 64;
    const int n0  = blockIdx.x * 64;

    float acc[4][4];
#pragma unroll
    for (int i = 0; i < 4; i++)
#pragma unroll
        for (int j = 0; j < 4; j++) acc[i][j] = 0.0f;

    for (int k0 = 0; k0 < K; k0 += 16) {
#pragma unroll
        for (int e = tid; e < 64 * 16; e += 256) {
            int m = e >> 4, k = e & 15;
            As[k][m] = A[(size_t)(m0 + m) * lda + k0 + k];
        }
#pragma unroll
        for (int e = tid; e < 16 * 64; e += 256) {
            int k = e >> 6, n = e & 63;
            Bs[k][n] = B[(size_t)(k0 + k) * ldb + n0 + n];
        }
        __syncthreads();

#pragma unroll
        for (int k = 0; k < 16; k++) {
            float4 av = *(const float4*)&As[k][ty * 4];
            float4 bv = *(const float4*)&Bs[k][tx * 4];
            float a4[4] = {av.x, av.y, av.z, av.w};
            float b4[4] = {bv.x, bv.y, bv.z, bv.w};
#pragma unroll
            for (int i = 0; i < 4; i++)
#pragma unroll
                for (int j = 0; j < 4; j++)
                    acc[i][j] += a4[i] * b4[j];
        }
        __syncthreads();
    }

#pragma unroll
    for (int i = 0; i < 4; i++) {
        int gm = m0 + ty * 4 + i;
#pragma unroll
        for (int j = 0; j < 4; j++) {
            int gn = n0 + tx * 4 + j;
            OUT[(size_t)gn * out_stride + gm] = __float2half_rn(acc[i][j]);
        }
    }
}

// ---------------------------- prolog kernels --------------------------------

__global__ void __launch_bounds__(256) k_w1g1_h(const float* __restrict__ w1,
                                                const float* __restrict__ g1,
                                                const float* __restrict__ b1) {
    if (blockIdx.z == NL) {
        if (blockIdx.x != 0 || blockIdx.y != 0) return;
        int k = threadIdx.x;
        float s = 0.0f;
        for (int h = 0; h < HID; h++) s += b1[h] * g1[(size_t)h * HID + k];
        g_b1g1[k] = s;
        return;
    }
    int l = blockIdx.z;
    gemm_tile_w16(w1 + (size_t)l * CIN * HID, HID, g1, HID,
                  g_w1g1h + (size_t)l * HID * 128, 128, HID);
}

__global__ void __launch_bounds__(256) k_g3w2_h(const float* __restrict__ g3,
                                                const float* __restrict__ w2) {
    int l = blockIdx.z;
    gemm_tile_w16(g3, HID, w2 + (size_t)l * HID * CIN, CIN,
                  g_g3w2h + (size_t)l * CIN * 256, 256, HID);
}

// Mega-prep: Tb | FTb | g2b | nfh | pad_yb | pad_g2b | wsh | w2h0.
#define PS_TB    96
#define PS_FTB   88
#define PS_G2B   256
#define PS_NFH   12544
#define PS_PADY  7680
#define PS_PADG  14336
#define PS_WSH   128
#define PS_W2H   128
__global__ void __launch_bounds__(256) k_prep_static(
    const float* __restrict__ nf, const float* __restrict__ T,
    const float* __restrict__ F,  const float* __restrict__ g2,
    const float* __restrict__ ws, const float* __restrict__ w2) {
    int b = blockIdx.x;
    int t = threadIdx.x;
    if (b < PS_TB) {
        int idx = b * 256 + t;
        int p = idx >> 6, i = idx & 63;
        float v = (p < NP && i < NC) ? T[p * NC + i] : 0.0f;
        g_Tb[idx] = __float2half_rn(v);
        return;
    }
    b -= PS_TB;
    if (b < PS_FTB) {
        int idx = b * 256 + t;
        int i = idx / PBLK, p = idx % PBLK;
        float v = (i < NC && p < NP) ? F[p * NC + i] : 0.0f;
        g_FTb[idx] = __float2half_rn(v);
        return;
    }
    b -= PS_FTB;
    if (b < PS_G2B) {
        int idx = b * 256 + t;
        int n = idx >> 8, k = idx & 255;
        g_g2b[idx] = __float2half_rn(g2[(size_t)k * HID + n]);
        return;
    }
    b -= PS_G2B;
    if (b < PS_NFH) {
        size_t gi = ((size_t)b * 256 + t) * 2;
        float2 v = *(const float2*)(nf + gi);
        *(uint32_t*)&g_nfh[gi] = pkh2(v.x, v.y);
        return;
    }
    b -= PS_NFH;
    if (b < PS_PADY) {
        size_t w = (size_t)b * 256 + t;
        int node = (int)(w / 1920);
        int rem  = (int)(w % 1920);
        int row  = NC + rem / 128;
        int c2   = rem & 127;
        *(uint32_t*)&g_yb[((size_t)node * 64 + row) * HID + c2 * 2] = 0;
        return;
    }
    b -= PS_PADY;
    if (b < PS_PADG) {
        size_t w = (size_t)b * 256 + t;
        int node = (int)(w / 3584);
        int rem  = (int)(w % 3584);
        int row  = NP + rem / 128;
        int c2   = rem & 127;
        *(uint32_t*)&g_grid2b[((size_t)node * PBLK + row) * HID + c2 * 2] = 0;
        return;
    }
    b -= PS_PADG;
    if (b < PS_WSH) {
        int idx = b * 256 + t;
        int n = idx >> 7, k = idx & 127;
        g_wsh[idx] = __float2half_rn(ws[(size_t)k * HID + n]);
        return;
    }
    b -= PS_WSH;
    {
        int idx = b * 256 + t;
        int n = idx >> 8, k = idx & 255;
        g_w2h0[idx] = __float2half_rn(w2[(size_t)k * CIN + n]);
    }
}

// ---------------------------- main stage kernels ----------------------------

// ---- y (blockIdx.y < NC) or gate (blockIdx.y == NC): K=128, 4 resident -----
__global__ void __launch_bounds__(512, 1) k_y_mma(const float* __restrict__ bs) {
    extern __shared__ __align__(128) char smem[];
    const uint32_t sbase = smem_u32(smem);
    const int tid = threadIdx.x;
    const int wid = tid >> 5;
    const int lid = tid & 31;
    const int wm  = wid & 1;
    const int wn  = wid >> 1;
    const bool is_gate = (blockIdx.y == NC);
    const int i   = is_gate ? 0 : blockIdx.y;
    const int l   = deg_of(i);
    const int m0  = blockIdx.x * BM;

    const uint32_t STAGE = BM * 64 + BN * 64;    // 24576
    const uint32_t BOFF  = BM * 64;

    uint32_t a_addr[4][2], b_addr[2][2];
#pragma unroll
    for (int mt = 0; mt < 4; mt++)
#pragma unroll
        for (int ks = 0; ks < 2; ks++) {
            int row = wm * 64 + mt * 16 + (lid & 7) + ((lid >> 3) & 1) * 8;
            int ch  = ks * 2 + (lid >> 4);
            a_addr[mt][ks] = sbase + row * 64 + 16 * (ch ^ ((row >> 1) & 3));
        }
#pragma unroll
    for (int np = 0; np < 2; np++)
#pragma unroll
        for (int ks = 0; ks < 2; ks++) {
            int row = wn * 32 + np * 16 + (lid & 7) + (lid >> 4) * 8;
            int ch  = ks * 2 + ((lid >> 3) & 1);
            b_addr[np][ks] = sbase + BOFF + row * 64 + 16 * (ch ^ ((row >> 1) & 3));
        }

    uint32_t a_rel, b_rel[2];
    const __half* a_basep;
    const __half* b_base[2];
    {
        int r = tid >> 2, c = tid & 3;
        a_rel = sbase + r * 64 + 16 * (c ^ ((r >> 1) & 3));
        a_basep = g_nfh + ((size_t)(m0 + r) * NC + i) * CIN + c * 8;
    }
#pragma unroll
    for (int j = 0; j < 2; j++) {
        int id = tid + j * 512, r = id >> 2, c = id & 3;
        b_rel[j] = sbase + BOFF + r * 64 + 16 * (c ^ ((r >> 1) & 3));
        b_base[j] = (is_gate ? g_wsh + (size_t)r * 128
                             : g_w1g1h + ((size_t)l * HID + r) * 128) + c * 8;
    }

#pragma unroll
    for (int s = 0; s < 4; s++) {
        uint32_t so = s * STAGE;
        cp_async16(a_rel + so, a_basep + s * 32);
#pragma unroll
        for (int j = 0; j < 2; j++) cp_async16(b_rel[j] + so, b_base[j] + s * 32);
        asm volatile("cp.async.commit_group;");
    }

    float acc[4][4][4];
#pragma unroll
    for (int mt = 0; mt < 4; mt++)
#pragma unroll
        for (int nt = 0; nt < 4; nt++)
#pragma unroll
            for (int v = 0; v < 4; v++) acc[mt][nt][v] = 0.0f;

    auto compute = [&](int kc) {
        const uint32_t so = kc * STAGE;
#pragma unroll
        for (int ks = 0; ks < 2; ks++) {
            uint32_t af[4][4], bf[4][2];
#pragma unroll
            for (int mt = 0; mt < 4; mt++)
                ldsm_x4(af[mt][0], af[mt][1], af[mt][2], af[mt][3],
                        a_addr[mt][ks] + so);
#pragma unroll
            for (int np = 0; np < 2; np++)
                ldsm_x4(bf[2 * np][0], bf[2 * np][1], bf[2 * np + 1][0],
                        bf[2 * np + 1][1], b_addr[np][ks] + so);
#pragma unroll
            for (int mt = 0; mt < 4; mt++)
#pragma unroll
                for (int nt = 0; nt < 4; nt++)
                    mma_f16(acc[mt][nt], af[mt], bf[nt]);
        }
    };

    waitg<2>(); __syncthreads();
    compute(0); compute(1);
    waitg<0>(); __syncthreads();
    compute(2); compute(3);

    const int tq = lid >> 2;
    const int tr = lid & 3;
#pragma unroll
    for (int mt = 0; mt < 4; mt++) {
#pragma unroll
        for (int half = 0; half < 2; half++) {
            int node = m0 + wm * 64 + mt * 16 + tq + half * 8;
#pragma unroll
            for (int nt = 0; nt < 4; nt++) {
                int col = wn * 32 + nt * 8 + tr * 2;
                float v0 = acc[mt][nt][half * 2 + 0];
                float v1 = acc[mt][nt][half * 2 + 1];
                if (is_gate) {
                    v0 = silu_f(v0 + bs[col]);
                    v1 = silu_f(v1 + bs[col + 1]);
                    *(uint32_t*)&g_gateh[(size_t)node * HID + col] = pkh2(v0, v1);
                } else {
                    if (i == 0) { v0 += g_b1g1[col]; v1 += g_b1g1[col + 1]; }
                    *(uint32_t*)&g_yb[((size_t)node * 64 + i) * HID + col] = pkh2(v0, v1);
                }
            }
        }
    }
}

// -------- grid1 = silu(T @ y[n]) : K=64, 2 resident chunks, trans-B ---------
__global__ void __launch_bounds__(512, 1) k_grid1_mma() {
    extern __shared__ __align__(128) char smem[];
    const uint32_t sbase = smem_u32(smem);
    const int tid = threadIdx.x;
    const int wid = tid >> 5;
    const int lid = tid & 31;
    const int wm  = wid & 1;
    const int wn  = wid >> 1;
    const int node = blockIdx.y;
    const int m0 = blockIdx.x * BM;

    const uint32_t STAGE = BM * 64 + BK * 512;   // 24576
    const uint32_t BOFF  = BM * 64;

    uint32_t a_addr[4][2], b_addr[2][2];
#pragma unroll
    for (int mt = 0; mt < 4; mt++)
#pragma unroll
        for (int ks = 0; ks < 2; ks++) {
            int row = wm * 64 + mt * 16 + (lid & 7) + ((lid >> 3) & 1) * 8;
            int ch  = ks * 2 + (lid >> 4);
            a_addr[mt][ks] = sbase + row * 64 + 16 * (ch ^ ((row >> 1) & 3));
        }
#pragma unroll
    for (int np = 0; np < 2; np++)
#pragma unroll
        for (int ks = 0; ks < 2; ks++) {
            int row = ks * 16 + (lid & 7) + 8 * ((lid >> 3) & 1);
            int cn  = wn * 4 + np * 2 + (lid >> 4);
            b_addr[np][ks] = sbase + BOFF + row * 512 + 16 * (cn ^ (row & 7));
        }

    uint32_t a_rel, b_rel[2];
    const __half* a_basep;
    const __half* b_base[2];
    const __half* ybn = g_yb + (size_t)node * (64 * HID);
    {
        int r = tid >> 2, c = tid & 3;
        a_rel = sbase + r * 64 + 16 * (c ^ ((r >> 1) & 3));
        a_basep = g_Tb + (m0 + r) * 64 + c * 8;
    }
#pragma unroll
    for (int j = 0; j < 2; j++) {
        int id = tid + j * 512, r = id >> 5, c = id & 31;
        b_rel[j] = sbase + BOFF + r * 512 + 16 * (c ^ (r & 7));
        b_base[j] = ybn + r * HID + c * 8;
    }

#pragma unroll
    for (int s = 0; s < 2; s++) {
        uint32_t so = s * STAGE;
        cp_async16(a_rel + so, a_basep + s * 32);
#pragma unroll
        for (int j = 0; j < 2; j++) cp_async16(b_rel[j] + so, b_base[j] + s * 32 * HID);
        asm volatile("cp.async.commit_group;");
    }

    float acc[4][4][4];
#pragma unroll
    for (int mt = 0; mt < 4; mt++)
#pragma unroll
        for (int nt = 0; nt < 4; nt++)
#pragma unroll
            for (int v = 0; v < 4; v++) acc[mt][nt][v] = 0.0f;

    auto compute = [&](int kc) {
        const uint32_t so = kc * STAGE;
#pragma unroll
        for (int ks = 0; ks < 2; ks++) {
            uint32_t af[4][4], bf[4][2];
#pragma unroll
            for (int mt = 0; mt < 4; mt++)
                ldsm_x4(af[mt][0], af[mt][1], af[mt][2], af[mt][3],
                        a_addr[mt][ks] + so);
#pragma unroll
            for (int np = 0; np < 2; np++)
                ldsm_x4_t(bf[2 * np][0], bf[2 * np][1], bf[2 * np + 1][0],
                          bf[2 * np + 1][1], b_addr[np][ks] + so);
#pragma unroll
            for (int mt = 0; mt < 4; mt++)
#pragma unroll
                for (int nt = 0; nt < 4; nt++)
                    mma_f16(acc[mt][nt], af[mt], bf[nt]);
        }
    };

    waitg<1>(); __syncthreads();
    compute(0);
    waitg<0>(); __syncthreads();
    compute(1);

    const int tq = lid >> 2;
    const int tr = lid & 3;
#pragma unroll
    for (int mt = 0; mt < 4; mt++) {
#pragma unroll
        for (int half = 0; half < 2; half++) {
            int p = m0 + wm * 64 + mt * 16 + tq + half * 8;
            if (p >= NP) continue;
            __half* row = g_grid1b + ((size_t)node * NP + p) * HID;
#pragma unroll
            for (int nt = 0; nt < 4; nt++) {
                int col = wn * 32 + nt * 8 + tr * 2;
                *(uint32_t*)&row[col] = pkh2(silu_f(acc[mt][nt][half * 2 + 0]),
                                             silu_f(acc[mt][nt][half * 2 + 1]));
            }
        }
    }
}

// -------- grid2 = silu(grid1 @ g2): K=256, BM=64, 256 thr, 2 CTAs/SM --------
// 8 warps, warp tile 32x64. 4-stage rolling pipeline, 80KB smem/CTA.
__global__ void __launch_bounds__(256, 2) k_grid2_mma() {
    extern __shared__ __align__(128) char smem[];
    const uint32_t sbase = smem_u32(smem);
    const int tid = threadIdx.x;
    const int wid = tid >> 5;           // 0..7
    const int lid = tid & 31;
    const int wm  = wid & 1;            // 32-row half
    const int wn  = wid >> 1;           // 0..3, 64 cols each
    const size_t m0 = (size_t)blockIdx.x * 64;

    const uint32_t STAGE = 64 * 64 + BN * 64;    // 4096 + 16384 = 20480
    const uint32_t BOFF  = 64 * 64;              // 4096

    uint32_t a_addr[2][2], b_addr[4][2];
#pragma unroll
    for (int mt = 0; mt < 2; mt++)
#pragma unroll
        for (int ks = 0; ks < 2; ks++) {
            int row = wm * 32 + mt * 16 + (lid & 7) + ((lid >> 3) & 1) * 8;
            int ch  = ks * 2 + (lid >> 4);
            a_addr[mt][ks] = sbase + row * 64 + 16 * (ch ^ ((row >> 1) & 3));
        }
#pragma unroll
    for (int np = 0; np < 4; np++)
#pragma unroll
        for (int ks = 0; ks < 2; ks++) {
            int row = wn * 64 + np * 16 + (lid & 7) + (lid >> 4) * 8;
            int ch  = ks * 2 + ((lid >> 3) & 1);
            b_addr[np][ks] = sbase + BOFF + row * 64 + 16 * (ch ^ ((row >> 1) & 3));
        }

    uint32_t a_rel, b_rel[4];
    const __half* a_basep;
    const __half* b_base[4];
    {
        int r = tid >> 2, c = tid & 3;      // 256 loads cover 64 rows x 4 chunks
        a_rel = sbase + r * 64 + 16 * (c ^ ((r >> 1) & 3));
        a_basep = g_grid1b + (m0 + r) * (size_t)HID + c * 8;
    }
#pragma unroll
    for (int j = 0; j < 4; j++) {
        int id = tid + j * 256, r = id >> 2, c = id & 3;
        b_rel[j] = sbase + BOFF + r * 64 + 16 * (c ^ ((r >> 1) & 3));
        b_base[j] = g_g2b + r * (size_t)256 + c * 8;
    }

    // prefetch stages 0..2
#pragma unroll
    for (int s = 0; s < 3; s++) {
        uint32_t so = s * STAGE;
        cp_async16(a_rel + so, a_basep + s * 32);
#pragma unroll
        for (int j = 0; j < 4; j++) cp_async16(b_rel[j] + so, b_base[j] + s * 32);
        asm volatile("cp.async.commit_group;");
    }

    float acc[2][8][4];
#pragma unroll
    for (int mt = 0; mt < 2; mt++)
#pragma unroll
        for (int nt = 0; nt < 8; nt++)
#pragma unroll
            for (int v = 0; v < 4; v++) acc[mt][nt][v] = 0.0f;

#pragma unroll 1
    for (int kc = 0; kc < 8; kc++) {
        waitg<2>();
        __syncthreads();
        int pf = kc + 3;
        if (pf < 8) {
            uint32_t so = (pf & 3) * STAGE;
            cp_async16(a_rel + so, a_basep + pf * 32);
#pragma unroll
            for (int j = 0; j < 4; j++) cp_async16(b_rel[j] + so, b_base[j] + pf * 32);
        }
        asm volatile("cp.async.commit_group;");

        const uint32_t so = (kc & 3) * STAGE;
#pragma unroll
        for (int ks = 0; ks < 2; ks++) {
            uint32_t af[2][4], bf[8][2];
#pragma unroll
            for (int mt = 0; mt < 2; mt++)
                ldsm_x4(af[mt][0], af[mt][1], af[mt][2], af[mt][3],
                        a_addr[mt][ks] + so);
#pragma unroll
            for (int np = 0; np < 4; np++)
                ldsm_x4(bf[2 * np][0], bf[2 * np][1], bf[2 * np + 1][0],
                        bf[2 * np + 1][1], b_addr[np][ks] + so);
#pragma unroll
            for (int mt = 0; mt < 2; mt++)
#pragma unroll
                for (int nt = 0; nt < 8; nt++)
                    mma_f16(acc[mt][nt], af[mt], bf[nt]);
        }
    }

    const int tq = lid >> 2;
    const int tr = lid & 3;
#pragma unroll
    for (int mt = 0; mt < 2; mt++) {
#pragma unroll
        for (int half = 0; half < 2; half++) {
            size_t r = m0 + wm * 32 + mt * 16 + tq + half * 8;
            uint32_t n = (uint32_t)(r / NP);
            uint32_t p = (uint32_t)(r - (size_t)n * NP);
            __half* row = g_grid2b + ((size_t)n * PBLK + p) * HID;
#pragma unroll
            for (int nt = 0; nt < 8; nt++) {
                int col = wn * 64 + nt * 8 + tr * 2;
                *(uint32_t*)&row[col] = pkh2(silu_f(acc[mt][nt][half * 2 + 0]),
                                             silu_f(acc[mt][nt][half * 2 + 1]));
            }
        }
    }
}

// -------- z = F^T @ grid2[n] : K=352, 11 resident chunks (225KB) ------------
__global__ void __launch_bounds__(512, 1) k_z_mma() {
    extern __shared__ __align__(128) char smem[];
    const uint32_t sbase = smem_u32(smem);
    const int tid = threadIdx.x;
    const int wid = tid >> 5;           // 0..15, 16 cols each
    const int lid = tid & 31;
    const int node = blockIdx.x;

    const uint32_t STAGE = 64 * 64 + BK * 512;   // 20480; x11 = 225280
    const uint32_t BOFF  = 64 * 64;

    uint32_t a_addr[4][2], b_addr[2];
#pragma unroll
    for (int mt = 0; mt < 4; mt++)
#pragma unroll
        for (int ks = 0; ks < 2; ks++) {
            int row = mt * 16 + (lid & 7) + ((lid >> 3) & 1) * 8;
            int ch  = ks * 2 + (lid >> 4);
            a_addr[mt][ks] = sbase + row * 64 + 16 * (ch ^ ((row >> 1) & 3));
        }
#pragma unroll
    for (int ks = 0; ks < 2; ks++) {
        int row = ks * 16 + (lid & 7) + 8 * ((lid >> 3) & 1);
        int cn  = wid * 2 + (lid >> 4);
        b_addr[ks] = sbase + BOFF + row * 512 + 16 * (cn ^ (row & 7));
    }

    uint32_t a_rel = 0, b_rel[2];
    const __half* a_basep = nullptr;
    const __half* b_base[2];
    const __half* g2bn = g_grid2b + (size_t)node * (PBLK * HID);
    if (tid < 256) {
        int r = tid >> 2, c = tid & 3;
        a_rel = sbase + r * 64 + 16 * (c ^ ((r >> 1) & 3));
        a_basep = g_FTb + r * PBLK + c * 8;
    }
#pragma unroll
    for (int j = 0; j < 2; j++) {
        int id = tid + j * 512, r = id >> 5, c = id & 31;
        b_rel[j] = sbase + BOFF + r * 512 + 16 * (c ^ (r & 7));
        b_base[j] = g2bn + r * HID + c * 8;
    }

    // issue all 11 chunks
#pragma unroll
    for (int s = 0; s < 11; s++) {
        uint32_t so = s * STAGE;
        if (tid < 256) cp_async16(a_rel + so, a_basep + s * 32);
#pragma unroll
        for (int j = 0; j < 2; j++) cp_async16(b_rel[j] + so, b_base[j] + s * 32 * HID);
        asm volatile("cp.async.commit_group;");
    }

    float acc[4][2][4];
#pragma unroll
    for (int mt = 0; mt < 4; mt++)
#pragma unroll
        for (int nt = 0; nt < 2; nt++)
#pragma unroll
            for (int v = 0; v < 4; v++) acc[mt][nt][v] = 0.0f;

    auto compute = [&](int kc) {
        const uint32_t so = kc * STAGE;
#pragma unroll
        for (int ks = 0; ks < 2; ks++) {
            uint32_t af[4][4], bf[2][2];
#pragma unroll
            for (int mt = 0; mt < 4; mt++)
                ldsm_x4(af[mt][0], af[mt][1], af[mt][2], af[mt][3],
                        a_addr[mt][ks] + so);
            ldsm_x4_t(bf[0][0], bf[0][1], bf[1][0], bf[1][1], b_addr[ks] + so);
#pragma unroll
            for (int mt = 0; mt < 4; mt++)
#pragma unroll
                for (int nt = 0; nt < 2; nt++)
                    mma_f16(acc[mt][nt], af[mt], bf[nt]);
        }
    };

    waitg<6>(); __syncthreads();
    compute(0); compute(1); compute(2); compute(3); compute(4);
    waitg<0>(); __syncthreads();
    compute(5); compute(6); compute(7); compute(8); compute(9); compute(10);

    const int tq = lid >> 2;
    const int tr = lid & 3;
#pragma unroll
    for (int mt = 0; mt < 4; mt++) {
#pragma unroll
        for (int half = 0; half < 2; half++) {
            int i = mt * 16 + tq + half * 8;
            if (i >= NC) continue;
            __half* row = g_zh + ((size_t)node * NC + i) * HID;
#pragma unroll
            for (int nt = 0; nt < 2; nt++) {
                int col = wid * 16 + nt * 8 + tr * 2;
                *(uint32_t*)&row[col] = pkh2(acc[mt][nt][half * 2 + 0],
                                             acc[mt][nt][half * 2 + 1]);
            }
        }
    }
}

// ---- out[:,i,:] : K=256, 8 resident chunks (128KB), 256 thr ----------------
__global__ void __launch_bounds__(256, 1) k_out_mma(const float* __restrict__ b2,
                                                    float* __restrict__ out) {
    extern __shared__ __align__(128) char smem[];
    const uint32_t sbase = smem_u32(smem);
    const int tid = threadIdx.x;
    const int wid = tid >> 5;
    const int lid = tid & 31;
    const int wm  = wid & 1;
    const int wn  = wid >> 1;
    const int i   = blockIdx.y;
    const int m0  = blockIdx.x * BM;

    const uint32_t STAGE = BM * 64 + CIN * 64;   // 16384
    const uint32_t BOFF  = BM * 64;

    uint32_t a_addr[4][2], b_addr[2][2];
#pragma unroll
    for (int mt = 0; mt < 4; mt++)
#pragma unroll
        for (int ks = 0; ks < 2; ks++) {
            int row = wm * 64 + mt * 16 + (lid & 7) + ((lid >> 3) & 1) * 8;
            int ch  = ks * 2 + (lid >> 4);
            a_addr[mt][ks] = sbase + row * 64 + 16 * (ch ^ ((row >> 1) & 3));
        }
#pragma unroll
    for (int np = 0; np < 2; np++)
#pragma unroll
        for (int ks = 0; ks < 2; ks++) {
            int row = wn * 32 + np * 16 + (lid & 7) + (lid >> 4) * 8;
            int ch  = ks * 2 + ((lid >> 3) & 1);
            b_addr[np][ks] = sbase + BOFF + row * 64 + 16 * (ch ^ ((row >> 1) & 3));
        }

    uint32_t a_rel[2], b_rel[2];
    const __half* a_base[2];
    const __half* b_base[2];
#pragma unroll
    for (int j = 0; j < 2; j++) {
        int id = tid + j * 256, r = id >> 2, c = id & 3;
        a_rel[j] = sbase + r * 64 + 16 * (c ^ ((r >> 1) & 3));
        b_rel[j] = sbase + BOFF + r * 64 + 16 * (c ^ ((r >> 1) & 3));
        if (i == 0) {
            a_base[j] = g_gateh + (size_t)(m0 + r) * HID + c * 8;
            b_base[j] = g_w2h0 + (size_t)r * 256 + c * 8;
        } else {
            int l = deg_of(i);
            a_base[j] = g_zh + ((size_t)(m0 + r) * NC + i) * HID + c * 8;
            b_base[j] = g_g3w2h + ((size_t)l * CIN + r) * 256 + c * 8;
        }
    }

#pragma unroll
    for (int s = 0; s < 8; s++) {
        uint32_t so = s * STAGE;
#pragma unroll
        for (int j = 0; j < 2; j++) {
            cp_async16(a_rel[j] + so, a_base[j] + s * 32);
            cp_async16(b_rel[j] + so, b_base[j] + s * 32);
        }
        asm volatile("cp.async.commit_group;");
    }

    float acc[4][4][4];
#pragma unroll
    for (int mt = 0; mt < 4; mt++)
#pragma unroll
        for (int nt = 0; nt < 4; nt++)
#pragma unroll
            for (int v = 0; v < 4; v++) acc[mt][nt][v] = 0.0f;

    auto compute = [&](int kc) {
        const uint32_t so = kc * STAGE;
#pragma unroll
        for (int ks = 0; ks < 2; ks++) {
            uint32_t af[4][4], bf[4][2];
#pragma unroll
            for (int mt = 0; mt < 4; mt++)
                ldsm_x4(af[mt][0], af[mt][1], af[mt][2], af[mt][3],
                        a_addr[mt][ks] + so);
#pragma unroll
            for (int np = 0; np < 2; np++)
                ldsm_x4(bf[2 * np][0], bf[2 * np][1], bf[2 * np + 1][0],
                        bf[2 * np + 1][1], b_addr[np][ks] + so);
#pragma unroll
            for (int mt = 0; mt < 4; mt++)
#pragma unroll
                for (int nt = 0; nt < 4; nt++)
                    mma_f16(acc[mt][nt], af[mt], bf[nt]);
        }
    };

    waitg<4>(); __syncthreads();
    compute(0); compute(1); compute(2); compute(3);
    waitg<0>(); __syncthreads();
    compute(4); compute(5); compute(6); compute(7);

    const int tq = lid >> 2;
    const int tr = lid & 3;
#pragma unroll
    for (int mt = 0; mt < 4; mt++) {
#pragma unroll
        for (int half = 0; half < 2; half++) {
            int node = m0 + wm * 64 + mt * 16 + tq + half * 8;
            float* row = out + ((size_t)node * NC + i) * CIN;
#pragma unroll
            for (int nt = 0; nt < 4; nt++) {
                int col = wn * 32 + nt * 8 + tr * 2;
                float2 v;
                v.x = acc[mt][nt][half * 2 + 0];
                v.y = acc[mt][nt][half * 2 + 1];
                if (i == 0) { v.x += b2[col]; v.y += b2[col + 1]; }
                *(float2*)&row[col] = v;
            }
        }
    }
}

// ---------------------------------------------------------------------------

extern "C" void kernel_launch(void* const* d_in, const int* in_sizes, int n_in,
                              void* d_out, int out_size) {
    const float* nf = (const float*)d_in[0];
    const float* w1 = (const float*)d_in[1];
    const float* b1 = (const float*)d_in[2];
    const float* w2 = (const float*)d_in[3];
    const float* b2 = (const float*)d_in[4];
    const float* ws = (const float*)d_in[5];
    const float* bs = (const float*)d_in[6];
    const float* g1 = (const float*)d_in[7];
    const float* g2 = (const float*)d_in[8];
    const float* g3 = (const float*)d_in[9];
    const float* Tg = (const float*)d_in[10];
    const float* Fg = (const float*)d_in[11];
    float* out = (float*)d_out;

    const int SMEM1 = 2 * 24576;    // 49152  (grid1)
    const int SMEM2 = 4 * 20480;    // 81920  (grid2, 2 CTAs/SM)
    const int SMEMY = 4 * 24576;    // 98304  (y / gate)
    const int SMEMZ = 11 * 20480;   // 225280 (z, fully resident)
    const int SMEMO = 8 * 16384;    // 131072 (out)
    cudaFuncSetAttribute(k_grid1_mma, cudaFuncAttributeMaxDynamicSharedMemorySize, SMEM1);
    cudaFuncSetAttribute(k_grid2_mma, cudaFuncAttributeMaxDynamicSharedMemorySize, SMEM2);
    cudaFuncSetAttribute(k_z_mma,     cudaFuncAttributeMaxDynamicSharedMemorySize, SMEMZ);
    cudaFuncSetAttribute(k_y_mma,     cudaFuncAttributeMaxDynamicSharedMemorySize, SMEMY);
    cudaFuncSetAttribute(k_out_mma,   cudaFuncAttributeMaxDynamicSharedMemorySize, SMEMO);

    const int PS_BLOCKS = PS_TB + PS_FTB + PS_G2B + PS_NFH + PS_PADY + PS_PADG
                        + PS_WSH + PS_W2H;

    // prologs (3 launches)
    k_w1g1_h<<<dim3(HID / 64, CIN / 64, NL + 1), 256>>>(w1, g1, b1);
    k_g3w2_h<<<dim3(CIN / 64, HID / 64, NL), 256>>>(g3, w2);
    k_prep_static<<<PS_BLOCKS, 256>>>(nf, Tg, Fg, g2, ws, w2);

    // main pipeline (all MMA, 5 launches)
    k_y_mma<<<dim3(N_NODES / BM, NC + 1), 512, SMEMY>>>(bs);   // y + gate
    k_grid1_mma<<<dim3(3, N_NODES), 512, SMEM1>>>();
    k_grid2_mma<<<(int)(MROWS / 64), 256, SMEM2>>>();
    k_z_mma<<<N_NODES, 512, SMEMZ>>>();
    k_out_mma<<<dim3(N_NODES / BM, NC), 256, SMEMO>>>(b2, out);
}

// round 16
// speedup vs baseline: 1.5591x; 1.0898x over previous
#include <cuda_runtime.h>
#include <cuda_fp16.h>
#include <cstdint>

// ---------------------------------------------------------------------------
// FeedForwardNetwork (SO(3) equivariant FFN), sm_103a — all-MMA plain-fp16
// Round 16: every MMA stage runs 256 threads / BM=64 / 2 CTAs per SM
// (warp tile 32x64; smem <= 98KB/CTA) so independent CTAs cover each
// other's stall windows. K-accumulation order unchanged (bit-identical).
// ---------------------------------------------------------------------------

#define N_NODES 1024
#define NC      49
#define CIN     128
#define HID     256
#define RES     18
#define NP      (RES*RES)   // 324
#define NL      7
#define MROWS   ((size_t)N_NODES * NP)   // 331776
#define PBLK    352
#define BN      256
#define BK      32

// -------- scratch (static device globals; no runtime allocation) -----------
__device__ float g_b1g1[HID];
__device__ __half g_Tb[384 * 64];                    // to_grid hi [384x64]
__device__ __half g_FTb[64 * PBLK];                  // from_grid^T hi [64x352]
__device__ __half g_g2b[HID * 256];                  // g2^T hi [256x256]
__device__ __half g_w1g1h[NL * HID * 128];           // W1G1^T hi rows
__device__ __half g_g3w2h[NL * CIN * 256];           // (g3 w2)^T hi rows
__device__ __half g_wsh[HID * 128];                  // ws^T hi [256x128]
__device__ __half g_w2h0[CIN * 256];                 // w2[0]^T hi [128x256]
__device__ __half g_nfh[(size_t)N_NODES * NC * CIN];       // 12.8 MB
__device__ __half g_yb[(size_t)N_NODES * 64 * HID];        // 34 MB
__device__ __half g_grid1b[MROWS * HID];                   // 170 MB
__device__ __half g_grid2b[(size_t)N_NODES * PBLK * HID];  // 185 MB
__device__ __half g_zh[(size_t)N_NODES * NC * HID];        // 25.7 MB
__device__ __half g_gateh[(size_t)N_NODES * HID];          // fp16 gate

__device__ __forceinline__ float silu_f(float x) {
    return x / (1.0f + __expf(-x));
}
__device__ __forceinline__ int deg_of(int i) {
    int l = 0;
    while ((l + 1) * (l + 1) <= i) ++l;
    return l;
}
__device__ __forceinline__ uint32_t smem_u32(const void* p) {
    uint32_t a;
    asm("{ .reg .u64 t; cvta.to.shared.u64 t, %1; cvt.u32.u64 %0, t; }"
        : "=r"(a) : "l"(p));
    return a;
}
__device__ __forceinline__ void cp_async16(uint32_t dst, const void* src) {
    asm volatile("cp.async.cg.shared.global [%0], [%1], 16;" :: "r"(dst), "l"(src));
}
template<int N>
__device__ __forceinline__ void waitg() {
    asm volatile("cp.async.wait_group %0;" :: "n"(N));
}
__device__ __forceinline__ void ldsm_x4(uint32_t& r0, uint32_t& r1,
                                        uint32_t& r2, uint32_t& r3, uint32_t addr) {
    asm volatile("ldmatrix.sync.aligned.m8n8.x4.shared.b16 {%0,%1,%2,%3}, [%4];"
                 : "=r"(r0), "=r"(r1), "=r"(r2), "=r"(r3) : "r"(addr));
}
__device__ __forceinline__ void ldsm_x4_t(uint32_t& r0, uint32_t& r1,
                                          uint32_t& r2, uint32_t& r3, uint32_t addr) {
    asm volatile("ldmatrix.sync.aligned.m8n8.x4.trans.shared.b16 {%0,%1,%2,%3}, [%4];"
                 : "=r"(r0), "=r"(r1), "=r"(r2), "=r"(r3) : "r"(addr));
}
__device__ __forceinline__ void mma_f16(float* d, const uint32_t* a, const uint32_t* b) {
    asm volatile(
        "mma.sync.aligned.m16n8k16.row.col.f32.f16.f16.f32 "
        "{%0,%1,%2,%3}, {%4,%5,%6,%7}, {%8,%9}, {%0,%1,%2,%3};"
        : "+f"(d[0]), "+f"(d[1]), "+f"(d[2]), "+f"(d[3])
        : "r"(a[0]), "r"(a[1]), "r"(a[2]), "r"(a[3]), "r"(b[0]), "r"(b[1]));
}
__device__ __forceinline__ uint32_t pkh2(float x, float y) {
    __half hx = __float2half_rn(x), hy = __float2half_rn(y);
    uint16_t bx = *(uint16_t*)&hx, by = *(uint16_t*)&hy;
    return (uint32_t)bx | ((uint32_t)by << 16);
}

// ---------------------------------------------------------------------------
// SIMT gemm body with fp16-transposed epilogue (weight prep only).
// ---------------------------------------------------------------------------
__device__ __forceinline__ void gemm_tile_w16(
    const float* __restrict__ A, int lda,
    const float* __restrict__ B, int ldb,
    __half* __restrict__ OUT, int out_stride,
    int K)
{
    __shared__ float As[16][64];
    __shared__ float Bs[16][64];

    const int tid = threadIdx.x;
    const int tx  = tid & 15;
    const int ty  = tid >> 4;
    const int m0  = blockIdx.y * 64;
    const int n0  = blockIdx.x * 64;

    float acc[4][4];
#pragma unroll
    for (int i = 0; i < 4; i++)
#pragma unroll
        for (int j = 0; j < 4; j++) acc[i][j] = 0.0f;

    for (int k0 = 0; k0 < K; k0 += 16) {
#pragma unroll
        for (int e = tid; e < 64 * 16; e += 256) {
            int m = e >> 4, k = e & 15;
            As[k][m] = A[(size_t)(m0 + m) * lda + k0 + k];
        }
#pragma unroll
        for (int e = tid; e < 16 * 64; e += 256) {
            int k = e >> 6, n = e & 63;
            Bs[k][n] = B[(size_t)(k0 + k) * ldb + n0 + n];
        }
        __syncthreads();

#pragma unroll
        for (int k = 0; k < 16; k++) {
            float4 av = *(const float4*)&As[k][ty * 4];
            float4 bv = *(const float4*)&Bs[k][tx * 4];
            float a4[4] = {av.x, av.y, av.z, av.w};
            float b4[4] = {bv.x, bv.y, bv.z, bv.w};
#pragma unroll
            for (int i = 0; i < 4; i++)
#pragma unroll
                for (int j = 0; j < 4; j++)
                    acc[i][j] += a4[i] * b4[j];
        }
        __syncthreads();
    }

#pragma unroll
    for (int i = 0; i < 4; i++) {
        int gm = m0 + ty * 4 + i;
#pragma unroll
        for (int j = 0; j < 4; j++) {
            int gn = n0 + tx * 4 + j;
            OUT[(size_t)gn * out_stride + gm] = __float2half_rn(acc[i][j]);
        }
    }
}

// ---------------------------- prolog kernels --------------------------------

__global__ void __launch_bounds__(256) k_w1g1_h(const float* __restrict__ w1,
                                                const float* __restrict__ g1,
                                                const float* __restrict__ b1) {
    if (blockIdx.z == NL) {
        if (blockIdx.x != 0 || blockIdx.y != 0) return;
        int k = threadIdx.x;
        float s = 0.0f;
        for (int h = 0; h < HID; h++) s += b1[h] * g1[(size_t)h * HID + k];
        g_b1g1[k] = s;
        return;
    }
    int l = blockIdx.z;
    gemm_tile_w16(w1 + (size_t)l * CIN * HID, HID, g1, HID,
                  g_w1g1h + (size_t)l * HID * 128, 128, HID);
}

__global__ void __launch_bounds__(256) k_g3w2_h(const float* __restrict__ g3,
                                                const float* __restrict__ w2) {
    int l = blockIdx.z;
    gemm_tile_w16(g3, HID, w2 + (size_t)l * HID * CIN, CIN,
                  g_g3w2h + (size_t)l * CIN * 256, 256, HID);
}

// Mega-prep: Tb | FTb | g2b | nfh | pad_yb | pad_g2b | wsh | w2h0.
#define PS_TB    96
#define PS_FTB   88
#define PS_G2B   256
#define PS_NFH   12544
#define PS_PADY  7680
#define PS_PADG  14336
#define PS_WSH   128
#define PS_W2H   128
__global__ void __launch_bounds__(256) k_prep_static(
    const float* __restrict__ nf, const float* __restrict__ T,
    const float* __restrict__ F,  const float* __restrict__ g2,
    const float* __restrict__ ws, const float* __restrict__ w2) {
    int b = blockIdx.x;
    int t = threadIdx.x;
    if (b < PS_TB) {
        int idx = b * 256 + t;
        int p = idx >> 6, i = idx & 63;
        float v = (p < NP && i < NC) ? T[p * NC + i] : 0.0f;
        g_Tb[idx] = __float2half_rn(v);
        return;
    }
    b -= PS_TB;
    if (b < PS_FTB) {
        int idx = b * 256 + t;
        int i = idx / PBLK, p = idx % PBLK;
        float v = (i < NC && p < NP) ? F[p * NC + i] : 0.0f;
        g_FTb[idx] = __float2half_rn(v);
        return;
    }
    b -= PS_FTB;
    if (b < PS_G2B) {
        int idx = b * 256 + t;
        int n = idx >> 8, k = idx & 255;
        g_g2b[idx] = __float2half_rn(g2[(size_t)k * HID + n]);
        return;
    }
    b -= PS_G2B;
    if (b < PS_NFH) {
        size_t gi = ((size_t)b * 256 + t) * 2;
        float2 v = *(const float2*)(nf + gi);
        *(uint32_t*)&g_nfh[gi] = pkh2(v.x, v.y);
        return;
    }
    b -= PS_NFH;
    if (b < PS_PADY) {
        size_t w = (size_t)b * 256 + t;
        int node = (int)(w / 1920);
        int rem  = (int)(w % 1920);
        int row  = NC + rem / 128;
        int c2   = rem & 127;
        *(uint32_t*)&g_yb[((size_t)node * 64 + row) * HID + c2 * 2] = 0;
        return;
    }
    b -= PS_PADY;
    if (b < PS_PADG) {
        size_t w = (size_t)b * 256 + t;
        int node = (int)(w / 3584);
        int rem  = (int)(w % 3584);
        int row  = NP + rem / 128;
        int c2   = rem & 127;
        *(uint32_t*)&g_grid2b[((size_t)node * PBLK + row) * HID + c2 * 2] = 0;
        return;
    }
    b -= PS_PADG;
    if (b < PS_WSH) {
        int idx = b * 256 + t;
        int n = idx >> 7, k = idx & 127;
        g_wsh[idx] = __float2half_rn(ws[(size_t)k * HID + n]);
        return;
    }
    b -= PS_WSH;
    {
        int idx = b * 256 + t;
        int n = idx >> 8, k = idx & 255;
        g_w2h0[idx] = __float2half_rn(w2[(size_t)k * CIN + n]);
    }
}

// ---------------------------- main stage kernels ----------------------------
// Common 2-CTA shape: 256 thr, BM=64, 8 warps, warp tile 32x64 over N=256.
//   wm = wid & 1  (32-row half),  wn = wid >> 1  (0..3, 64 cols each)
// A chunk: 64 rows x 64B (4KB);  B chunk (K-major): 256 rows x 64B (16KB).

// ---- y (blockIdx.y < NC) or gate (== NC): K=128, 4 resident, 80KB ----------
__global__ void __launch_bounds__(256, 2) k_y_mma(const float* __restrict__ bs) {
    extern __shared__ __align__(128) char smem[];
    const uint32_t sbase = smem_u32(smem);
    const int tid = threadIdx.x;
    const int wid = tid >> 5;
    const int lid = tid & 31;
    const int wm  = wid & 1;
    const int wn  = wid >> 1;
    const bool is_gate = (blockIdx.y == NC);
    const int i   = is_gate ? 0 : blockIdx.y;
    const int l   = deg_of(i);
    const int m0  = blockIdx.x * 64;

    const uint32_t STAGE = 64 * 64 + BN * 64;    // 20480
    const uint32_t BOFF  = 64 * 64;              // 4096

    uint32_t a_addr[2][2], b_addr[4][2];
#pragma unroll
    for (int mt = 0; mt < 2; mt++)
#pragma unroll
        for (int ks = 0; ks < 2; ks++) {
            int row = wm * 32 + mt * 16 + (lid & 7) + ((lid >> 3) & 1) * 8;
            int ch  = ks * 2 + (lid >> 4);
            a_addr[mt][ks] = sbase + row * 64 + 16 * (ch ^ ((row >> 1) & 3));
        }
#pragma unroll
    for (int np = 0; np < 4; np++)
#pragma unroll
        for (int ks = 0; ks < 2; ks++) {
            int row = wn * 64 + np * 16 + (lid & 7) + (lid >> 4) * 8;
            int ch  = ks * 2 + ((lid >> 3) & 1);
            b_addr[np][ks] = sbase + BOFF + row * 64 + 16 * (ch ^ ((row >> 1) & 3));
        }

    uint32_t a_rel, b_rel[4];
    const __half* a_basep;
    const __half* b_base[4];
    {
        int r = tid >> 2, c = tid & 3;
        a_rel = sbase + r * 64 + 16 * (c ^ ((r >> 1) & 3));
        a_basep = g_nfh + ((size_t)(m0 + r) * NC + i) * CIN + c * 8;
    }
#pragma unroll
    for (int j = 0; j < 4; j++) {
        int id = tid + j * 256, r = id >> 2, c = id & 3;
        b_rel[j] = sbase + BOFF + r * 64 + 16 * (c ^ ((r >> 1) & 3));
        b_base[j] = (is_gate ? g_wsh + (size_t)r * 128
                             : g_w1g1h + ((size_t)l * HID + r) * 128) + c * 8;
    }

#pragma unroll
    for (int s = 0; s < 4; s++) {
        uint32_t so = s * STAGE;
        cp_async16(a_rel + so, a_basep + s * 32);
#pragma unroll
        for (int j = 0; j < 4; j++) cp_async16(b_rel[j] + so, b_base[j] + s * 32);
        asm volatile("cp.async.commit_group;");
    }

    float acc[2][8][4];
#pragma unroll
    for (int mt = 0; mt < 2; mt++)
#pragma unroll
        for (int nt = 0; nt < 8; nt++)
#pragma unroll
            for (int v = 0; v < 4; v++) acc[mt][nt][v] = 0.0f;

    auto compute = [&](int kc) {
        const uint32_t so = kc * STAGE;
#pragma unroll
        for (int ks = 0; ks < 2; ks++) {
            uint32_t af[2][4], bf[8][2];
#pragma unroll
            for (int mt = 0; mt < 2; mt++)
                ldsm_x4(af[mt][0], af[mt][1], af[mt][2], af[mt][3],
                        a_addr[mt][ks] + so);
#pragma unroll
            for (int np = 0; np < 4; np++)
                ldsm_x4(bf[2 * np][0], bf[2 * np][1], bf[2 * np + 1][0],
                        bf[2 * np + 1][1], b_addr[np][ks] + so);
#pragma unroll
            for (int mt = 0; mt < 2; mt++)
#pragma unroll
                for (int nt = 0; nt < 8; nt++)
                    mma_f16(acc[mt][nt], af[mt], bf[nt]);
        }
    };

    waitg<2>(); __syncthreads();
    compute(0); compute(1);
    waitg<0>(); __syncthreads();
    compute(2); compute(3);

    const int tq = lid >> 2;
    const int tr = lid & 3;
#pragma unroll
    for (int mt = 0; mt < 2; mt++) {
#pragma unroll
        for (int half = 0; half < 2; half++) {
            int node = m0 + wm * 32 + mt * 16 + tq + half * 8;
#pragma unroll
            for (int nt = 0; nt < 8; nt++) {
                int col = wn * 64 + nt * 8 + tr * 2;
                float v0 = acc[mt][nt][half * 2 + 0];
                float v1 = acc[mt][nt][half * 2 + 1];
                if (is_gate) {
                    v0 = silu_f(v0 + bs[col]);
                    v1 = silu_f(v1 + bs[col + 1]);
                    *(uint32_t*)&g_gateh[(size_t)node * HID + col] = pkh2(v0, v1);
                } else {
                    if (i == 0) { v0 += g_b1g1[col]; v1 += g_b1g1[col + 1]; }
                    *(uint32_t*)&g_yb[((size_t)node * 64 + i) * HID + col] = pkh2(v0, v1);
                }
            }
        }
    }
}

// -------- grid1 = silu(T @ y[n]) : K=64, 2 resident, trans-B, 40KB ----------
__global__ void __launch_bounds__(256, 2) k_grid1_mma() {
    extern __shared__ __align__(128) char smem[];
    const uint32_t sbase = smem_u32(smem);
    const int tid = threadIdx.x;
    const int wid = tid >> 5;
    const int lid = tid & 31;
    const int wm  = wid & 1;
    const int wn  = wid >> 1;
    const int node = blockIdx.y;
    const int m0 = blockIdx.x * 64;

    const uint32_t STAGE = 64 * 64 + BK * 512;   // 20480
    const uint32_t BOFF  = 64 * 64;

    uint32_t a_addr[2][2], b_addr[4][2];
#pragma unroll
    for (int mt = 0; mt < 2; mt++)
#pragma unroll
        for (int ks = 0; ks < 2; ks++) {
            int row = wm * 32 + mt * 16 + (lid & 7) + ((lid >> 3) & 1) * 8;
            int ch  = ks * 2 + (lid >> 4);
            a_addr[mt][ks] = sbase + row * 64 + 16 * (ch ^ ((row >> 1) & 3));
        }
#pragma unroll
    for (int np = 0; np < 4; np++)
#pragma unroll
        for (int ks = 0; ks < 2; ks++) {
            int row = ks * 16 + (lid & 7) + 8 * ((lid >> 3) & 1);
            int cn  = wn * 8 + np * 2 + (lid >> 4);
            b_addr[np][ks] = sbase + BOFF + row * 512 + 16 * (cn ^ (row & 7));
        }

    uint32_t a_rel, b_rel[4];
    const __half* a_basep;
    const __half* b_base[4];
    const __half* ybn = g_yb + (size_t)node * (64 * HID);
    {
        int r = tid >> 2, c = tid & 3;
        a_rel = sbase + r * 64 + 16 * (c ^ ((r >> 1) & 3));
        a_basep = g_Tb + (m0 + r) * 64 + c * 8;
    }
#pragma unroll
    for (int j = 0; j < 4; j++) {
        int id = tid + j * 256, r = id >> 5, c = id & 31;
        b_rel[j] = sbase + BOFF + r * 512 + 16 * (c ^ (r & 7));
        b_base[j] = ybn + r * HID + c * 8;
    }

#pragma unroll
    for (int s = 0; s < 2; s++) {
        uint32_t so = s * STAGE;
        cp_async16(a_rel + so, a_basep + s * 32);
#pragma unroll
        for (int j = 0; j < 4; j++) cp_async16(b_rel[j] + so, b_base[j] + s * 32 * HID);
        asm volatile("cp.async.commit_group;");
    }

    float acc[2][8][4];
#pragma unroll
    for (int mt = 0; mt < 2; mt++)
#pragma unroll
        for (int nt = 0; nt < 8; nt++)
#pragma unroll
            for (int v = 0; v < 4; v++) acc[mt][nt][v] = 0.0f;

    auto compute = [&](int kc) {
        const uint32_t so = kc * STAGE;
#pragma unroll
        for (int ks = 0; ks < 2; ks++) {
            uint32_t af[2][4], bf[8][2];
#pragma unroll
            for (int mt = 0; mt < 2; mt++)
                ldsm_x4(af[mt][0], af[mt][1], af[mt][2], af[mt][3],
                        a_addr[mt][ks] + so);
#pragma unroll
            for (int np = 0; np < 4; np++)
                ldsm_x4_t(bf[2 * np][0], bf[2 * np][1], bf[2 * np + 1][0],
                          bf[2 * np + 1][1], b_addr[np][ks] + so);
#pragma unroll
            for (int mt = 0; mt < 2; mt++)
#pragma unroll
                for (int nt = 0; nt < 8; nt++)
                    mma_f16(acc[mt][nt], af[mt], bf[nt]);
        }
    };

    waitg<1>(); __syncthreads();
    compute(0);
    waitg<0>(); __syncthreads();
    compute(1);

    const int tq = lid >> 2;
    const int tr = lid & 3;
#pragma unroll
    for (int mt = 0; mt < 2; mt++) {
#pragma unroll
        for (int half = 0; half < 2; half++) {
            int p = m0 + wm * 32 + mt * 16 + tq + half * 8;
            if (p >= NP) continue;
            __half* row = g_grid1b + ((size_t)node * NP + p) * HID;
#pragma unroll
            for (int nt = 0; nt < 8; nt++) {
                int col = wn * 64 + nt * 8 + tr * 2;
                *(uint32_t*)&row[col] = pkh2(silu_f(acc[mt][nt][half * 2 + 0]),
                                             silu_f(acc[mt][nt][half * 2 + 1]));
            }
        }
    }
}

// -------- grid2 = silu(grid1 @ g2): K=256, 4-stage rolling, 80KB ------------
__global__ void __launch_bounds__(256, 2) k_grid2_mma() {
    extern __shared__ __align__(128) char smem[];
    const uint32_t sbase = smem_u32(smem);
    const int tid = threadIdx.x;
    const int wid = tid >> 5;
    const int lid = tid & 31;
    const int wm  = wid & 1;
    const int wn  = wid >> 1;
    const size_t m0 = (size_t)blockIdx.x * 64;

    const uint32_t STAGE = 64 * 64 + BN * 64;    // 20480
    const uint32_t BOFF  = 64 * 64;

    uint32_t a_addr[2][2], b_addr[4][2];
#pragma unroll
    for (int mt = 0; mt < 2; mt++)
#pragma unroll
        for (int ks = 0; ks < 2; ks++) {
            int row = wm * 32 + mt * 16 + (lid & 7) + ((lid >> 3) & 1) * 8;
            int ch  = ks * 2 + (lid >> 4);
            a_addr[mt][ks] = sbase + row * 64 + 16 * (ch ^ ((row >> 1) & 3));
        }
#pragma unroll
    for (int np = 0; np < 4; np++)
#pragma unroll
        for (int ks = 0; ks < 2; ks++) {
            int row = wn * 64 + np * 16 + (lid & 7) + (lid >> 4) * 8;
            int ch  = ks * 2 + ((lid >> 3) & 1);
            b_addr[np][ks] = sbase + BOFF + row * 64 + 16 * (ch ^ ((row >> 1) & 3));
        }

    uint32_t a_rel, b_rel[4];
    const __half* a_basep;
    const __half* b_base[4];
    {
        int r = tid >> 2, c = tid & 3;
        a_rel = sbase + r * 64 + 16 * (c ^ ((r >> 1) & 3));
        a_basep = g_grid1b + (m0 + r) * (size_t)HID + c * 8;
    }
#pragma unroll
    for (int j = 0; j < 4; j++) {
        int id = tid + j * 256, r = id >> 2, c = id & 3;
        b_rel[j] = sbase + BOFF + r * 64 + 16 * (c ^ ((r >> 1) & 3));
        b_base[j] = g_g2b + r * (size_t)256 + c * 8;
    }

#pragma unroll
    for (int s = 0; s < 3; s++) {
        uint32_t so = s * STAGE;
        cp_async16(a_rel + so, a_basep + s * 32);
#pragma unroll
        for (int j = 0; j < 4; j++) cp_async16(b_rel[j] + so, b_base[j] + s * 32);
        asm volatile("cp.async.commit_group;");
    }

    float acc[2][8][4];
#pragma unroll
    for (int mt = 0; mt < 2; mt++)
#pragma unroll
        for (int nt = 0; nt < 8; nt++)
#pragma unroll
            for (int v = 0; v < 4; v++) acc[mt][nt][v] = 0.0f;

#pragma unroll 1
    for (int kc = 0; kc < 8; kc++) {
        waitg<2>();
        __syncthreads();
        int pf = kc + 3;
        if (pf < 8) {
            uint32_t so = (pf & 3) * STAGE;
            cp_async16(a_rel + so, a_basep + pf * 32);
#pragma unroll
            for (int j = 0; j < 4; j++) cp_async16(b_rel[j] + so, b_base[j] + pf * 32);
        }
        asm volatile("cp.async.commit_group;");

        const uint32_t so = (kc & 3) * STAGE;
#pragma unroll
        for (int ks = 0; ks < 2; ks++) {
            uint32_t af[2][4], bf[8][2];
#pragma unroll
            for (int mt = 0; mt < 2; mt++)
                ldsm_x4(af[mt][0], af[mt][1], af[mt][2], af[mt][3],
                        a_addr[mt][ks] + so);
#pragma unroll
            for (int np = 0; np < 4; np++)
                ldsm_x4(bf[2 * np][0], bf[2 * np][1], bf[2 * np + 1][0],
                        bf[2 * np + 1][1], b_addr[np][ks] + so);
#pragma unroll
            for (int mt = 0; mt < 2; mt++)
#pragma unroll
                for (int nt = 0; nt < 8; nt++)
                    mma_f16(acc[mt][nt], af[mt], bf[nt]);
        }
    }

    const int tq = lid >> 2;
    const int tr = lid & 3;
#pragma unroll
    for (int mt = 0; mt < 2; mt++) {
#pragma unroll
        for (int half = 0; half < 2; half++) {
            size_t r = m0 + wm * 32 + mt * 16 + tq + half * 8;
            uint32_t n = (uint32_t)(r / NP);
            uint32_t p = (uint32_t)(r - (size_t)n * NP);
            __half* row = g_grid2b + ((size_t)n * PBLK + p) * HID;
#pragma unroll
            for (int nt = 0; nt < 8; nt++) {
                int col = wn * 64 + nt * 8 + tr * 2;
                *(uint32_t*)&row[col] = pkh2(silu_f(acc[mt][nt][half * 2 + 0]),
                                             silu_f(acc[mt][nt][half * 2 + 1]));
            }
        }
    }
}

// -------- z = F^T @ grid2[n] : K=352, 4-stage rolling, trans-B, 80KB --------
__global__ void __launch_bounds__(256, 2) k_z_mma() {
    extern __shared__ __align__(128) char smem[];
    const uint32_t sbase = smem_u32(smem);
    const int tid = threadIdx.x;
    const int wid = tid >> 5;
    const int lid = tid & 31;
    const int wm  = wid & 1;
    const int wn  = wid >> 1;
    const int node = blockIdx.x;

    const uint32_t STAGE = 64 * 64 + BK * 512;   // 20480
    const uint32_t BOFF  = 64 * 64;

    uint32_t a_addr[2][2], b_addr[4][2];
#pragma unroll
    for (int mt = 0; mt < 2; mt++)
#pragma unroll
        for (int ks = 0; ks < 2; ks++) {
            int row = wm * 32 + mt * 16 + (lid & 7) + ((lid >> 3) & 1) * 8;
            int ch  = ks * 2 + (lid >> 4);
            a_addr[mt][ks] = sbase + row * 64 + 16 * (ch ^ ((row >> 1) & 3));
        }
#pragma unroll
    for (int np = 0; np < 4; np++)
#pragma unroll
        for (int ks = 0; ks < 2; ks++) {
            int row = ks * 16 + (lid & 7) + 8 * ((lid >> 3) & 1);
            int cn  = wn * 8 + np * 2 + (lid >> 4);
            b_addr[np][ks] = sbase + BOFF + row * 512 + 16 * (cn ^ (row & 7));
        }

    uint32_t a_rel, b_rel[4];
    const __half* a_basep;
    const __half* b_base[4];
    const __half* g2bn = g_grid2b + (size_t)node * (PBLK * HID);
    {
        int r = tid >> 2, c = tid & 3;
        a_rel = sbase + r * 64 + 16 * (c ^ ((r >> 1) & 3));
        a_basep = g_FTb + r * PBLK + c * 8;
    }
#pragma unroll
    for (int j = 0; j < 4; j++) {
        int id = tid + j * 256, r = id >> 5, c = id & 31;
        b_rel[j] = sbase + BOFF + r * 512 + 16 * (c ^ (r & 7));
        b_base[j] = g2bn + r * HID + c * 8;
    }

#pragma unroll
    for (int s = 0; s < 3; s++) {
        uint32_t so = s * STAGE;
        cp_async16(a_rel + so, a_basep + s * 32);
#pragma unroll
        for (int j = 0; j < 4; j++) cp_async16(b_rel[j] + so, b_base[j] + s * 32 * HID);
        asm volatile("cp.async.commit_group;");
    }

    float acc[2][8][4];
#pragma unroll
    for (int mt = 0; mt < 2; mt++)
#pragma unroll
        for (int nt = 0; nt < 8; nt++)
#pragma unroll
            for (int v = 0; v < 4; v++) acc[mt][nt][v] = 0.0f;

#pragma unroll 1
    for (int kc = 0; kc < 11; kc++) {
        waitg<2>();
        __syncthreads();
        int pf = kc + 3;
        if (pf < 11) {
            uint32_t so = (pf & 3) * STAGE;
            cp_async16(a_rel + so, a_basep + pf * 32);
#pragma unroll
            for (int j = 0; j < 4; j++) cp_async16(b_rel[j] + so, b_base[j] + pf * 32 * HID);
        }
        asm volatile("cp.async.commit_group;");

        const uint32_t so = (kc & 3) * STAGE;
#pragma unroll
        for (int ks = 0; ks < 2; ks++) {
            uint32_t af[2][4], bf[8][2];
#pragma unroll
            for (int mt = 0; mt < 2; mt++)
                ldsm_x4(af[mt][0], af[mt][1], af[mt][2], af[mt][3],
                        a_addr[mt][ks] + so);
#pragma unroll
            for (int np = 0; np < 4; np++)
                ldsm_x4_t(bf[2 * np][0], bf[2 * np][1], bf[2 * np + 1][0],
                          bf[2 * np + 1][1], b_addr[np][ks] + so);
#pragma unroll
            for (int mt = 0; mt < 2; mt++)
#pragma unroll
                for (int nt = 0; nt < 8; nt++)
                    mma_f16(acc[mt][nt], af[mt], bf[nt]);
        }
    }

    const int tq = lid >> 2;
    const int tr = lid & 3;
#pragma unroll
    for (int mt = 0; mt < 2; mt++) {
#pragma unroll
        for (int half = 0; half < 2; half++) {
            int i = wm * 32 + mt * 16 + tq + half * 8;
            if (i >= NC) continue;
            __half* row = g_zh + ((size_t)node * NC + i) * HID;
#pragma unroll
            for (int nt = 0; nt < 8; nt++) {
                int col = wn * 64 + nt * 8 + tr * 2;
                *(uint32_t*)&row[col] = pkh2(acc[mt][nt][half * 2 + 0],
                                             acc[mt][nt][half * 2 + 1]);
            }
        }
    }
}

// ---- out[:,i,:] : K=256, BN=128, 8 resident chunks (96KB), 2 CTAs/SM -------
__global__ void __launch_bounds__(256, 2) k_out_mma(const float* __restrict__ b2,
                                                    float* __restrict__ out) {
    extern __shared__ __align__(128) char smem[];
    const uint32_t sbase = smem_u32(smem);
    const int tid = threadIdx.x;
    const int wid = tid >> 5;
    const int lid = tid & 31;
    const int wm  = wid & 1;
    const int wn  = wid >> 1;   // 0..3, 32 cols each
    const int i   = blockIdx.y;
    const int m0  = blockIdx.x * 64;

    const uint32_t STAGE = 64 * 64 + CIN * 64;   // 4096 + 8192 = 12288
    const uint32_t BOFF  = 64 * 64;

    uint32_t a_addr[2][2], b_addr[2][2];
#pragma unroll
    for (int mt = 0; mt < 2; mt++)
#pragma unroll
        for (int ks = 0; ks < 2; ks++) {
            int row = wm * 32 + mt * 16 + (lid & 7) + ((lid >> 3) & 1) * 8;
            int ch  = ks * 2 + (lid >> 4);
            a_addr[mt][ks] = sbase + row * 64 + 16 * (ch ^ ((row >> 1) & 3));
        }
#pragma unroll
    for (int np = 0; np < 2; np++)
#pragma unroll
        for (int ks = 0; ks < 2; ks++) {
            int row = wn * 32 + np * 16 + (lid & 7) + (lid >> 4) * 8;
            int ch  = ks * 2 + ((lid >> 3) & 1);
            b_addr[np][ks] = sbase + BOFF + row * 64 + 16 * (ch ^ ((row >> 1) & 3));
        }

    uint32_t a_rel, b_rel[2];
    const __half* a_basep;
    const __half* b_base[2];
    {
        int r = tid >> 2, c = tid & 3;
        a_rel = sbase + r * 64 + 16 * (c ^ ((r >> 1) & 3));
        a_basep = (i == 0 ? g_gateh + (size_t)(m0 + r) * HID
                          : g_zh + ((size_t)(m0 + r) * NC + i) * HID) + c * 8;
    }
    {
        int l = deg_of(i);
#pragma unroll
        for (int j = 0; j < 2; j++) {
            int id = tid + j * 256, r = id >> 2, c = id & 3;   // r 0..127
            b_rel[j] = sbase + BOFF + r * 64 + 16 * (c ^ ((r >> 1) & 3));
            b_base[j] = (i == 0 ? g_w2h0 + (size_t)r * 256
                                : g_g3w2h + ((size_t)l * CIN + r) * 256) + c * 8;
        }
    }

#pragma unroll
    for (int s = 0; s < 8; s++) {
        uint32_t so = s * STAGE;
        cp_async16(a_rel + so, a_basep + s * 32);
#pragma unroll
        for (int j = 0; j < 2; j++) cp_async16(b_rel[j] + so, b_base[j] + s * 32);
        asm volatile("cp.async.commit_group;");
    }

    float acc[2][4][4];
#pragma unroll
    for (int mt = 0; mt < 2; mt++)
#pragma unroll
        for (int nt = 0; nt < 4; nt++)
#pragma unroll
            for (int v = 0; v < 4; v++) acc[mt][nt][v] = 0.0f;

    auto compute = [&](int kc) {
        const uint32_t so = kc * STAGE;
#pragma unroll
        for (int ks = 0; ks < 2; ks++) {
            uint32_t af[2][4], bf[4][2];
#pragma unroll
            for (int mt = 0; mt < 2; mt++)
                ldsm_x4(af[mt][0], af[mt][1], af[mt][2], af[mt][3],
                        a_addr[mt][ks] + so);
#pragma unroll
            for (int np = 0; np < 2; np++)
                ldsm_x4(bf[2 * np][0], bf[2 * np][1], bf[2 * np + 1][0],
                        bf[2 * np + 1][1], b_addr[np][ks] + so);
#pragma unroll
            for (int mt = 0; mt < 2; mt++)
#pragma unroll
                for (int nt = 0; nt < 4; nt++)
                    mma_f16(acc[mt][nt], af[mt], bf[nt]);
        }
    };

    waitg<4>(); __syncthreads();
    compute(0); compute(1); compute(2); compute(3);
    waitg<0>(); __syncthreads();
    compute(4); compute(5); compute(6); compute(7);

    const int tq = lid >> 2;
    const int tr = lid & 3;
#pragma unroll
    for (int mt = 0; mt < 2; mt++) {
#pragma unroll
        for (int half = 0; half < 2; half++) {
            int node = m0 + wm * 32 + mt * 16 + tq + half * 8;
            float* row = out + ((size_t)node * NC + i) * CIN;
#pragma unroll
            for (int nt = 0; nt < 4; nt++) {
                int col = wn * 32 + nt * 8 + tr * 2;
                float2 v;
                v.x = acc[mt][nt][half * 2 + 0];
                v.y = acc[mt][nt][half * 2 + 1];
                if (i == 0) { v.x += b2[col]; v.y += b2[col + 1]; }
                *(float2*)&row[col] = v;
            }
        }
    }
}

// ---------------------------------------------------------------------------

extern "C" void kernel_launch(void* const* d_in, const int* in_sizes, int n_in,
                              void* d_out, int out_size) {
    const float* nf = (const float*)d_in[0];
    const float* w1 = (const float*)d_in[1];
    const float* b1 = (const float*)d_in[2];
    const float* w2 = (const float*)d_in[3];
    const float* b2 = (const float*)d_in[4];
    const float* ws = (const float*)d_in[5];
    const float* bs = (const float*)d_in[6];
    const float* g1 = (const float*)d_in[7];
    const float* g2 = (const float*)d_in[8];
    const float* g3 = (const float*)d_in[9];
    const float* Tg = (const float*)d_in[10];
    const float* Fg = (const float*)d_in[11];
    float* out = (float*)d_out;

    const int SMEM1 = 2 * 20480;    // 40960  (grid1)
    const int SMEM2 = 4 * 20480;    // 81920  (grid2)
    const int SMEMY = 4 * 20480;    // 81920  (y / gate)
    const int SMEMZ = 4 * 20480;    // 81920  (z)
    const int SMEMO = 8 * 12288;    // 98304  (out)
    cudaFuncSetAttribute(k_grid1_mma, cudaFuncAttributeMaxDynamicSharedMemorySize, SMEM1);
    cudaFuncSetAttribute(k_grid2_mma, cudaFuncAttributeMaxDynamicSharedMemorySize, SMEM2);
    cudaFuncSetAttribute(k_z_mma,     cudaFuncAttributeMaxDynamicSharedMemorySize, SMEMZ);
    cudaFuncSetAttribute(k_y_mma,     cudaFuncAttributeMaxDynamicSharedMemorySize, SMEMY);
    cudaFuncSetAttribute(k_out_mma,   cudaFuncAttributeMaxDynamicSharedMemorySize, SMEMO);

    const int PS_BLOCKS = PS_TB + PS_FTB + PS_G2B + PS_NFH + PS_PADY + PS_PADG
                        + PS_WSH + PS_W2H;

    // prologs (3 launches)
    k_w1g1_h<<<dim3(HID / 64, CIN / 64, NL + 1), 256>>>(w1, g1, b1);
    k_g3w2_h<<<dim3(CIN / 64, HID / 64, NL), 256>>>(g3, w2);
    k_prep_static<<<PS_BLOCKS, 256>>>(nf, Tg, Fg, g2, ws, w2);

    // main pipeline (all MMA, 5 launches, all 2 CTAs/SM)
    k_y_mma<<<dim3(N_NODES / 64, NC + 1), 256, SMEMY>>>(bs);   // y + gate
    k_grid1_mma<<<dim3(6, N_NODES), 256, SMEM1>>>();
    k_grid2_mma<<<(int)(MROWS / 64), 256, SMEM2>>>();
    k_z_mma<<<N_NODES, 256, SMEMZ>>>();
    k_out_mma<<<dim3(N_NODES / 64, NC), 256, SMEMO>>>(b2, out);
}

// round 17
// speedup vs baseline: 1.6023x; 1.0277x over previous
#include <cuda_runtime.h>
#include <cuda_fp16.h>
#include <cstdint>

// ---------------------------------------------------------------------------
// FeedForwardNetwork (SO(3) equivariant FFN), sm_103a — all-MMA plain-fp16
// Round 17: grid2 and z pushed to 4 CTAs/SM (128 thr, tile 64x128, 12KB
// stages, 48KB smem/CTA). y/gate/grid1/out keep the round-16 2-CTA shape.
// K-accumulation order unchanged (bit-identical rel_err).
// ---------------------------------------------------------------------------

#define N_NODES 1024
#define NC      49
#define CIN     128
#define HID     256
#define RES     18
#define NP      (RES*RES)   // 324
#define NL      7
#define MROWS   ((size_t)N_NODES * NP)   // 331776
#define PBLK    352
#define BN      256
#define BK      32

// -------- scratch (static device globals; no runtime allocation) -----------
__device__ float g_b1g1[HID];
__device__ __half g_Tb[384 * 64];                    // to_grid hi [384x64]
__device__ __half g_FTb[64 * PBLK];                  // from_grid^T hi [64x352]
__device__ __half g_g2b[HID * 256];                  // g2^T hi [256x256]
__device__ __half g_w1g1h[NL * HID * 128];           // W1G1^T hi rows
__device__ __half g_g3w2h[NL * CIN * 256];           // (g3 w2)^T hi rows
__device__ __half g_wsh[HID * 128];                  // ws^T hi [256x128]
__device__ __half g_w2h0[CIN * 256];                 // w2[0]^T hi [128x256]
__device__ __half g_nfh[(size_t)N_NODES * NC * CIN];       // 12.8 MB
__device__ __half g_yb[(size_t)N_NODES * 64 * HID];        // 34 MB
__device__ __half g_grid1b[MROWS * HID];                   // 170 MB
__device__ __half g_grid2b[(size_t)N_NODES * PBLK * HID];  // 185 MB
__device__ __half g_zh[(size_t)N_NODES * NC * HID];        // 25.7 MB
__device__ __half g_gateh[(size_t)N_NODES * HID];          // fp16 gate

__device__ __forceinline__ float silu_f(float x) {
    return x / (1.0f + __expf(-x));
}
__device__ __forceinline__ int deg_of(int i) {
    int l = 0;
    while ((l + 1) * (l + 1) <= i) ++l;
    return l;
}
__device__ __forceinline__ uint32_t smem_u32(const void* p) {
    uint32_t a;
    asm("{ .reg .u64 t; cvta.to.shared.u64 t, %1; cvt.u32.u64 %0, t; }"
        : "=r"(a) : "l"(p));
    return a;
}
__device__ __forceinline__ void cp_async16(uint32_t dst, const void* src) {
    asm volatile("cp.async.cg.shared.global [%0], [%1], 16;" :: "r"(dst), "l"(src));
}
template<int N>
__device__ __forceinline__ void waitg() {
    asm volatile("cp.async.wait_group %0;" :: "n"(N));
}
__device__ __forceinline__ void ldsm_x4(uint32_t& r0, uint32_t& r1,
                                        uint32_t& r2, uint32_t& r3, uint32_t addr) {
    asm volatile("ldmatrix.sync.aligned.m8n8.x4.shared.b16 {%0,%1,%2,%3}, [%4];"
                 : "=r"(r0), "=r"(r1), "=r"(r2), "=r"(r3) : "r"(addr));
}
__device__ __forceinline__ void ldsm_x4_t(uint32_t& r0, uint32_t& r1,
                                          uint32_t& r2, uint32_t& r3, uint32_t addr) {
    asm volatile("ldmatrix.sync.aligned.m8n8.x4.trans.shared.b16 {%0,%1,%2,%3}, [%4];"
                 : "=r"(r0), "=r"(r1), "=r"(r2), "=r"(r3) : "r"(addr));
}
__device__ __forceinline__ void mma_f16(float* d, const uint32_t* a, const uint32_t* b) {
    asm volatile(
        "mma.sync.aligned.m16n8k16.row.col.f32.f16.f16.f32 "
        "{%0,%1,%2,%3}, {%4,%5,%6,%7}, {%8,%9}, {%0,%1,%2,%3};"
        : "+f"(d[0]), "+f"(d[1]), "+f"(d[2]), "+f"(d[3])
        : "r"(a[0]), "r"(a[1]), "r"(a[2]), "r"(a[3]), "r"(b[0]), "r"(b[1]));
}
__device__ __forceinline__ uint32_t pkh2(float x, float y) {
    __half hx = __float2half_rn(x), hy = __float2half_rn(y);
    uint16_t bx = *(uint16_t*)&hx, by = *(uint16_t*)&hy;
    return (uint32_t)bx | ((uint32_t)by << 16);
}

// ---------------------------------------------------------------------------
// SIMT gemm body with fp16-transposed epilogue (weight prep only).
// ---------------------------------------------------------------------------
__device__ __forceinline__ void gemm_tile_w16(
    const float* __restrict__ A, int lda,
    const float* __restrict__ B, int ldb,
    __half* __restrict__ OUT, int out_stride,
    int K)
{
    __shared__ float As[16][64];
    __shared__ float Bs[16][64];

    const int tid = threadIdx.x;
    const int tx  = tid & 15;
    const int ty  = tid >> 4;
    const int m0  = blockIdx.y * 64;
    const int n0  = blockIdx.x * 64;

    float acc[4][4];
#pragma unroll
    for (int i = 0; i < 4; i++)
#pragma unroll
        for (int j = 0; j < 4; j++) acc[i][j] = 0.0f;

    for (int k0 = 0; k0 < K; k0 += 16) {
#pragma unroll
        for (int e = tid; e < 64 * 16; e += 256) {
            int m = e >> 4, k = e & 15;
            As[k][m] = A[(size_t)(m0 + m) * lda + k0 + k];
        }
#pragma unroll
        for (int e = tid; e < 16 * 64; e += 256) {
            int k = e >> 6, n = e & 63;
            Bs[k][n] = B[(size_t)(k0 + k) * ldb + n0 + n];
        }
        __syncthreads();

#pragma unroll
        for (int k = 0; k < 16; k++) {
            float4 av = *(const float4*)&As[k][ty * 4];
            float4 bv = *(const float4*)&Bs[k][tx * 4];
            float a4[4] = {av.x, av.y, av.z, av.w};
            float b4[4] = {bv.x, bv.y, bv.z, bv.w};
#pragma unroll
            for (int i = 0; i < 4; i++)
#pragma unroll
                for (int j = 0; j < 4; j++)
                    acc[i][j] += a4[i] * b4[j];
        }
        __syncthreads();
    }

#pragma unroll
    for (int i = 0; i < 4; i++) {
        int gm = m0 + ty * 4 + i;
#pragma unroll
        for (int j = 0; j < 4; j++) {
            int gn = n0 + tx * 4 + j;
            OUT[(size_t)gn * out_stride + gm] = __float2half_rn(acc[i][j]);
        }
    }
}

// ---------------------------- prolog kernels --------------------------------

__global__ void __launch_bounds__(256) k_w1g1_h(const float* __restrict__ w1,
                                                const float* __restrict__ g1,
                                                const float* __restrict__ b1) {
    if (blockIdx.z == NL) {
        if (blockIdx.x != 0 || blockIdx.y != 0) return;
        int k = threadIdx.x;
        float s = 0.0f;
        for (int h = 0; h < HID; h++) s += b1[h] * g1[(size_t)h * HID + k];
        g_b1g1[k] = s;
        return;
    }
    int l = blockIdx.z;
    gemm_tile_w16(w1 + (size_t)l * CIN * HID, HID, g1, HID,
                  g_w1g1h + (size_t)l * HID * 128, 128, HID);
}

__global__ void __launch_bounds__(256) k_g3w2_h(const float* __restrict__ g3,
                                                const float* __restrict__ w2) {
    int l = blockIdx.z;
    gemm_tile_w16(g3, HID, w2 + (size_t)l * HID * CIN, CIN,
                  g_g3w2h + (size_t)l * CIN * 256, 256, HID);
}

// Mega-prep: Tb | FTb | g2b | nfh | pad_yb | pad_g2b | wsh | w2h0.
#define PS_TB    96
#define PS_FTB   88
#define PS_G2B   256
#define PS_NFH   12544
#define PS_PADY  7680
#define PS_PADG  14336
#define PS_WSH   128
#define PS_W2H   128
__global__ void __launch_bounds__(256) k_prep_static(
    const float* __restrict__ nf, const float* __restrict__ T,
    const float* __restrict__ F,  const float* __restrict__ g2,
    const float* __restrict__ ws, const float* __restrict__ w2) {
    int b = blockIdx.x;
    int t = threadIdx.x;
    if (b < PS_TB) {
        int idx = b * 256 + t;
        int p = idx >> 6, i = idx & 63;
        float v = (p < NP && i < NC) ? T[p * NC + i] : 0.0f;
        g_Tb[idx] = __float2half_rn(v);
        return;
    }
    b -= PS_TB;
    if (b < PS_FTB) {
        int idx = b * 256 + t;
        int i = idx / PBLK, p = idx % PBLK;
        float v = (i < NC && p < NP) ? F[p * NC + i] : 0.0f;
        g_FTb[idx] = __float2half_rn(v);
        return;
    }
    b -= PS_FTB;
    if (b < PS_G2B) {
        int idx = b * 256 + t;
        int n = idx >> 8, k = idx & 255;
        g_g2b[idx] = __float2half_rn(g2[(size_t)k * HID + n]);
        return;
    }
    b -= PS_G2B;
    if (b < PS_NFH) {
        size_t gi = ((size_t)b * 256 + t) * 2;
        float2 v = *(const float2*)(nf + gi);
        *(uint32_t*)&g_nfh[gi] = pkh2(v.x, v.y);
        return;
    }
    b -= PS_NFH;
    if (b < PS_PADY) {
        size_t w = (size_t)b * 256 + t;
        int node = (int)(w / 1920);
        int rem  = (int)(w % 1920);
        int row  = NC + rem / 128;
        int c2   = rem & 127;
        *(uint32_t*)&g_yb[((size_t)node * 64 + row) * HID + c2 * 2] = 0;
        return;
    }
    b -= PS_PADY;
    if (b < PS_PADG) {
        size_t w = (size_t)b * 256 + t;
        int node = (int)(w / 3584);
        int rem  = (int)(w % 3584);
        int row  = NP + rem / 128;
        int c2   = rem & 127;
        *(uint32_t*)&g_grid2b[((size_t)node * PBLK + row) * HID + c2 * 2] = 0;
        return;
    }
    b -= PS_PADG;
    if (b < PS_WSH) {
        int idx = b * 256 + t;
        int n = idx >> 7, k = idx & 127;
        g_wsh[idx] = __float2half_rn(ws[(size_t)k * HID + n]);
        return;
    }
    b -= PS_WSH;
    {
        int idx = b * 256 + t;
        int n = idx >> 8, k = idx & 255;
        g_w2h0[idx] = __float2half_rn(w2[(size_t)k * CIN + n]);
    }
}

// ---------------------------- main stage kernels ----------------------------

// ---- y (blockIdx.y < NC) or gate (== NC): K=128, 4 resident, 80KB, 2 CTA ---
__global__ void __launch_bounds__(256, 2) k_y_mma(const float* __restrict__ bs) {
    extern __shared__ __align__(128) char smem[];
    const uint32_t sbase = smem_u32(smem);
    const int tid = threadIdx.x;
    const int wid = tid >> 5;
    const int lid = tid & 31;
    const int wm  = wid & 1;
    const int wn  = wid >> 1;
    const bool is_gate = (blockIdx.y == NC);
    const int i   = is_gate ? 0 : blockIdx.y;
    const int l   = deg_of(i);
    const int m0  = blockIdx.x * 64;

    const uint32_t STAGE = 64 * 64 + BN * 64;    // 20480
    const uint32_t BOFF  = 64 * 64;              // 4096

    uint32_t a_addr[2][2], b_addr[4][2];
#pragma unroll
    for (int mt = 0; mt < 2; mt++)
#pragma unroll
        for (int ks = 0; ks < 2; ks++) {
            int row = wm * 32 + mt * 16 + (lid & 7) + ((lid >> 3) & 1) * 8;
            int ch  = ks * 2 + (lid >> 4);
            a_addr[mt][ks] = sbase + row * 64 + 16 * (ch ^ ((row >> 1) & 3));
        }
#pragma unroll
    for (int np = 0; np < 4; np++)
#pragma unroll
        for (int ks = 0; ks < 2; ks++) {
            int row = wn * 64 + np * 16 + (lid & 7) + (lid >> 4) * 8;
            int ch  = ks * 2 + ((lid >> 3) & 1);
            b_addr[np][ks] = sbase + BOFF + row * 64 + 16 * (ch ^ ((row >> 1) & 3));
        }

    uint32_t a_rel, b_rel[4];
    const __half* a_basep;
    const __half* b_base[4];
    {
        int r = tid >> 2, c = tid & 3;
        a_rel = sbase + r * 64 + 16 * (c ^ ((r >> 1) & 3));
        a_basep = g_nfh + ((size_t)(m0 + r) * NC + i) * CIN + c * 8;
    }
#pragma unroll
    for (int j = 0; j < 4; j++) {
        int id = tid + j * 256, r = id >> 2, c = id & 3;
        b_rel[j] = sbase + BOFF + r * 64 + 16 * (c ^ ((r >> 1) & 3));
        b_base[j] = (is_gate ? g_wsh + (size_t)r * 128
                             : g_w1g1h + ((size_t)l * HID + r) * 128) + c * 8;
    }

#pragma unroll
    for (int s = 0; s < 4; s++) {
        uint32_t so = s * STAGE;
        cp_async16(a_rel + so, a_basep + s * 32);
#pragma unroll
        for (int j = 0; j < 4; j++) cp_async16(b_rel[j] + so, b_base[j] + s * 32);
        asm volatile("cp.async.commit_group;");
    }

    float acc[2][8][4];
#pragma unroll
    for (int mt = 0; mt < 2; mt++)
#pragma unroll
        for (int nt = 0; nt < 8; nt++)
#pragma unroll
            for (int v = 0; v < 4; v++) acc[mt][nt][v] = 0.0f;

    auto compute = [&](int kc) {
        const uint32_t so = kc * STAGE;
#pragma unroll
        for (int ks = 0; ks < 2; ks++) {
            uint32_t af[2][4], bf[8][2];
#pragma unroll
            for (int mt = 0; mt < 2; mt++)
                ldsm_x4(af[mt][0], af[mt][1], af[mt][2], af[mt][3],
                        a_addr[mt][ks] + so);
#pragma unroll
            for (int np = 0; np < 4; np++)
                ldsm_x4(bf[2 * np][0], bf[2 * np][1], bf[2 * np + 1][0],
                        bf[2 * np + 1][1], b_addr[np][ks] + so);
#pragma unroll
            for (int mt = 0; mt < 2; mt++)
#pragma unroll
                for (int nt = 0; nt < 8; nt++)
                    mma_f16(acc[mt][nt], af[mt], bf[nt]);
        }
    };

    waitg<2>(); __syncthreads();
    compute(0); compute(1);
    waitg<0>(); __syncthreads();
    compute(2); compute(3);

    const int tq = lid >> 2;
    const int tr = lid & 3;
#pragma unroll
    for (int mt = 0; mt < 2; mt++) {
#pragma unroll
        for (int half = 0; half < 2; half++) {
            int node = m0 + wm * 32 + mt * 16 + tq + half * 8;
#pragma unroll
            for (int nt = 0; nt < 8; nt++) {
                int col = wn * 64 + nt * 8 + tr * 2;
                float v0 = acc[mt][nt][half * 2 + 0];
                float v1 = acc[mt][nt][half * 2 + 1];
                if (is_gate) {
                    v0 = silu_f(v0 + bs[col]);
                    v1 = silu_f(v1 + bs[col + 1]);
                    *(uint32_t*)&g_gateh[(size_t)node * HID + col] = pkh2(v0, v1);
                } else {
                    if (i == 0) { v0 += g_b1g1[col]; v1 += g_b1g1[col + 1]; }
                    *(uint32_t*)&g_yb[((size_t)node * 64 + i) * HID + col] = pkh2(v0, v1);
                }
            }
        }
    }
}

// -------- grid1 = silu(T @ y[n]) : K=64, 2 resident, trans-B, 2 CTA ---------
__global__ void __launch_bounds__(256, 2) k_grid1_mma() {
    extern __shared__ __align__(128) char smem[];
    const uint32_t sbase = smem_u32(smem);
    const int tid = threadIdx.x;
    const int wid = tid >> 5;
    const int lid = tid & 31;
    const int wm  = wid & 1;
    const int wn  = wid >> 1;
    const int node = blockIdx.y;
    const int m0 = blockIdx.x * 64;

    const uint32_t STAGE = 64 * 64 + BK * 512;   // 20480
    const uint32_t BOFF  = 64 * 64;

    uint32_t a_addr[2][2], b_addr[4][2];
#pragma unroll
    for (int mt = 0; mt < 2; mt++)
#pragma unroll
        for (int ks = 0; ks < 2; ks++) {
            int row = wm * 32 + mt * 16 + (lid & 7) + ((lid >> 3) & 1) * 8;
            int ch  = ks * 2 + (lid >> 4);
            a_addr[mt][ks] = sbase + row * 64 + 16 * (ch ^ ((row >> 1) & 3));
        }
#pragma unroll
    for (int np = 0; np < 4; np++)
#pragma unroll
        for (int ks = 0; ks < 2; ks++) {
            int row = ks * 16 + (lid & 7) + 8 * ((lid >> 3) & 1);
            int cn  = wn * 8 + np * 2 + (lid >> 4);
            b_addr[np][ks] = sbase + BOFF + row * 512 + 16 * (cn ^ (row & 7));
        }

    uint32_t a_rel, b_rel[4];
    const __half* a_basep;
    const __half* b_base[4];
    const __half* ybn = g_yb + (size_t)node * (64 * HID);
    {
        int r = tid >> 2, c = tid & 3;
        a_rel = sbase + r * 64 + 16 * (c ^ ((r >> 1) & 3));
        a_basep = g_Tb + (m0 + r) * 64 + c * 8;
    }
#pragma unroll
    for (int j = 0; j < 4; j++) {
        int id = tid + j * 256, r = id >> 5, c = id & 31;
        b_rel[j] = sbase + BOFF + r * 512 + 16 * (c ^ (r & 7));
        b_base[j] = ybn + r * HID + c * 8;
    }

#pragma unroll
    for (int s = 0; s < 2; s++) {
        uint32_t so = s * STAGE;
        cp_async16(a_rel + so, a_basep + s * 32);
#pragma unroll
        for (int j = 0; j < 4; j++) cp_async16(b_rel[j] + so, b_base[j] + s * 32 * HID);
        asm volatile("cp.async.commit_group;");
    }

    float acc[2][8][4];
#pragma unroll
    for (int mt = 0; mt < 2; mt++)
#pragma unroll
        for (int nt = 0; nt < 8; nt++)
#pragma unroll
            for (int v = 0; v < 4; v++) acc[mt][nt][v] = 0.0f;

    auto compute = [&](int kc) {
        const uint32_t so = kc * STAGE;
#pragma unroll
        for (int ks = 0; ks < 2; ks++) {
            uint32_t af[2][4], bf[8][2];
#pragma unroll
            for (int mt = 0; mt < 2; mt++)
                ldsm_x4(af[mt][0], af[mt][1], af[mt][2], af[mt][3],
                        a_addr[mt][ks] + so);
#pragma unroll
            for (int np = 0; np < 4; np++)
                ldsm_x4_t(bf[2 * np][0], bf[2 * np][1], bf[2 * np + 1][0],
                          bf[2 * np + 1][1], b_addr[np][ks] + so);
#pragma unroll
            for (int mt = 0; mt < 2; mt++)
#pragma unroll
                for (int nt = 0; nt < 8; nt++)
                    mma_f16(acc[mt][nt], af[mt], bf[nt]);
        }
    };

    waitg<1>(); __syncthreads();
    compute(0);
    waitg<0>(); __syncthreads();
    compute(1);

    const int tq = lid >> 2;
    const int tr = lid & 3;
#pragma unroll
    for (int mt = 0; mt < 2; mt++) {
#pragma unroll
        for (int half = 0; half < 2; half++) {
            int p = m0 + wm * 32 + mt * 16 + tq + half * 8;
            if (p >= NP) continue;
            __half* row = g_grid1b + ((size_t)node * NP + p) * HID;
#pragma unroll
            for (int nt = 0; nt < 8; nt++) {
                int col = wn * 64 + nt * 8 + tr * 2;
                *(uint32_t*)&row[col] = pkh2(silu_f(acc[mt][nt][half * 2 + 0]),
                                             silu_f(acc[mt][nt][half * 2 + 1]));
            }
        }
    }
}

// ---- grid2 = silu(grid1 @ g2): K=256, tile 64x128, 128 thr, 4 CTAs/SM ------
__global__ void __launch_bounds__(128, 4) k_grid2_mma() {
    extern __shared__ __align__(128) char smem[];
    const uint32_t sbase = smem_u32(smem);
    const int tid = threadIdx.x;
    const int wid = tid >> 5;           // 0..3
    const int lid = tid & 31;
    const int wm  = wid & 1;            // 32-row half
    const int wn  = wid >> 1;           // 0..1, 64 cols each
    const size_t m0 = (size_t)blockIdx.x * 64;
    const int n0  = blockIdx.y * 128;   // N block-column

    const uint32_t STAGE = 64 * 64 + 128 * 64;   // 4096 + 8192 = 12288
    const uint32_t BOFF  = 64 * 64;

    uint32_t a_addr[2][2], b_addr[4][2];
#pragma unroll
    for (int mt = 0; mt < 2; mt++)
#pragma unroll
        for (int ks = 0; ks < 2; ks++) {
            int row = wm * 32 + mt * 16 + (lid & 7) + ((lid >> 3) & 1) * 8;
            int ch  = ks * 2 + (lid >> 4);
            a_addr[mt][ks] = sbase + row * 64 + 16 * (ch ^ ((row >> 1) & 3));
        }
#pragma unroll
    for (int np = 0; np < 4; np++)
#pragma unroll
        for (int ks = 0; ks < 2; ks++) {
            int row = wn * 64 + np * 16 + (lid & 7) + (lid >> 4) * 8;
            int ch  = ks * 2 + ((lid >> 3) & 1);
            b_addr[np][ks] = sbase + BOFF + row * 64 + 16 * (ch ^ ((row >> 1) & 3));
        }

    uint32_t a_rel[2], b_rel[4];
    const __half* a_base[2];
    const __half* b_base[4];
#pragma unroll
    for (int j = 0; j < 2; j++) {
        int id = tid + j * 128, r = id >> 2, c = id & 3;
        a_rel[j] = sbase + r * 64 + 16 * (c ^ ((r >> 1) & 3));
        a_base[j] = g_grid1b + (m0 + r) * (size_t)HID + c * 8;
    }
#pragma unroll
    for (int j = 0; j < 4; j++) {
        int id = tid + j * 128, r = id >> 2, c = id & 3;    // r 0..127
        b_rel[j] = sbase + BOFF + r * 64 + 16 * (c ^ ((r >> 1) & 3));
        b_base[j] = g_g2b + (size_t)(n0 + r) * 256 + c * 8;
    }

#pragma unroll
    for (int s = 0; s < 3; s++) {
        uint32_t so = s * STAGE;
#pragma unroll
        for (int j = 0; j < 2; j++) cp_async16(a_rel[j] + so, a_base[j] + s * 32);
#pragma unroll
        for (int j = 0; j < 4; j++) cp_async16(b_rel[j] + so, b_base[j] + s * 32);
        asm volatile("cp.async.commit_group;");
    }

    float acc[2][8][4];
#pragma unroll
    for (int mt = 0; mt < 2; mt++)
#pragma unroll
        for (int nt = 0; nt < 8; nt++)
#pragma unroll
            for (int v = 0; v < 4; v++) acc[mt][nt][v] = 0.0f;

#pragma unroll 1
    for (int kc = 0; kc < 8; kc++) {
        waitg<2>();
        __syncthreads();
        int pf = kc + 3;
        if (pf < 8) {
            uint32_t so = (pf & 3) * STAGE;
#pragma unroll
            for (int j = 0; j < 2; j++) cp_async16(a_rel[j] + so, a_base[j] + pf * 32);
#pragma unroll
            for (int j = 0; j < 4; j++) cp_async16(b_rel[j] + so, b_base[j] + pf * 32);
        }
        asm volatile("cp.async.commit_group;");

        const uint32_t so = (kc & 3) * STAGE;
#pragma unroll
        for (int ks = 0; ks < 2; ks++) {
            uint32_t af[2][4], bf[8][2];
#pragma unroll
            for (int mt = 0; mt < 2; mt++)
                ldsm_x4(af[mt][0], af[mt][1], af[mt][2], af[mt][3],
                        a_addr[mt][ks] + so);
#pragma unroll
            for (int np = 0; np < 4; np++)
                ldsm_x4(bf[2 * np][0], bf[2 * np][1], bf[2 * np + 1][0],
                        bf[2 * np + 1][1], b_addr[np][ks] + so);
#pragma unroll
            for (int mt = 0; mt < 2; mt++)
#pragma unroll
                for (int nt = 0; nt < 8; nt++)
                    mma_f16(acc[mt][nt], af[mt], bf[nt]);
        }
    }

    const int tq = lid >> 2;
    const int tr = lid & 3;
#pragma unroll
    for (int mt = 0; mt < 2; mt++) {
#pragma unroll
        for (int half = 0; half < 2; half++) {
            size_t r = m0 + wm * 32 + mt * 16 + tq + half * 8;
            uint32_t n = (uint32_t)(r / NP);
            uint32_t p = (uint32_t)(r - (size_t)n * NP);
            __half* row = g_grid2b + ((size_t)n * PBLK + p) * HID;
#pragma unroll
            for (int nt = 0; nt < 8; nt++) {
                int col = n0 + wn * 64 + nt * 8 + tr * 2;
                *(uint32_t*)&row[col] = pkh2(silu_f(acc[mt][nt][half * 2 + 0]),
                                             silu_f(acc[mt][nt][half * 2 + 1]));
            }
        }
    }
}

// ---- z = F^T @ grid2[n] : K=352, tile 64x128, 128 thr, 4 CTAs/SM, trans-B --
__global__ void __launch_bounds__(128, 4) k_z_mma() {
    extern __shared__ __align__(128) char smem[];
    const uint32_t sbase = smem_u32(smem);
    const int tid = threadIdx.x;
    const int wid = tid >> 5;           // 0..3
    const int lid = tid & 31;
    const int wm  = wid & 1;
    const int wn  = wid >> 1;           // 0..1, 64 cols each
    const int node = blockIdx.x;
    const int n0  = blockIdx.y * 128;   // h block-column

    const uint32_t STAGE = 64 * 64 + BK * 256;   // 4096 + 8192 = 12288
    const uint32_t BOFF  = 64 * 64;

    uint32_t a_addr[2][2], b_addr[4][2];
#pragma unroll
    for (int mt = 0; mt < 2; mt++)
#pragma unroll
        for (int ks = 0; ks < 2; ks++) {
            int row = wm * 32 + mt * 16 + (lid & 7) + ((lid >> 3) & 1) * 8;
            int ch  = ks * 2 + (lid >> 4);
            a_addr[mt][ks] = sbase + row * 64 + 16 * (ch ^ ((row >> 1) & 3));
        }
#pragma unroll
    for (int np = 0; np < 4; np++)
#pragma unroll
        for (int ks = 0; ks < 2; ks++) {
            int row = ks * 16 + (lid & 7) + 8 * ((lid >> 3) & 1);
            int cn  = wn * 8 + np * 2 + (lid >> 4);     // 0..15
            b_addr[np][ks] = sbase + BOFF + row * 256 + 16 * (cn ^ (row & 7));
        }

    uint32_t a_rel[2], b_rel[4];
    const __half* a_base[2];
    const __half* b_base[4];
    const __half* g2bn = g_grid2b + (size_t)node * (PBLK * HID);
#pragma unroll
    for (int j = 0; j < 2; j++) {
        int id = tid + j * 128, r = id >> 2, c = id & 3;
        a_rel[j] = sbase + r * 64 + 16 * (c ^ ((r >> 1) & 3));
        a_base[j] = g_FTb + r * PBLK + c * 8;
    }
#pragma unroll
    for (int j = 0; j < 4; j++) {
        int id = tid + j * 128, r = id >> 4, c = id & 15;   // r 0..31, c 0..15
        b_rel[j] = sbase + BOFF + r * 256 + 16 * (c ^ (r & 7));
        b_base[j] = g2bn + (size_t)r * HID + n0 + c * 8;
    }

#pragma unroll
    for (int s = 0; s < 3; s++) {
        uint32_t so = s * STAGE;
#pragma unroll
        for (int j = 0; j < 2; j++) cp_async16(a_rel[j] + so, a_base[j] + s * 32);
#pragma unroll
        for (int j = 0; j < 4; j++) cp_async16(b_rel[j] + so, b_base[j] + (size_t)s * 32 * HID);
        asm volatile("cp.async.commit_group;");
    }

    float acc[2][8][4];
#pragma unroll
    for (int mt = 0; mt < 2; mt++)
#pragma unroll
        for (int nt = 0; nt < 8; nt++)
#pragma unroll
            for (int v = 0; v < 4; v++) acc[mt][nt][v] = 0.0f;

#pragma unroll 1
    for (int kc = 0; kc < 11; kc++) {
        waitg<2>();
        __syncthreads();
        int pf = kc + 3;
        if (pf < 11) {
            uint32_t so = (pf & 3) * STAGE;
#pragma unroll
            for (int j = 0; j < 2; j++) cp_async16(a_rel[j] + so, a_base[j] + pf * 32);
#pragma unroll
            for (int j = 0; j < 4; j++) cp_async16(b_rel[j] + so, b_base[j] + (size_t)pf * 32 * HID);
        }
        asm volatile("cp.async.commit_group;");

        const uint32_t so = (kc & 3) * STAGE;
#pragma unroll
        for (int ks = 0; ks < 2; ks++) {
            uint32_t af[2][4], bf[8][2];
#pragma unroll
            for (int mt = 0; mt < 2; mt++)
                ldsm_x4(af[mt][0], af[mt][1], af[mt][2], af[mt][3],
                        a_addr[mt][ks] + so);
#pragma unroll
            for (int np = 0; np < 4; np++)
                ldsm_x4_t(bf[2 * np][0], bf[2 * np][1], bf[2 * np + 1][0],
                          bf[2 * np + 1][1], b_addr[np][ks] + so);
#pragma unroll
            for (int mt = 0; mt < 2; mt++)
#pragma unroll
                for (int nt = 0; nt < 8; nt++)
                    mma_f16(acc[mt][nt], af[mt], bf[nt]);
        }
    }

    const int tq = lid >> 2;
    const int tr = lid & 3;
#pragma unroll
    for (int mt = 0; mt < 2; mt++) {
#pragma unroll
        for (int half = 0; half < 2; half++) {
            int i = wm * 32 + mt * 16 + tq + half * 8;
            if (i >= NC) continue;
            __half* row = g_zh + ((size_t)node * NC + i) * HID;
#pragma unroll
            for (int nt = 0; nt < 8; nt++) {
                int col = n0 + wn * 64 + nt * 8 + tr * 2;
                *(uint32_t*)&row[col] = pkh2(acc[mt][nt][half * 2 + 0],
                                             acc[mt][nt][half * 2 + 1]);
            }
        }
    }
}

// ---- out[:,i,:] : K=256, BN=128, 8 resident chunks (96KB), 2 CTAs/SM -------
__global__ void __launch_bounds__(256, 2) k_out_mma(const float* __restrict__ b2,
                                                    float* __restrict__ out) {
    extern __shared__ __align__(128) char smem[];
    const uint32_t sbase = smem_u32(smem);
    const int tid = threadIdx.x;
    const int wid = tid >> 5;
    const int lid = tid & 31;
    const int wm  = wid & 1;
    const int wn  = wid >> 1;   // 0..3, 32 cols each
    const int i   = blockIdx.y;
    const int m0  = blockIdx.x * 64;

    const uint32_t STAGE = 64 * 64 + CIN * 64;   // 12288
    const uint32_t BOFF  = 64 * 64;

    uint32_t a_addr[2][2], b_addr[2][2];
#pragma unroll
    for (int mt = 0; mt < 2; mt++)
#pragma unroll
        for (int ks = 0; ks < 2; ks++) {
            int row = wm * 32 + mt * 16 + (lid & 7) + ((lid >> 3) & 1) * 8;
            int ch  = ks * 2 + (lid >> 4);
            a_addr[mt][ks] = sbase + row * 64 + 16 * (ch ^ ((row >> 1) & 3));
        }
#pragma unroll
    for (int np = 0; np < 2; np++)
#pragma unroll
        for (int ks = 0; ks < 2; ks++) {
            int row = wn * 32 + np * 16 + (lid & 7) + (lid >> 4) * 8;
            int ch  = ks * 2 + ((lid >> 3) & 1);
            b_addr[np][ks] = sbase + BOFF + row * 64 + 16 * (ch ^ ((row >> 1) & 3));
        }

    uint32_t a_rel, b_rel[2];
    const __half* a_basep;
    const __half* b_base[2];
    {
        int r = tid >> 2, c = tid & 3;
        a_rel = sbase + r * 64 + 16 * (c ^ ((r >> 1) & 3));
        a_basep = (i == 0 ? g_gateh + (size_t)(m0 + r) * HID
                          : g_zh + ((size_t)(m0 + r) * NC + i) * HID) + c * 8;
    }
    {
        int l = deg_of(i);
#pragma unroll
        for (int j = 0; j < 2; j++) {
            int id = tid + j * 256, r = id >> 2, c = id & 3;
            b_rel[j] = sbase + BOFF + r * 64 + 16 * (c ^ ((r >> 1) & 3));
            b_base[j] = (i == 0 ? g_w2h0 + (size_t)r * 256
                                : g_g3w2h + ((size_t)l * CIN + r) * 256) + c * 8;
        }
    }

#pragma unroll
    for (int s = 0; s < 8; s++) {
        uint32_t so = s * STAGE;
        cp_async16(a_rel + so, a_basep + s * 32);
#pragma unroll
        for (int j = 0; j < 2; j++) cp_async16(b_rel[j] + so, b_base[j] + s * 32);
        asm volatile("cp.async.commit_group;");
    }

    float acc[2][4][4];
#pragma unroll
    for (int mt = 0; mt < 2; mt++)
#pragma unroll
        for (int nt = 0; nt < 4; nt++)
#pragma unroll
            for (int v = 0; v < 4; v++) acc[mt][nt][v] = 0.0f;

    auto compute = [&](int kc) {
        const uint32_t so = kc * STAGE;
#pragma unroll
        for (int ks = 0; ks < 2; ks++) {
            uint32_t af[2][4], bf[4][2];
#pragma unroll
            for (int mt = 0; mt < 2; mt++)
                ldsm_x4(af[mt][0], af[mt][1], af[mt][2], af[mt][3],
                        a_addr[mt][ks] + so);
#pragma unroll
            for (int np = 0; np < 2; np++)
                ldsm_x4(bf[2 * np][0], bf[2 * np][1], bf[2 * np + 1][0],
                        bf[2 * np + 1][1], b_addr[np][ks] + so);
#pragma unroll
            for (int mt = 0; mt < 2; mt++)
#pragma unroll
                for (int nt = 0; nt < 4; nt++)
                    mma_f16(acc[mt][nt], af[mt], bf[nt]);
        }
    };

    waitg<4>(); __syncthreads();
    compute(0); compute(1); compute(2); compute(3);
    waitg<0>(); __syncthreads();
    compute(4); compute(5); compute(6); compute(7);

    const int tq = lid >> 2;
    const int tr = lid & 3;
#pragma unroll
    for (int mt = 0; mt < 2; mt++) {
#pragma unroll
        for (int half = 0; half < 2; half++) {
            int node = m0 + wm * 32 + mt * 16 + tq + half * 8;
            float* row = out + ((size_t)node * NC + i) * CIN;
#pragma unroll
            for (int nt = 0; nt < 4; nt++) {
                int col = wn * 32 + nt * 8 + tr * 2;
                float2 v;
                v.x = acc[mt][nt][half * 2 + 0];
                v.y = acc[mt][nt][half * 2 + 1];
                if (i == 0) { v.x += b2[col]; v.y += b2[col + 1]; }
                *(float2*)&row[col] = v;
            }
        }
    }
}

// ---------------------------------------------------------------------------

extern "C" void kernel_launch(void* const* d_in, const int* in_sizes, int n_in,
                              void* d_out, int out_size) {
    const float* nf = (const float*)d_in[0];
    const float* w1 = (const float*)d_in[1];
    const float* b1 = (const float*)d_in[2];
    const float* w2 = (const float*)d_in[3];
    const float* b2 = (const float*)d_in[4];
    const float* ws = (const float*)d_in[5];
    const float* bs = (const float*)d_in[6];
    const float* g1 = (const float*)d_in[7];
    const float* g2 = (const float*)d_in[8];
    const float* g3 = (const float*)d_in[9];
    const float* Tg = (const float*)d_in[10];
    const float* Fg = (const float*)d_in[11];
    float* out = (float*)d_out;

    const int SMEM1 = 2 * 20480;    // 40960  (grid1, 2 CTA)
    const int SMEM2 = 4 * 12288;    // 49152  (grid2, 4 CTA)
    const int SMEMY = 4 * 20480;    // 81920  (y / gate, 2 CTA)
    const int SMEMZ = 4 * 12288;    // 49152  (z, 4 CTA)
    const int SMEMO = 8 * 12288;    // 98304  (out, 2 CTA)
    cudaFuncSetAttribute(k_grid1_mma, cudaFuncAttributeMaxDynamicSharedMemorySize, SMEM1);
    cudaFuncSetAttribute(k_grid2_mma, cudaFuncAttributeMaxDynamicSharedMemorySize, SMEM2);
    cudaFuncSetAttribute(k_z_mma,     cudaFuncAttributeMaxDynamicSharedMemorySize, SMEMZ);
    cudaFuncSetAttribute(k_y_mma,     cudaFuncAttributeMaxDynamicSharedMemorySize, SMEMY);
    cudaFuncSetAttribute(k_out_mma,   cudaFuncAttributeMaxDynamicSharedMemorySize, SMEMO);

    const int PS_BLOCKS = PS_TB + PS_FTB + PS_G2B + PS_NFH + PS_PADY + PS_PADG
                        + PS_WSH + PS_W2H;

    // prologs (3 launches)
    k_w1g1_h<<<dim3(HID / 64, CIN / 64, NL + 1), 256>>>(w1, g1, b1);
    k_g3w2_h<<<dim3(CIN / 64, HID / 64, NL), 256>>>(g3, w2);
    k_prep_static<<<PS_BLOCKS, 256>>>(nf, Tg, Fg, g2, ws, w2);

    // main pipeline (all MMA, 5 launches)
    k_y_mma<<<dim3(N_NODES / 64, NC + 1), 256, SMEMY>>>(bs);   // y + gate
    k_grid1_mma<<<dim3(6, N_NODES), 256, SMEM1>>>();
    k_grid2_mma<<<dim3((int)(MROWS / 64), 2), 128, SMEM2>>>();
    k_z_mma<<<dim3(N_NODES, 2), 128, SMEMZ>>>();
    k_out_mma<<<dim3(N_NODES / 64, NC), 256, SMEMO>>>(b2, out);
}